// round 10
// baseline (speedup 1.0000x reference)
#include <cuda_runtime.h>
#include <cuda_bf16.h>
#include <cstdint>
#include <math.h>

// ---------------------------------------------------------------------------
// Problem constants
// ---------------------------------------------------------------------------
#define NQ   64
#define MMQ  16
#define BB   8
#define KK   256
#define CC   512
#define K3   1536           // 3*CC for split-bf16 GEMMs
#define NROWS_Q 8192
#define NROWS_K 2048
#define BKP     2048
#define INV_EPS 20.0f
#define X_ELEMS (NROWS_Q*CC)

// ---------------------------------------------------------------------------
// Scratch (device globals; no allocation allowed)
// ---------------------------------------------------------------------------
__device__ __nv_bfloat16 g_xq3[NROWS_Q*K3];
__device__ __nv_bfloat16 g_xk3[NROWS_K*K3];
__device__ __nv_bfloat16 g_xv3[NROWS_K*K3];
__device__ __nv_bfloat16 g_wq3[CC*K3];
__device__ __nv_bfloat16 g_wk3[CC*K3];
__device__ __nv_bfloat16 g_wv3[CC*K3];
__device__ __nv_bfloat16 g_wp3[CC*K3];
__device__ float g_qlin[NROWS_Q*CC];
__device__ float g_klin[NROWS_K*CC];
__device__ float g_v   [NROWS_K*CC];          // vp = v @ Wp^T (fp32)
__device__ __nv_bfloat16 g_qr3[NROWS_Q*K3];
__device__ __nv_bfloat16 g_kn3[NROWS_K*K3];
__device__ float g_S0[BKP*MMQ*NQ];            // sim split-K partial 0
__device__ float g_S1[BKP*MMQ*NQ];            // sim split-K partial 1
__device__ __nv_bfloat16 g_Tt3[BB*1024*768];
__device__ __nv_bfloat16 g_vT3[BB*512*768];
__device__ __nv_bfloat16 g_v3[NROWS_K*K3];    // split-bf16 v (A-mode)

// ---------------------------------------------------------------------------
// PTX helpers
// ---------------------------------------------------------------------------
__device__ __forceinline__ uint32_t s2u(const void* p){
    uint32_t a;
    asm("{ .reg .u64 t; cvta.to.shared.u64 t, %1; cvt.u32.u64 %0, t; }"
        : "=r"(a) : "l"(p));
    return a;
}

#define CP_ASYNC16(dst, src) \
    asm volatile("cp.async.cg.shared.global [%0], [%1], 16;" :: "r"(dst), "l"(src) : "memory")
#define CP_COMMIT() asm volatile("cp.async.commit_group;" ::: "memory")
#define CP_WAIT1()  asm volatile("cp.async.wait_group 1;" ::: "memory")
#define CP_WAIT0()  asm volatile("cp.async.wait_group 0;" ::: "memory")

#define LDMATRIX_X4(r0, r1, r2, r3, addr) \
    asm volatile("ldmatrix.sync.aligned.m8n8.x4.shared.b16 {%0,%1,%2,%3}, [%4];" \
                 : "=r"(r0), "=r"(r1), "=r"(r2), "=r"(r3) : "r"(addr))

#define MMA16816(d, a, b0, b1) \
    asm volatile("mma.sync.aligned.m16n8k16.row.col.f32.bf16.bf16.f32 " \
                 "{%0,%1,%2,%3}, {%4,%5,%6,%7}, {%8,%9}, {%0,%1,%2,%3};" \
                 : "+f"((d)[0]), "+f"((d)[1]), "+f"((d)[2]), "+f"((d)[3]) \
                 : "r"((a)[0]), "r"((a)[1]), "r"((a)[2]), "r"((a)[3]), \
                   "r"(b0), "r"(b1))

__device__ __forceinline__ unsigned short bfr(__nv_bfloat16 h){
    return *reinterpret_cast<unsigned short*>(&h);
}
__device__ __forceinline__ void split_bf16(float x, __nv_bfloat16& h, __nv_bfloat16& l){
    h = __float2bfloat16(x);
    l = __float2bfloat16(x - __bfloat162float(h));
}
__device__ __forceinline__ uint32_t pack2(__nv_bfloat16 a, __nv_bfloat16 b){
    return (uint32_t)bfr(a) | ((uint32_t)bfr(b) << 16);
}

// ---------------------------------------------------------------------------
// HMMA GEMM core (R6-proven): C[M,N] = A(M,K')·B(N,K')ᵀ, K-major bf16,
// fp32 accum. CTA tile 128x128, BK=64, 3-stage cp.async ring,
// 8 warps (4m x 2n), warp tile 32x64, 256 threads, 2 CTAs/SM.
// lda/ldb allow K-slicing (split-K). EPI=0 fp32 store; EPI=2 split-bf16
// A-mode emit; EPI=3 batched out scatter+bias.
// ---------------------------------------------------------------------------
#define STG   32768
#define GSMEM (3*STG)

template<int EPI>
__device__ __forceinline__
void gemm_core(const __nv_bfloat16* __restrict__ A, const __nv_bfloat16* __restrict__ B,
               void* __restrict__ Cv, const float* __restrict__ bias,
               int Kp, int lda, int ldb, int ldc, int mb, int nb, int bz,
               long cStride, char* smem)
{
    const int tid  = threadIdx.x;
    const int w    = tid >> 5;
    const int lane = tid & 31;
    const int wm   = (w & 3) * 32;
    const int wn   = (w >> 2) * 64;

    const uint32_t sbase = s2u(smem);
    const int NC = Kp >> 6;

    const int lrow = tid >> 1;
    const int lcg0 = (tid & 1) * 4;

    auto load_chunk = [&](int c, int s){
        const uint32_t st = sbase + s * STG;
        const __nv_bfloat16* Ag = A + (long)(mb + lrow) * lda + c * 64 + lcg0 * 8;
        const __nv_bfloat16* Bg = B + (long)(nb + lrow) * ldb + c * 64 + lcg0 * 8;
        const uint32_t rbase = lrow * 128;
        const uint32_t sw    = (lrow & 7) << 4;
#pragma unroll
        for (int j = 0; j < 4; j++) {
            uint32_t off = rbase + (((lcg0 + j) << 4) ^ sw);
            CP_ASYNC16(st + off, Ag + j * 8);
            CP_ASYNC16(st + 16384 + off, Bg + j * 8);
        }
        CP_COMMIT();
    };

    float acc[2][8][4];
#pragma unroll
    for (int i = 0; i < 2; i++)
#pragma unroll
        for (int j = 0; j < 8; j++)
#pragma unroll
            for (int q = 0; q < 4; q++) acc[i][j][q] = 0.f;

    load_chunk(0, 0);
    load_chunk(1, 1);

    const int a_r  = lane & 15;
    const int a_kb = (lane & 16);
    const int b_r  = ((lane >> 4) << 3) + (lane & 7);
    const int b_kb = ((lane >> 3) & 1) << 4;

    int stage = 0;
    for (int c = 0; c < NC; c++) {
        if (c + 1 < NC) CP_WAIT1(); else CP_WAIT0();
        __syncthreads();

        if (c + 2 < NC) {
            int ns = stage + 2; if (ns >= 3) ns -= 3;
            load_chunk(c + 2, ns);
        }

        const uint32_t sa = sbase + stage * STG;
        const uint32_t sb = sa + 16384;

        uint32_t br2[2][4][4];
#pragma unroll
        for (int nj = 0; nj < 4; nj++) {
            int row = wn + nj * 16 + b_r;
            uint32_t kb = (uint32_t)(b_kb) ^ ((row & 7) << 4);
            LDMATRIX_X4(br2[0][nj][0], br2[0][nj][1], br2[0][nj][2], br2[0][nj][3],
                        sb + row * 128 + kb);
        }
#pragma unroll
        for (int ks = 0; ks < 4; ks++) {
            const int cur = ks & 1;
            if (ks < 3) {
#pragma unroll
                for (int nj = 0; nj < 4; nj++) {
                    int row = wn + nj * 16 + b_r;
                    uint32_t kb = (uint32_t)((ks + 1) * 32 + b_kb) ^ ((row & 7) << 4);
                    LDMATRIX_X4(br2[cur ^ 1][nj][0], br2[cur ^ 1][nj][1],
                                br2[cur ^ 1][nj][2], br2[cur ^ 1][nj][3],
                                sb + row * 128 + kb);
                }
            }
            uint32_t ar[2][4];
#pragma unroll
            for (int mi = 0; mi < 2; mi++) {
                int row = wm + mi * 16 + a_r;
                uint32_t kb = (uint32_t)(ks * 32 + a_kb) ^ ((row & 7) << 4);
                LDMATRIX_X4(ar[mi][0], ar[mi][1], ar[mi][2], ar[mi][3],
                            sa + row * 128 + kb);
            }
#pragma unroll
            for (int mi = 0; mi < 2; mi++)
#pragma unroll
                for (int nj = 0; nj < 4; nj++) {
                    MMA16816(acc[mi][nj * 2],     ar[mi], br2[cur][nj][0], br2[cur][nj][1]);
                    MMA16816(acc[mi][nj * 2 + 1], ar[mi], br2[cur][nj][2], br2[cur][nj][3]);
                }
        }
        stage++; if (stage == 3) stage = 0;
    }

    // ---- epilogue ----
    const int er = lane >> 2;
    const int ec = (lane & 3) * 2;
#pragma unroll
    for (int mi = 0; mi < 2; mi++) {
#pragma unroll
        for (int half = 0; half < 2; half++) {
            const int R = mb + wm + mi * 16 + er + half * 8;
            if (EPI == 0) {
                float* Crow = (float*)Cv + (long)bz * cStride + (long)R * ldc;
#pragma unroll
                for (int nj = 0; nj < 8; nj++) {
                    const int col = nb + wn + nj * 8 + ec;
                    *(float2*)&Crow[col] =
                        make_float2(acc[mi][nj][half * 2], acc[mi][nj][half * 2 + 1]);
                }
            } else if (EPI == 3) {
                const int mq = R >> 6, nq = R & 63;
                float* Crow = (float*)Cv + (long)(((nq << 4) + mq) * 8 + bz) * CC;
#pragma unroll
                for (int nj = 0; nj < 8; nj++) {
                    const int col = nb + wn + nj * 8 + ec;
                    *(float2*)&Crow[col] = make_float2(
                        acc[mi][nj][half * 2] + bias[col],
                        acc[mi][nj][half * 2 + 1] + bias[col + 1]);
                }
            } else {
                // EPI==2: split-bf16 A-mode emit [hi|lo|hi]
                __nv_bfloat16* Yr = (__nv_bfloat16*)Cv + (long)bz * cStride + (long)R * K3;
#pragma unroll
                for (int nj = 0; nj < 8; nj++) {
                    const int col = nb + wn + nj * 8 + ec;
                    __nv_bfloat16 h0, l0, h1, l1;
                    split_bf16(acc[mi][nj][half * 2],     h0, l0);
                    split_bf16(acc[mi][nj][half * 2 + 1], h1, l1);
                    uint32_t hp = pack2(h0, h1), lp = pack2(l0, l1);
                    *(uint32_t*)&Yr[col]        = hp;
                    *(uint32_t*)&Yr[col + CC]   = lp;
                    *(uint32_t*)&Yr[col + 2*CC] = hp;
                }
            }
        }
    }
}

// generic GEMM (vp, projV)
template<int EPI>
__global__ __launch_bounds__(256, 2)
void hgemm(const __nv_bfloat16* __restrict__ A, const __nv_bfloat16* __restrict__ B,
           void* __restrict__ C, const float* __restrict__ bias, int Kp, int ldc)
{
    extern __shared__ char smem[];
    gemm_core<EPI>(A, B, C, bias, Kp, Kp, Kp, ldc,
                   blockIdx.y * 128, blockIdx.x * 128, 0, 0, smem);
}

// q+k projections fused: grid.y in [0,80): 0-63 q, 64-79 k
__global__ __launch_bounds__(256, 2)
void hgemm_projqk(const __nv_bfloat16* __restrict__ Aq, const __nv_bfloat16* __restrict__ Bq,
                  float* __restrict__ Cq,
                  const __nv_bfloat16* __restrict__ Ak, const __nv_bfloat16* __restrict__ Bk,
                  float* __restrict__ Ck)
{
    extern __shared__ char smem[];
    const int by = blockIdx.y;
    if (by < 64)
        gemm_core<0>(Aq, Bq, Cq, nullptr, K3, K3, K3, CC,
                     by * 128, blockIdx.x * 128, 0, 0, smem);
    else
        gemm_core<0>(Ak, Bk, Ck, nullptr, K3, K3, K3, CC,
                     (by - 64) * 128, blockIdx.x * 128, 0, 0, smem);
}

// sim split-K: z = (b-bbase)*2 + kh; partial kh -> S_kh[b*256*1024 ...]
__global__ __launch_bounds__(256, 2)
void hgemm_sim(const __nv_bfloat16* __restrict__ A, const __nv_bfloat16* __restrict__ B,
               float* __restrict__ S0, float* __restrict__ S1, int bbase)
{
    extern __shared__ char smem[];
    const int z = blockIdx.z;
    const int b = bbase + (z >> 1);
    const int kh = z & 1;
    gemm_core<0>(A + (long)b * 256 * K3 + kh * 768,
                 B + (long)b * 1024 * K3 + kh * 768,
                 kh ? S1 : S0, nullptr,
                 768, K3, K3, 1024,
                 blockIdx.y * 128, blockIdx.x * 128, b, (long)256 * 1024, smem);
}

// attn·v per-batch: x = Tt3_b · vT3_b^T + bias, scatter to (n,m,b,c)
__global__ __launch_bounds__(256, 2)
void hgemm_att(const __nv_bfloat16* __restrict__ Tt3, const __nv_bfloat16* __restrict__ vT3,
               float* __restrict__ out, const float* __restrict__ bias, int bbase)
{
    extern __shared__ char smem[];
    const int b = bbase + blockIdx.z;
    gemm_core<3>(Tt3 + (long)b * 1024 * 768, vT3 + (long)b * 512 * 768,
                 out, bias, 768, 768, 768, CC,
                 blockIdx.y * 128, blockIdx.x * 128, b, 0, smem);
}

// ---------------------------------------------------------------------------
// conv3 helpers
// ---------------------------------------------------------------------------
__device__ __forceinline__ void conv3_row(const float* __restrict__ in,
                                          __nv_bfloat16* __restrict__ out,
                                          int t, int mode)
{
    float4 v = ((const float4*)in)[t];
    __nv_bfloat16 h0,h1,h2,h3,l0,l1,l2,l3;
    split_bf16(v.x,h0,l0); split_bf16(v.y,h1,l1);
    split_bf16(v.z,h2,l2); split_bf16(v.w,h3,l3);
    ushort4 hp = make_ushort4(bfr(h0),bfr(h1),bfr(h2),bfr(h3));
    ushort4 lp = make_ushort4(bfr(l0),bfr(l1),bfr(l2),bfr(l3));
    ((ushort4*)(out))[t]        = hp;
    ((ushort4*)(out + CC))[t]   = mode ? hp : lp;
    ((ushort4*)(out + 2*CC))[t] = mode ? lp : hp;
}

__global__ void conv3_weights(const float* __restrict__ w0, __nv_bfloat16* __restrict__ o0,
                              const float* __restrict__ w1, __nv_bfloat16* __restrict__ o1,
                              const float* __restrict__ w2, __nv_bfloat16* __restrict__ o2,
                              const float* __restrict__ w3, __nv_bfloat16* __restrict__ o3)
{
    const int r = blockIdx.x;
    const int sel = r >> 9, rw = r & 511;
    const float* in; __nv_bfloat16* out;
    if (sel == 0)      { in = w0; out = o0; }
    else if (sel == 1) { in = w1; out = o1; }
    else if (sel == 2) { in = w2; out = o2; }
    else               { in = w3; out = o3; }
    conv3_row(in + (long)rw * CC, out + (long)rw * K3, threadIdx.x, 1);
}

__global__ void conv3_acts(const float* __restrict__ xq, __nv_bfloat16* __restrict__ oq,
                           const float* __restrict__ xk, __nv_bfloat16* __restrict__ ok,
                           const float* __restrict__ xv, __nv_bfloat16* __restrict__ ov)
{
    const int r = blockIdx.x;       // 0..12287
    const float* in; __nv_bfloat16* out; int rr;
    if (r < 8192)       { in = xq; out = oq; rr = r; }
    else if (r < 10240) { in = xk; out = ok; rr = r - 8192; }
    else                { in = xv; out = ov; rr = r - 10240; }
    conv3_row(in + (long)rr * CC, out + (long)rr * K3, threadIdx.x, 0);
}

// ---------------------------------------------------------------------------
// Fused norm: rows <8192 = q (reorder + MODE1), else k (MODE0).
// ---------------------------------------------------------------------------
__global__ void norm_fused(const float* __restrict__ qin, __nv_bfloat16* __restrict__ qout,
                           const float* __restrict__ kin, __nv_bfloat16* __restrict__ kout)
{
    const int r = blockIdx.x;
    const int t = threadIdx.x;
    const float* in;
    __nv_bfloat16* out;
    long orow;
    int mode;
    if (r < NROWS_Q) {
        in = qin + (long)r * CC;
        int n = r >> 7, m = (r >> 3) & 15, b = r & 7;
        orow = (long)(b * 1024 + m * 64 + n);
        out = qout; mode = 1;
    } else {
        int rk = r - NROWS_Q;
        in = kin + (long)rk * CC;
        orow = rk;
        out = kout; mode = 0;
    }
    float4 v = ((const float4*)in)[t];
    float ss = v.x*v.x + v.y*v.y + v.z*v.z + v.w*v.w;
#pragma unroll
    for (int o = 16; o; o >>= 1) ss += __shfl_xor_sync(0xffffffffu, ss, o);
    __shared__ float sw[4];
    if ((t & 31) == 0) sw[t >> 5] = ss;
    __syncthreads();
    float tot = sw[0] + sw[1] + sw[2] + sw[3];
    float scale = 1.0f / fmaxf(sqrtf(tot), 1e-12f);

    __nv_bfloat16 h0,h1,h2,h3,l0,l1,l2,l3;
    split_bf16(v.x*scale,h0,l0); split_bf16(v.y*scale,h1,l1);
    split_bf16(v.z*scale,h2,l2); split_bf16(v.w*scale,h3,l3);
    ushort4 hp = make_ushort4(bfr(h0),bfr(h1),bfr(h2),bfr(h3));
    ushort4 lp = make_ushort4(bfr(l0),bfr(l1),bfr(l2),bfr(l3));
    __nv_bfloat16* base = out + orow * K3;
    ((ushort4*)(base))[t]        = hp;
    ((ushort4*)(base + CC))[t]   = mode ? hp : lp;
    ((ushort4*)(base + 2*CC))[t] = mode ? lp : hp;
}

// ---------------------------------------------------------------------------
// Transpose + split-convert (B-mode): fp32 [b][256][W] -> bf16 [b][W][768]
// ---------------------------------------------------------------------------
template<int MODE>
__global__ void trconv_kernel(const float* __restrict__ in, __nv_bfloat16* __restrict__ out, int W)
{
    __shared__ float s[32][33];
    const int b = blockIdx.z;
    const float* ib = in + (long)b * 256 * W;
    __nv_bfloat16* ob = out + (long)b * W * 768;
    const int k0 = blockIdx.y * 32, w0 = blockIdx.x * 32;
    const int tx = threadIdx.x, ty = threadIdx.y;
#pragma unroll
    for (int i = 0; i < 4; i++)
        s[ty + 8*i][tx] = ib[(long)(k0 + ty + 8*i) * W + w0 + tx];
    __syncthreads();
#pragma unroll
    for (int i = 0; i < 4; i++) {
        const int wrow = w0 + ty + 8*i;
        float x = s[tx][ty + 8*i];
        __nv_bfloat16 h, l; split_bf16(x, h, l);
        __nv_bfloat16* p = ob + (long)wrow * 768 + k0 + tx;
        p[0]   = h;
        p[256] = MODE ? h : l;
        p[512] = MODE ? l : h;
    }
}

// ---------------------------------------------------------------------------
// Sinkhorn: one warp per (b,k) problem. Reads split-K partials S0+S1.
// Writes score AND transposed split-bf16 T (Tt3, A-mode [hi|lo|hi]) directly
// via an smem-staged transpose (8 warps = 8 consecutive k of one b).
// ---------------------------------------------------------------------------
__global__ __launch_bounds__(256)
void sinkhorn_kernel(const float* __restrict__ S0, const float* __restrict__ S1,
                     __nv_bfloat16* __restrict__ Tt3, float* __restrict__ score,
                     int p_off)
{
    __shared__ __align__(16) __nv_bfloat16 th[1024][8];
    __shared__ __align__(16) __nv_bfloat16 tl[1024][8];

    const int w    = threadIdx.x >> 5;
    const int lane = threadIdx.x & 31;
    const int p    = p_off + blockIdx.x * 8 + w;
    const float* s0 = S0 + (long)p * (MMQ * NQ);
    const float* s1 = S1 + (long)p * (MMQ * NQ);

    float Km[32];
#pragma unroll
    for (int i = 0; i < 16; i++) {
        Km[i]      = __expf((s0[i*64+lane]    + s1[i*64+lane]    - 1.0f) * INV_EPS);
        Km[i + 16] = __expf((s0[i*64+lane+32] + s1[i*64+lane+32] - 1.0f) * INV_EPS);
    }

    const float MU = 1.0f / 16.0f + 1e-8f;
    const float NU = 1.0f / 64.0f + 1e-8f;
    float b0 = 1.0f, b1 = 1.0f;
    float a[16];

#pragma unroll 1
    for (int iter = 0; iter < 100; iter++) {
        float v[16];
#pragma unroll
        for (int i = 0; i < 16; i++) v[i] = Km[i] * b0 + Km[i + 16] * b1;
#pragma unroll
        for (int i = 0; i < 8; i++) {
            float t0 = v[i], t1 = v[i + 8];
            float r0 = __shfl_xor_sync(0xffffffffu, t0, 16);
            float r1 = __shfl_xor_sync(0xffffffffu, t1, 16);
            v[i] = (lane & 16) ? (t1 + r1) : (t0 + r0);
        }
#pragma unroll
        for (int i = 0; i < 4; i++) {
            float t0 = v[i], t1 = v[i + 4];
            float r0 = __shfl_xor_sync(0xffffffffu, t0, 8);
            float r1 = __shfl_xor_sync(0xffffffffu, t1, 8);
            v[i] = (lane & 8) ? (t1 + r1) : (t0 + r0);
        }
#pragma unroll
        for (int i = 0; i < 2; i++) {
            float t0 = v[i], t1 = v[i + 2];
            float r0 = __shfl_xor_sync(0xffffffffu, t0, 4);
            float r1 = __shfl_xor_sync(0xffffffffu, t1, 4);
            v[i] = (lane & 4) ? (t1 + r1) : (t0 + r0);
        }
        {
            float t0 = v[0], t1 = v[1];
            float r0 = __shfl_xor_sync(0xffffffffu, t0, 2);
            float r1 = __shfl_xor_sync(0xffffffffu, t1, 2);
            v[0] = (lane & 2) ? (t1 + r1) : (t0 + r0);
        }
        v[0] += __shfl_xor_sync(0xffffffffu, v[0], 1);

        float av = __fdividef(MU, v[0]);
#pragma unroll
        for (int i = 0; i < 16; i++) a[i] = __shfl_sync(0xffffffffu, av, 2 * i);

        float c0a = 0.f, c0b = 0.f, c1a = 0.f, c1b = 0.f;
#pragma unroll
        for (int i = 0; i < 16; i += 2) {
            c0a += Km[i] * a[i];       c0b += Km[i + 1] * a[i + 1];
            c1a += Km[i + 16] * a[i];  c1b += Km[i + 17] * a[i + 1];
        }
        b0 = __fdividef(NU, c0a + c0b);
        b1 = __fdividef(NU, c1a + c1b);
    }

    // ---- epilogue: score + staged transpose of T into smem ----
    float* Srow = score + (long)p * (MMQ * NQ);
#pragma unroll
    for (int i = 0; i < 16; i++) {
        float T0 = a[i] * Km[i] * b0;
        float T1 = a[i] * Km[i + 16] * b1;
        float sv0 = s0[i*64+lane]    + s1[i*64+lane];
        float sv1 = s0[i*64+lane+32] + s1[i*64+lane+32];
        Srow[i * 64 + lane]      = 1024.0f * sv0 * T0;
        Srow[i * 64 + lane + 32] = 1024.0f * sv1 * T1;
        __nv_bfloat16 h, l;
        split_bf16(T0, h, l);
        th[i * 64 + lane][w] = h;  tl[i * 64 + lane][w] = l;
        split_bf16(T1, h, l);
        th[i * 64 + lane + 32][w] = h;  tl[i * 64 + lane + 32][w] = l;
    }
    __syncthreads();

    // write out: rows of Tt3[b], 8 k-columns (k0..k0+7) per row, A-mode trio
    const int pb = p_off + blockIdx.x * 8;
    const int b  = pb >> 8;
    const int k0 = pb & 255;
    __nv_bfloat16* base = Tt3 + (long)b * 1024 * 768 + k0;
#pragma unroll
    for (int r4 = 0; r4 < 4; r4++) {
        const int r = threadIdx.x * 4 + r4;
        __nv_bfloat16* d = base + (long)r * 768;
        uint4 hv = *(const uint4*)&th[r][0];
        uint4 lv = *(const uint4*)&tl[r][0];
        *(uint4*)(d)       = hv;
        *(uint4*)(d + 256) = lv;
        *(uint4*)(d + 512) = hv;
    }
}

// ---------------------------------------------------------------------------
extern "C" void kernel_launch(void* const* d_in, const int* in_sizes, int n_in,
                              void* d_out, int out_size)
{
    const float* xq = (const float*)d_in[0];
    const float* xk = (const float*)d_in[1];
    const float* xv = (const float*)d_in[2];
    const float* Wq = (const float*)d_in[3];
    const float* Wk = (const float*)d_in[4];
    const float* Wv = (const float*)d_in[5];
    const float* Wp = (const float*)d_in[6];
    const float* bp = (const float*)d_in[7];
    float* out_x     = (float*)d_out;
    float* out_score = out_x + X_ELEMS;

    __nv_bfloat16 *xq3,*xk3,*xv3,*wq3,*wk3,*wv3,*wp3,*qr3,*kn3,*Tt3,*vT3,*v3;
    float *qlin,*klin,*vp,*S0,*S1;
    cudaGetSymbolAddress((void**)&xq3, g_xq3);
    cudaGetSymbolAddress((void**)&xk3, g_xk3);
    cudaGetSymbolAddress((void**)&xv3, g_xv3);
    cudaGetSymbolAddress((void**)&wq3, g_wq3);
    cudaGetSymbolAddress((void**)&wk3, g_wk3);
    cudaGetSymbolAddress((void**)&wv3, g_wv3);
    cudaGetSymbolAddress((void**)&wp3, g_wp3);
    cudaGetSymbolAddress((void**)&qr3, g_qr3);
    cudaGetSymbolAddress((void**)&kn3, g_kn3);
    cudaGetSymbolAddress((void**)&Tt3, g_Tt3);
    cudaGetSymbolAddress((void**)&vT3, g_vT3);
    cudaGetSymbolAddress((void**)&v3,  g_v3);
    cudaGetSymbolAddress((void**)&qlin, g_qlin);
    cudaGetSymbolAddress((void**)&klin, g_klin);
    cudaGetSymbolAddress((void**)&vp,   g_v);
    cudaGetSymbolAddress((void**)&S0,   g_S0);
    cudaGetSymbolAddress((void**)&S1,   g_S1);

    cudaFuncSetAttribute(hgemm<0>,     cudaFuncAttributeMaxDynamicSharedMemorySize, GSMEM);
    cudaFuncSetAttribute(hgemm<2>,     cudaFuncAttributeMaxDynamicSharedMemorySize, GSMEM);
    cudaFuncSetAttribute(hgemm_projqk, cudaFuncAttributeMaxDynamicSharedMemorySize, GSMEM);
    cudaFuncSetAttribute(hgemm_sim,    cudaFuncAttributeMaxDynamicSharedMemorySize, GSMEM);
    cudaFuncSetAttribute(hgemm_att,    cudaFuncAttributeMaxDynamicSharedMemorySize, GSMEM);

    // streams/events (host objects; replays skip host code)
    cudaStream_t sA;
    cudaStreamCreateWithFlags(&sA, cudaStreamNonBlocking);
    cudaEvent_t eRoot, eW, eActs, eS1, eS2, eK1, eK2, eV;
    cudaEventCreateWithFlags(&eRoot, cudaEventDisableTiming);
    cudaEventCreateWithFlags(&eW,    cudaEventDisableTiming);
    cudaEventCreateWithFlags(&eActs, cudaEventDisableTiming);
    cudaEventCreateWithFlags(&eS1,   cudaEventDisableTiming);
    cudaEventCreateWithFlags(&eS2,   cudaEventDisableTiming);
    cudaEventCreateWithFlags(&eK1,   cudaEventDisableTiming);
    cudaEventCreateWithFlags(&eK2,   cudaEventDisableTiming);
    cudaEventCreateWithFlags(&eV,    cudaEventDisableTiming);

    // --- fork: weights conv (main) || acts conv (sA) ---
    cudaEventRecord(eRoot, 0);
    conv3_weights<<<4 * CC, 128>>>(Wq, wq3, Wk, wk3, Wv, wv3, Wp, wp3);
    cudaEventRecord(eW, 0);
    cudaStreamWaitEvent(sA, eRoot, 0);
    conv3_acts<<<12288, 128, 0, sA>>>(xq, xq3, xk, xk3, xv, xv3);
    cudaEventRecord(eActs, sA);

    // --- sA: v projection -> vp -> transpose (runs concurrent with projQK) ---
    cudaStreamWaitEvent(sA, eW, 0);
    hgemm<2><<<dim3(4, 16), 256, GSMEM, sA>>>(xv3, wv3, v3, nullptr, K3, 0);
    hgemm<0><<<dim3(4, 16), 256, GSMEM, sA>>>(v3, wp3, vp, nullptr, K3, CC);
    trconv_kernel<1><<<dim3(16, 8, 8), dim3(32, 8), 0, sA>>>(vp, vT3, 512);
    cudaEventRecord(eV, sA);

    // --- main: q+k projections ---
    cudaStreamWaitEvent(0, eActs, 0);
    hgemm_projqk<<<dim3(4, 80), 256, GSMEM>>>(xq3, wq3, qlin, xk3, wk3, klin);

    // --- l2 normalize (fused q+k), split-bf16 emit ---
    norm_fused<<<NROWS_Q + NROWS_K, 128>>>(qlin, qr3, klin, kn3);

    // --- sim split-K=2, batch halves, pipelined with sinkhorn ---
    hgemm_sim<<<dim3(8, 2, 8), 256, GSMEM>>>(kn3, qr3, S0, S1, 0);   // b 0-3
    cudaEventRecord(eS1, 0);
    hgemm_sim<<<dim3(8, 2, 8), 256, GSMEM>>>(kn3, qr3, S0, S1, 4);   // b 4-7
    cudaEventRecord(eS2, 0);

    cudaStreamWaitEvent(sA, eS1, 0);
    sinkhorn_kernel<<<128, 256, 0, sA>>>(S0, S1, Tt3, out_score, 0);     // b 0-3
    cudaEventRecord(eK1, sA);
    cudaStreamWaitEvent(sA, eS2, 0);
    sinkhorn_kernel<<<128, 256, 0, sA>>>(S0, S1, Tt3, out_score, 1024);  // b 4-7
    cudaEventRecord(eK2, sA);

    // --- attn·v halves (direct out scatter + bias) ---
    cudaStreamWaitEvent(0, eK1, 0);
    cudaStreamWaitEvent(0, eV, 0);
    hgemm_att<<<dim3(4, 8, 4), 256, GSMEM>>>(Tt3, vT3, out_x, bp, 0);   // b 0-3
    cudaStreamWaitEvent(0, eK2, 0);
    hgemm_att<<<dim3(4, 8, 4), 256, GSMEM>>>(Tt3, vT3, out_x, bp, 4);   // b 4-7
}

// round 11
// speedup vs baseline: 1.1900x; 1.1900x over previous
#include <cuda_runtime.h>
#include <cuda_bf16.h>
#include <cstdint>
#include <math.h>

// ---------------------------------------------------------------------------
// Problem constants
// ---------------------------------------------------------------------------
#define NQ   64
#define MMQ  16
#define BB   8
#define KK   256
#define CC   512
#define K3   1536           // 3*CC for split-bf16 GEMMs
#define NROWS_Q 8192
#define NROWS_K 2048
#define BKP     2048
#define INV_EPS 20.0f
#define X_ELEMS (NROWS_Q*CC)

// ---------------------------------------------------------------------------
// Scratch (device globals; no allocation allowed)
// ---------------------------------------------------------------------------
__device__ __nv_bfloat16 g_xq3[NROWS_Q*K3];
__device__ __nv_bfloat16 g_xk3[NROWS_K*K3];
__device__ __nv_bfloat16 g_xv3[NROWS_K*K3];
__device__ __nv_bfloat16 g_wq3[CC*K3];
__device__ __nv_bfloat16 g_wk3[CC*K3];
__device__ __nv_bfloat16 g_wv3[CC*K3];
__device__ __nv_bfloat16 g_wp3[CC*K3];
__device__ float g_qlin[NROWS_Q*CC];
__device__ float g_klin[NROWS_K*CC];
__device__ float g_v   [NROWS_K*CC];          // vp = v @ Wp^T (fp32)
__device__ __nv_bfloat16 g_qr3[NROWS_Q*K3];
__device__ __nv_bfloat16 g_kn3[NROWS_K*K3];
__device__ float g_S0[BKP*MMQ*NQ];            // sim split-K partial 0
__device__ float g_S1[BKP*MMQ*NQ];            // sim split-K partial 1
__device__ float g_T [BKP*MMQ*NQ];
__device__ __nv_bfloat16 g_Tt3[BB*1024*768];
__device__ __nv_bfloat16 g_vT3[BB*512*768];
__device__ __nv_bfloat16 g_v3[NROWS_K*K3];    // split-bf16 v (A-mode)

// ---------------------------------------------------------------------------
// PTX helpers
// ---------------------------------------------------------------------------
__device__ __forceinline__ uint32_t s2u(const void* p){
    uint32_t a;
    asm("{ .reg .u64 t; cvta.to.shared.u64 t, %1; cvt.u32.u64 %0, t; }"
        : "=r"(a) : "l"(p));
    return a;
}

#define CP_ASYNC16(dst, src) \
    asm volatile("cp.async.cg.shared.global [%0], [%1], 16;" :: "r"(dst), "l"(src) : "memory")
#define CP_COMMIT() asm volatile("cp.async.commit_group;" ::: "memory")
#define CP_WAIT1()  asm volatile("cp.async.wait_group 1;" ::: "memory")
#define CP_WAIT0()  asm volatile("cp.async.wait_group 0;" ::: "memory")

#define LDMATRIX_X4(r0, r1, r2, r3, addr) \
    asm volatile("ldmatrix.sync.aligned.m8n8.x4.shared.b16 {%0,%1,%2,%3}, [%4];" \
                 : "=r"(r0), "=r"(r1), "=r"(r2), "=r"(r3) : "r"(addr))

#define MMA16816(d, a, b0, b1) \
    asm volatile("mma.sync.aligned.m16n8k16.row.col.f32.bf16.bf16.f32 " \
                 "{%0,%1,%2,%3}, {%4,%5,%6,%7}, {%8,%9}, {%0,%1,%2,%3};" \
                 : "+f"((d)[0]), "+f"((d)[1]), "+f"((d)[2]), "+f"((d)[3]) \
                 : "r"((a)[0]), "r"((a)[1]), "r"((a)[2]), "r"((a)[3]), \
                   "r"(b0), "r"(b1))

__device__ __forceinline__ unsigned short bfr(__nv_bfloat16 h){
    return *reinterpret_cast<unsigned short*>(&h);
}
__device__ __forceinline__ void split_bf16(float x, __nv_bfloat16& h, __nv_bfloat16& l){
    h = __float2bfloat16(x);
    l = __float2bfloat16(x - __bfloat162float(h));
}
__device__ __forceinline__ uint32_t pack2(__nv_bfloat16 a, __nv_bfloat16 b){
    return (uint32_t)bfr(a) | ((uint32_t)bfr(b) << 16);
}

// ---------------------------------------------------------------------------
// HMMA GEMM core (R6-proven): C[M,N] = A(M,K')·B(N,K')ᵀ, K-major bf16,
// fp32 accum. CTA tile 128x128, BK=64, 3-stage cp.async ring,
// 8 warps (4m x 2n), warp tile 32x64, 256 threads, 2 CTAs/SM.
// lda/ldb allow K-slicing for split-K.
// EPI=0 fp32 store; EPI=2 split-bf16 A-mode emit; EPI=3 out scatter+bias.
// ---------------------------------------------------------------------------
#define STG   32768
#define GSMEM (3*STG)

template<int EPI>
__device__ __forceinline__
void gemm_core(const __nv_bfloat16* __restrict__ A, const __nv_bfloat16* __restrict__ B,
               void* __restrict__ Cv, const float* __restrict__ bias,
               int Kp, int lda, int ldb, int ldc, int mb, int nb, int bz,
               long cStride, char* smem)
{
    const int tid  = threadIdx.x;
    const int w    = tid >> 5;
    const int lane = tid & 31;
    const int wm   = (w & 3) * 32;
    const int wn   = (w >> 2) * 64;

    const uint32_t sbase = s2u(smem);
    const int NC = Kp >> 6;

    const int lrow = tid >> 1;
    const int lcg0 = (tid & 1) * 4;

    auto load_chunk = [&](int c, int s){
        const uint32_t st = sbase + s * STG;
        const __nv_bfloat16* Ag = A + (long)(mb + lrow) * lda + c * 64 + lcg0 * 8;
        const __nv_bfloat16* Bg = B + (long)(nb + lrow) * ldb + c * 64 + lcg0 * 8;
        const uint32_t rbase = lrow * 128;
        const uint32_t sw    = (lrow & 7) << 4;
#pragma unroll
        for (int j = 0; j < 4; j++) {
            uint32_t off = rbase + (((lcg0 + j) << 4) ^ sw);
            CP_ASYNC16(st + off, Ag + j * 8);
            CP_ASYNC16(st + 16384 + off, Bg + j * 8);
        }
        CP_COMMIT();
    };

    float acc[2][8][4];
#pragma unroll
    for (int i = 0; i < 2; i++)
#pragma unroll
        for (int j = 0; j < 8; j++)
#pragma unroll
            for (int q = 0; q < 4; q++) acc[i][j][q] = 0.f;

    load_chunk(0, 0);
    load_chunk(1, 1);

    const int a_r  = lane & 15;
    const int a_kb = (lane & 16);
    const int b_r  = ((lane >> 4) << 3) + (lane & 7);
    const int b_kb = ((lane >> 3) & 1) << 4;

    int stage = 0;
    for (int c = 0; c < NC; c++) {
        if (c + 1 < NC) CP_WAIT1(); else CP_WAIT0();
        __syncthreads();

        if (c + 2 < NC) {
            int ns = stage + 2; if (ns >= 3) ns -= 3;
            load_chunk(c + 2, ns);
        }

        const uint32_t sa = sbase + stage * STG;
        const uint32_t sb = sa + 16384;

        uint32_t br2[2][4][4];
#pragma unroll
        for (int nj = 0; nj < 4; nj++) {
            int row = wn + nj * 16 + b_r;
            uint32_t kb = (uint32_t)(b_kb) ^ ((row & 7) << 4);
            LDMATRIX_X4(br2[0][nj][0], br2[0][nj][1], br2[0][nj][2], br2[0][nj][3],
                        sb + row * 128 + kb);
        }
#pragma unroll
        for (int ks = 0; ks < 4; ks++) {
            const int cur = ks & 1;
            if (ks < 3) {
#pragma unroll
                for (int nj = 0; nj < 4; nj++) {
                    int row = wn + nj * 16 + b_r;
                    uint32_t kb = (uint32_t)((ks + 1) * 32 + b_kb) ^ ((row & 7) << 4);
                    LDMATRIX_X4(br2[cur ^ 1][nj][0], br2[cur ^ 1][nj][1],
                                br2[cur ^ 1][nj][2], br2[cur ^ 1][nj][3],
                                sb + row * 128 + kb);
                }
            }
            uint32_t ar[2][4];
#pragma unroll
            for (int mi = 0; mi < 2; mi++) {
                int row = wm + mi * 16 + a_r;
                uint32_t kb = (uint32_t)(ks * 32 + a_kb) ^ ((row & 7) << 4);
                LDMATRIX_X4(ar[mi][0], ar[mi][1], ar[mi][2], ar[mi][3],
                            sa + row * 128 + kb);
            }
#pragma unroll
            for (int mi = 0; mi < 2; mi++)
#pragma unroll
                for (int nj = 0; nj < 4; nj++) {
                    MMA16816(acc[mi][nj * 2],     ar[mi], br2[cur][nj][0], br2[cur][nj][1]);
                    MMA16816(acc[mi][nj * 2 + 1], ar[mi], br2[cur][nj][2], br2[cur][nj][3]);
                }
        }
        stage++; if (stage == 3) stage = 0;
    }

    // ---- epilogue ----
    const int er = lane >> 2;
    const int ec = (lane & 3) * 2;
#pragma unroll
    for (int mi = 0; mi < 2; mi++) {
#pragma unroll
        for (int half = 0; half < 2; half++) {
            const int R = mb + wm + mi * 16 + er + half * 8;
            if (EPI == 0) {
                float* Crow = (float*)Cv + (long)bz * cStride + (long)R * ldc;
#pragma unroll
                for (int nj = 0; nj < 8; nj++) {
                    const int col = nb + wn + nj * 8 + ec;
                    *(float2*)&Crow[col] =
                        make_float2(acc[mi][nj][half * 2], acc[mi][nj][half * 2 + 1]);
                }
            } else if (EPI == 3) {
                const int mq = R >> 6, nq = R & 63;
                float* Crow = (float*)Cv + (long)(((nq << 4) + mq) * 8 + bz) * CC;
#pragma unroll
                for (int nj = 0; nj < 8; nj++) {
                    const int col = nb + wn + nj * 8 + ec;
                    *(float2*)&Crow[col] = make_float2(
                        acc[mi][nj][half * 2] + bias[col],
                        acc[mi][nj][half * 2 + 1] + bias[col + 1]);
                }
            } else {
                // EPI==2: split-bf16 A-mode emit [hi|lo|hi]
                __nv_bfloat16* Yr = (__nv_bfloat16*)Cv + (long)bz * cStride + (long)R * K3;
#pragma unroll
                for (int nj = 0; nj < 8; nj++) {
                    const int col = nb + wn + nj * 8 + ec;
                    __nv_bfloat16 h0, l0, h1, l1;
                    split_bf16(acc[mi][nj][half * 2],     h0, l0);
                    split_bf16(acc[mi][nj][half * 2 + 1], h1, l1);
                    uint32_t hp = pack2(h0, h1), lp = pack2(l0, l1);
                    *(uint32_t*)&Yr[col]        = hp;
                    *(uint32_t*)&Yr[col + CC]   = lp;
                    *(uint32_t*)&Yr[col + 2*CC] = hp;
                }
            }
        }
    }
}

// generic GEMM (vp, attn·v)
template<int EPI>
__global__ __launch_bounds__(256, 2)
void hgemm(const __nv_bfloat16* __restrict__ A, const __nv_bfloat16* __restrict__ B,
           void* __restrict__ C, const float* __restrict__ bias,
           int Kp, int ldc, long aStride, long bStride, long cStride)
{
    extern __shared__ char smem[];
    const int bz = blockIdx.z;
    gemm_core<EPI>(A + bz * aStride, B + bz * bStride, C, bias,
                   Kp, Kp, Kp, ldc, blockIdx.y * 128, blockIdx.x * 128, bz,
                   cStride, smem);
}

// Fused q/k/v projection: grid.y in [0,96): 0-63 q, 64-79 k (fp32 out),
// 80-95 v (split-bf16 emit for the vp GEMM).
__global__ __launch_bounds__(256, 2)
void hgemm_proj(const __nv_bfloat16* __restrict__ Aq, const __nv_bfloat16* __restrict__ Bq,
                float* __restrict__ Cq,
                const __nv_bfloat16* __restrict__ Ak, const __nv_bfloat16* __restrict__ Bk,
                float* __restrict__ Ck,
                const __nv_bfloat16* __restrict__ Av, const __nv_bfloat16* __restrict__ Bv,
                __nv_bfloat16* __restrict__ Cv3)
{
    extern __shared__ char smem[];
    const int by = blockIdx.y;
    if (by < 64) {
        gemm_core<0>(Aq, Bq, Cq, nullptr, K3, K3, K3, CC,
                     by * 128, blockIdx.x * 128, 0, 0, smem);
    } else if (by < 80) {
        gemm_core<0>(Ak, Bk, Ck, nullptr, K3, K3, K3, CC,
                     (by - 64) * 128, blockIdx.x * 128, 0, 0, smem);
    } else {
        gemm_core<2>(Av, Bv, Cv3, nullptr, K3, K3, K3, 0,
                     (by - 80) * 128, blockIdx.x * 128, 0, 0, smem);
    }
}

// sim split-K=2, single launch: z = b*2 + kh -> partial kh of batch b
__global__ __launch_bounds__(256, 2)
void hgemm_sim(const __nv_bfloat16* __restrict__ A, const __nv_bfloat16* __restrict__ B,
               float* __restrict__ S0, float* __restrict__ S1)
{
    extern __shared__ char smem[];
    const int z = blockIdx.z;
    const int b = z >> 1;
    const int kh = z & 1;
    gemm_core<0>(A + (long)b * 256 * K3 + kh * 768,
                 B + (long)b * 1024 * K3 + kh * 768,
                 kh ? S1 : S0, nullptr,
                 768, K3, K3, 1024,
                 blockIdx.y * 128, blockIdx.x * 128, b, (long)256 * 1024, smem);
}

// ---------------------------------------------------------------------------
// conv3 helpers
// ---------------------------------------------------------------------------
__device__ __forceinline__ void conv3_row(const float* __restrict__ in,
                                          __nv_bfloat16* __restrict__ out,
                                          int t, int mode)
{
    float4 v = ((const float4*)in)[t];
    __nv_bfloat16 h0,h1,h2,h3,l0,l1,l2,l3;
    split_bf16(v.x,h0,l0); split_bf16(v.y,h1,l1);
    split_bf16(v.z,h2,l2); split_bf16(v.w,h3,l3);
    ushort4 hp = make_ushort4(bfr(h0),bfr(h1),bfr(h2),bfr(h3));
    ushort4 lp = make_ushort4(bfr(l0),bfr(l1),bfr(l2),bfr(l3));
    ((ushort4*)(out))[t]        = hp;
    ((ushort4*)(out + CC))[t]   = mode ? hp : lp;
    ((ushort4*)(out + 2*CC))[t] = mode ? lp : hp;
}

__global__ void conv3_weights(const float* __restrict__ w0, __nv_bfloat16* __restrict__ o0,
                              const float* __restrict__ w1, __nv_bfloat16* __restrict__ o1,
                              const float* __restrict__ w2, __nv_bfloat16* __restrict__ o2,
                              const float* __restrict__ w3, __nv_bfloat16* __restrict__ o3)
{
    const int r = blockIdx.x;
    const int sel = r >> 9, rw = r & 511;
    const float* in; __nv_bfloat16* out;
    if (sel == 0)      { in = w0; out = o0; }
    else if (sel == 1) { in = w1; out = o1; }
    else if (sel == 2) { in = w2; out = o2; }
    else               { in = w3; out = o3; }
    conv3_row(in + (long)rw * CC, out + (long)rw * K3, threadIdx.x, 1);
}

__global__ void conv3_acts(const float* __restrict__ xq, __nv_bfloat16* __restrict__ oq,
                           const float* __restrict__ xk, __nv_bfloat16* __restrict__ ok,
                           const float* __restrict__ xv, __nv_bfloat16* __restrict__ ov)
{
    const int r = blockIdx.x;       // 0..12287
    const float* in; __nv_bfloat16* out; int rr;
    if (r < 8192)       { in = xq; out = oq; rr = r; }
    else if (r < 10240) { in = xk; out = ok; rr = r - 8192; }
    else                { in = xv; out = ov; rr = r - 10240; }
    conv3_row(in + (long)rr * CC, out + (long)rr * K3, threadIdx.x, 0);
}

// ---------------------------------------------------------------------------
// Fused norm: rows <8192 = q (reorder + MODE1), else k (MODE0).
// ---------------------------------------------------------------------------
__global__ void norm_fused(const float* __restrict__ qin, __nv_bfloat16* __restrict__ qout,
                           const float* __restrict__ kin, __nv_bfloat16* __restrict__ kout)
{
    const int r = blockIdx.x;
    const int t = threadIdx.x;
    const float* in;
    __nv_bfloat16* out;
    long orow;
    int mode;
    if (r < NROWS_Q) {
        in = qin + (long)r * CC;
        int n = r >> 7, m = (r >> 3) & 15, b = r & 7;
        orow = (long)(b * 1024 + m * 64 + n);
        out = qout; mode = 1;
    } else {
        int rk = r - NROWS_Q;
        in = kin + (long)rk * CC;
        orow = rk;
        out = kout; mode = 0;
    }
    float4 v = ((const float4*)in)[t];
    float ss = v.x*v.x + v.y*v.y + v.z*v.z + v.w*v.w;
#pragma unroll
    for (int o = 16; o; o >>= 1) ss += __shfl_xor_sync(0xffffffffu, ss, o);
    __shared__ float sw[4];
    if ((t & 31) == 0) sw[t >> 5] = ss;
    __syncthreads();
    float tot = sw[0] + sw[1] + sw[2] + sw[3];
    float scale = 1.0f / fmaxf(sqrtf(tot), 1e-12f);

    __nv_bfloat16 h0,h1,h2,h3,l0,l1,l2,l3;
    split_bf16(v.x*scale,h0,l0); split_bf16(v.y*scale,h1,l1);
    split_bf16(v.z*scale,h2,l2); split_bf16(v.w*scale,h3,l3);
    ushort4 hp = make_ushort4(bfr(h0),bfr(h1),bfr(h2),bfr(h3));
    ushort4 lp = make_ushort4(bfr(l0),bfr(l1),bfr(l2),bfr(l3));
    __nv_bfloat16* base = out + orow * K3;
    ((ushort4*)(base))[t]        = hp;
    ((ushort4*)(base + CC))[t]   = mode ? hp : lp;
    ((ushort4*)(base + 2*CC))[t] = mode ? lp : hp;
}

// ---------------------------------------------------------------------------
// Transpose + split-convert: in fp32 [b][256][W] -> out bf16 [b][W][768]
// ---------------------------------------------------------------------------
template<int MODE>
__global__ void trconv_kernel(const float* __restrict__ in, __nv_bfloat16* __restrict__ out, int W)
{
    __shared__ float s[32][33];
    const int b = blockIdx.z;
    const float* ib = in + (long)b * 256 * W;
    __nv_bfloat16* ob = out + (long)b * W * 768;
    const int k0 = blockIdx.y * 32, w0 = blockIdx.x * 32;
    const int tx = threadIdx.x, ty = threadIdx.y;
#pragma unroll
    for (int i = 0; i < 4; i++)
        s[ty + 8*i][tx] = ib[(long)(k0 + ty + 8*i) * W + w0 + tx];
    __syncthreads();
#pragma unroll
    for (int i = 0; i < 4; i++) {
        const int wrow = w0 + ty + 8*i;
        float x = s[tx][ty + 8*i];
        __nv_bfloat16 h, l; split_bf16(x, h, l);
        __nv_bfloat16* p = ob + (long)wrow * 768 + k0 + tx;
        p[0]   = h;
        p[256] = MODE ? h : l;
        p[512] = MODE ? l : h;
    }
}

// ---------------------------------------------------------------------------
// Sinkhorn: one warp per (b,k) problem, scaling-domain, halving shfl tree.
// Reads split-K partials S0+S1; writes T (fp32) + score.
// ---------------------------------------------------------------------------
__global__ __launch_bounds__(256)
void sinkhorn_kernel(const float* __restrict__ S0, const float* __restrict__ S1,
                     float* __restrict__ T, float* __restrict__ score)
{
    const int p    = blockIdx.x * 8 + (threadIdx.x >> 5);
    const int lane = threadIdx.x & 31;
    const float* s0 = S0 + (long)p * (MMQ * NQ);
    const float* s1 = S1 + (long)p * (MMQ * NQ);

    float Km[32];
#pragma unroll
    for (int i = 0; i < 16; i++) {
        Km[i]      = __expf((s0[i*64+lane]    + s1[i*64+lane]    - 1.0f) * INV_EPS);
        Km[i + 16] = __expf((s0[i*64+lane+32] + s1[i*64+lane+32] - 1.0f) * INV_EPS);
    }

    const float MU = 1.0f / 16.0f + 1e-8f;
    const float NU = 1.0f / 64.0f + 1e-8f;
    float b0 = 1.0f, b1 = 1.0f;
    float a[16];

#pragma unroll 1
    for (int iter = 0; iter < 100; iter++) {
        float v[16];
#pragma unroll
        for (int i = 0; i < 16; i++) v[i] = Km[i] * b0 + Km[i + 16] * b1;
#pragma unroll
        for (int i = 0; i < 8; i++) {
            float t0 = v[i], t1 = v[i + 8];
            float r0 = __shfl_xor_sync(0xffffffffu, t0, 16);
            float r1 = __shfl_xor_sync(0xffffffffu, t1, 16);
            v[i] = (lane & 16) ? (t1 + r1) : (t0 + r0);
        }
#pragma unroll
        for (int i = 0; i < 4; i++) {
            float t0 = v[i], t1 = v[i + 4];
            float r0 = __shfl_xor_sync(0xffffffffu, t0, 8);
            float r1 = __shfl_xor_sync(0xffffffffu, t1, 8);
            v[i] = (lane & 8) ? (t1 + r1) : (t0 + r0);
        }
#pragma unroll
        for (int i = 0; i < 2; i++) {
            float t0 = v[i], t1 = v[i + 2];
            float r0 = __shfl_xor_sync(0xffffffffu, t0, 4);
            float r1 = __shfl_xor_sync(0xffffffffu, t1, 4);
            v[i] = (lane & 4) ? (t1 + r1) : (t0 + r0);
        }
        {
            float t0 = v[0], t1 = v[1];
            float r0 = __shfl_xor_sync(0xffffffffu, t0, 2);
            float r1 = __shfl_xor_sync(0xffffffffu, t1, 2);
            v[0] = (lane & 2) ? (t1 + r1) : (t0 + r0);
        }
        v[0] += __shfl_xor_sync(0xffffffffu, v[0], 1);

        float av = __fdividef(MU, v[0]);
#pragma unroll
        for (int i = 0; i < 16; i++) a[i] = __shfl_sync(0xffffffffu, av, 2 * i);

        float c0a = 0.f, c0b = 0.f, c1a = 0.f, c1b = 0.f;
#pragma unroll
        for (int i = 0; i < 16; i += 2) {
            c0a += Km[i] * a[i];       c0b += Km[i + 1] * a[i + 1];
            c1a += Km[i + 16] * a[i];  c1b += Km[i + 17] * a[i + 1];
        }
        b0 = __fdividef(NU, c0a + c0b);
        b1 = __fdividef(NU, c1a + c1b);
    }

    float* Trow = T + (long)p * (MMQ * NQ);
    float* Srow = score + (long)p * (MMQ * NQ);
#pragma unroll
    for (int i = 0; i < 16; i++) {
        float T0 = a[i] * Km[i] * b0;
        float T1 = a[i] * Km[i + 16] * b1;
        float sv0 = s0[i*64+lane]    + s1[i*64+lane];
        float sv1 = s0[i*64+lane+32] + s1[i*64+lane+32];
        Trow[i * 64 + lane]      = T0;
        Trow[i * 64 + lane + 32] = T1;
        Srow[i * 64 + lane]      = 1024.0f * sv0 * T0;
        Srow[i * 64 + lane + 32] = 1024.0f * sv1 * T1;
    }
}

// ---------------------------------------------------------------------------
extern "C" void kernel_launch(void* const* d_in, const int* in_sizes, int n_in,
                              void* d_out, int out_size)
{
    const float* xq = (const float*)d_in[0];
    const float* xk = (const float*)d_in[1];
    const float* xv = (const float*)d_in[2];
    const float* Wq = (const float*)d_in[3];
    const float* Wk = (const float*)d_in[4];
    const float* Wv = (const float*)d_in[5];
    const float* Wp = (const float*)d_in[6];
    const float* bp = (const float*)d_in[7];
    float* out_x     = (float*)d_out;
    float* out_score = out_x + X_ELEMS;

    __nv_bfloat16 *xq3,*xk3,*xv3,*wq3,*wk3,*wv3,*wp3,*qr3,*kn3,*Tt3,*vT3,*v3;
    float *qlin,*klin,*vp,*S0,*S1,*T;
    cudaGetSymbolAddress((void**)&xq3, g_xq3);
    cudaGetSymbolAddress((void**)&xk3, g_xk3);
    cudaGetSymbolAddress((void**)&xv3, g_xv3);
    cudaGetSymbolAddress((void**)&wq3, g_wq3);
    cudaGetSymbolAddress((void**)&wk3, g_wk3);
    cudaGetSymbolAddress((void**)&wv3, g_wv3);
    cudaGetSymbolAddress((void**)&wp3, g_wp3);
    cudaGetSymbolAddress((void**)&qr3, g_qr3);
    cudaGetSymbolAddress((void**)&kn3, g_kn3);
    cudaGetSymbolAddress((void**)&Tt3, g_Tt3);
    cudaGetSymbolAddress((void**)&vT3, g_vT3);
    cudaGetSymbolAddress((void**)&v3,  g_v3);
    cudaGetSymbolAddress((void**)&qlin, g_qlin);
    cudaGetSymbolAddress((void**)&klin, g_klin);
    cudaGetSymbolAddress((void**)&vp,   g_v);
    cudaGetSymbolAddress((void**)&S0,   g_S0);
    cudaGetSymbolAddress((void**)&S1,   g_S1);
    cudaGetSymbolAddress((void**)&T,    g_T);

    cudaFuncSetAttribute(hgemm<0>,   cudaFuncAttributeMaxDynamicSharedMemorySize, GSMEM);
    cudaFuncSetAttribute(hgemm<3>,   cudaFuncAttributeMaxDynamicSharedMemorySize, GSMEM);
    cudaFuncSetAttribute(hgemm_proj, cudaFuncAttributeMaxDynamicSharedMemorySize, GSMEM);
    cudaFuncSetAttribute(hgemm_sim,  cudaFuncAttributeMaxDynamicSharedMemorySize, GSMEM);

    // Side stream + events for fork/join (host objects; graph replays skip host code)
    cudaStream_t sA;
    cudaStreamCreateWithFlags(&sA, cudaStreamNonBlocking);
    cudaEvent_t eRoot, eActs, eProj, eV;
    cudaEventCreateWithFlags(&eRoot, cudaEventDisableTiming);
    cudaEventCreateWithFlags(&eActs, cudaEventDisableTiming);
    cudaEventCreateWithFlags(&eProj, cudaEventDisableTiming);
    cudaEventCreateWithFlags(&eV,    cudaEventDisableTiming);

    // --- fork: weights conv (main) || acts conv (sA) ---
    cudaEventRecord(eRoot, 0);
    conv3_weights<<<4 * CC, 128>>>(Wq, wq3, Wk, wk3, Wv, wv3, Wp, wp3);
    cudaStreamWaitEvent(sA, eRoot, 0);
    conv3_acts<<<12288, 128, 0, sA>>>(xq, xq3, xk, xk3, xv, xv3);
    cudaEventRecord(eActs, sA);
    cudaStreamWaitEvent(0, eActs, 0);

    // --- q/k/v projections: single fused launch (v emits split-bf16) ---
    hgemm_proj<<<dim3(4, 96, 1), 256, GSMEM>>>(
        xq3, wq3, qlin, xk3, wk3, klin, xv3, wv3, v3);
    cudaEventRecord(eProj, 0);

    // --- fork (sA): vp = v·Wp^T, then transpose+split — overlapped with
    //     norm + sim + sinkhorn on main ---
    cudaStreamWaitEvent(sA, eProj, 0);
    hgemm<0><<<dim3(4, 16, 1), 256, GSMEM, sA>>>(
        v3, wp3, vp, nullptr, K3, CC, 0, 0, 0);
    trconv_kernel<1><<<dim3(16, 8, 8), dim3(32, 8), 0, sA>>>(vp, vT3, 512);
    cudaEventRecord(eV, sA);

    // --- main: l2 normalize (fused q+k) ---
    norm_fused<<<NROWS_Q + NROWS_K, 128>>>(qlin, qr3, klin, kn3);

    // --- sim split-K=2, single launch, 256 CTAs (full chip) ---
    hgemm_sim<<<dim3(8, 2, 16), 256, GSMEM>>>(kn3, qr3, S0, S1);

    // --- Sinkhorn (reads S0+S1) -> T + score_map ---
    sinkhorn_kernel<<<BKP / 8, 256>>>(S0, S1, T, out_score);

    // --- T transpose ---
    trconv_kernel<0><<<dim3(32, 8, 8), dim3(32, 8)>>>(T, Tt3, 1024);

    // --- join vp path; x = T^T·vp + bp with direct scatter to (n,m,b,c) ---
    cudaStreamWaitEvent(0, eV, 0);
    hgemm<3><<<dim3(4, 8, 8), 256, GSMEM>>>(
        Tt3, vT3, out_x, bp, 768, CC,
        (long)1024 * 768, (long)512 * 768, 0);
}

// round 12
// speedup vs baseline: 1.2290x; 1.0328x over previous
#include <cuda_runtime.h>
#include <cuda_bf16.h>
#include <cstdint>
#include <math.h>

// ---------------------------------------------------------------------------
// Problem constants
// ---------------------------------------------------------------------------
#define NQ   64
#define MMQ  16
#define BB   8
#define KK   256
#define CC   512
#define K3   1536           // 3*CC for split-bf16 GEMMs
#define NROWS_Q 8192
#define NROWS_K 2048
#define BKP     2048
#define INV_EPS 20.0f
#define X_ELEMS (NROWS_Q*CC)

// ---------------------------------------------------------------------------
// Scratch (device globals; no allocation allowed)
// ---------------------------------------------------------------------------
__device__ __nv_bfloat16 g_xq3[NROWS_Q*K3];
__device__ __nv_bfloat16 g_xk3[NROWS_K*K3];
__device__ __nv_bfloat16 g_xv3[NROWS_K*K3];
__device__ __nv_bfloat16 g_wq3[CC*K3];
__device__ __nv_bfloat16 g_wk3[CC*K3];
__device__ __nv_bfloat16 g_wv3[CC*K3];
__device__ __nv_bfloat16 g_wp3[CC*K3];
__device__ float g_qlin[NROWS_Q*CC];
__device__ float g_klin[NROWS_K*CC];
__device__ float g_v   [NROWS_K*CC];          // vp = v @ Wp^T (fp32)
__device__ __nv_bfloat16 g_qr3[NROWS_Q*K3];
__device__ __nv_bfloat16 g_kn3[NROWS_K*K3];
__device__ float g_S0[BKP*MMQ*NQ];            // sim split-K partial 0
__device__ float g_S1[BKP*MMQ*NQ];            // sim split-K partial 1
__device__ float g_T [BKP*MMQ*NQ];
__device__ __nv_bfloat16 g_Tt3[BB*1024*768];
__device__ __nv_bfloat16 g_vT3[BB*512*768];
__device__ __nv_bfloat16 g_v3[NROWS_K*K3];    // split-bf16 v (A-mode)

// ---------------------------------------------------------------------------
// PTX helpers
// ---------------------------------------------------------------------------
__device__ __forceinline__ uint32_t s2u(const void* p){
    uint32_t a;
    asm("{ .reg .u64 t; cvta.to.shared.u64 t, %1; cvt.u32.u64 %0, t; }"
        : "=r"(a) : "l"(p));
    return a;
}

#define CP_ASYNC16(dst, src) \
    asm volatile("cp.async.cg.shared.global [%0], [%1], 16;" :: "r"(dst), "l"(src) : "memory")
#define CP_COMMIT() asm volatile("cp.async.commit_group;" ::: "memory")
#define CP_WAIT1()  asm volatile("cp.async.wait_group 1;" ::: "memory")
#define CP_WAIT0()  asm volatile("cp.async.wait_group 0;" ::: "memory")

#define LDMATRIX_X4(r0, r1, r2, r3, addr) \
    asm volatile("ldmatrix.sync.aligned.m8n8.x4.shared.b16 {%0,%1,%2,%3}, [%4];" \
                 : "=r"(r0), "=r"(r1), "=r"(r2), "=r"(r3) : "r"(addr))

#define MMA16816(d, a, b0, b1) \
    asm volatile("mma.sync.aligned.m16n8k16.row.col.f32.bf16.bf16.f32 " \
                 "{%0,%1,%2,%3}, {%4,%5,%6,%7}, {%8,%9}, {%0,%1,%2,%3};" \
                 : "+f"((d)[0]), "+f"((d)[1]), "+f"((d)[2]), "+f"((d)[3]) \
                 : "r"((a)[0]), "r"((a)[1]), "r"((a)[2]), "r"((a)[3]), \
                   "r"(b0), "r"(b1))

__device__ __forceinline__ unsigned short bfr(__nv_bfloat16 h){
    return *reinterpret_cast<unsigned short*>(&h);
}
__device__ __forceinline__ void split_bf16(float x, __nv_bfloat16& h, __nv_bfloat16& l){
    h = __float2bfloat16(x);
    l = __float2bfloat16(x - __bfloat162float(h));
}
__device__ __forceinline__ uint32_t pack2(__nv_bfloat16 a, __nv_bfloat16 b){
    return (uint32_t)bfr(a) | ((uint32_t)bfr(b) << 16);
}

// ---------------------------------------------------------------------------
// HMMA GEMM core (R6-proven): C[M,N] = A(M,K')·B(N,K')ᵀ, K-major bf16,
// fp32 accum. CTA tile 128x128, BK=64, 3-stage cp.async ring,
// 8 warps (4m x 2n), warp tile 32x64, 256 threads, 2 CTAs/SM.
// lda/ldb allow K-slicing for split-K.
// EPI=0 fp32 store; EPI=2 split-bf16 A-mode emit; EPI=3 out scatter+bias.
// ---------------------------------------------------------------------------
#define STG   32768
#define GSMEM (3*STG)

template<int EPI>
__device__ __forceinline__
void gemm_core(const __nv_bfloat16* __restrict__ A, const __nv_bfloat16* __restrict__ B,
               void* __restrict__ Cv, const float* __restrict__ bias,
               int Kp, int lda, int ldb, int ldc, int mb, int nb, int bz,
               long cStride, char* smem)
{
    const int tid  = threadIdx.x;
    const int w    = tid >> 5;
    const int lane = tid & 31;
    const int wm   = (w & 3) * 32;
    const int wn   = (w >> 2) * 64;

    const uint32_t sbase = s2u(smem);
    const int NC = Kp >> 6;

    const int lrow = tid >> 1;
    const int lcg0 = (tid & 1) * 4;

    auto load_chunk = [&](int c, int s){
        const uint32_t st = sbase + s * STG;
        const __nv_bfloat16* Ag = A + (long)(mb + lrow) * lda + c * 64 + lcg0 * 8;
        const __nv_bfloat16* Bg = B + (long)(nb + lrow) * ldb + c * 64 + lcg0 * 8;
        const uint32_t rbase = lrow * 128;
        const uint32_t sw    = (lrow & 7) << 4;
#pragma unroll
        for (int j = 0; j < 4; j++) {
            uint32_t off = rbase + (((lcg0 + j) << 4) ^ sw);
            CP_ASYNC16(st + off, Ag + j * 8);
            CP_ASYNC16(st + 16384 + off, Bg + j * 8);
        }
        CP_COMMIT();
    };

    float acc[2][8][4];
#pragma unroll
    for (int i = 0; i < 2; i++)
#pragma unroll
        for (int j = 0; j < 8; j++)
#pragma unroll
            for (int q = 0; q < 4; q++) acc[i][j][q] = 0.f;

    load_chunk(0, 0);
    load_chunk(1, 1);

    const int a_r  = lane & 15;
    const int a_kb = (lane & 16);
    const int b_r  = ((lane >> 4) << 3) + (lane & 7);
    const int b_kb = ((lane >> 3) & 1) << 4;

    int stage = 0;
    for (int c = 0; c < NC; c++) {
        if (c + 1 < NC) CP_WAIT1(); else CP_WAIT0();
        __syncthreads();

        if (c + 2 < NC) {
            int ns = stage + 2; if (ns >= 3) ns -= 3;
            load_chunk(c + 2, ns);
        }

        const uint32_t sa = sbase + stage * STG;
        const uint32_t sb = sa + 16384;

        uint32_t br2[2][4][4];
#pragma unroll
        for (int nj = 0; nj < 4; nj++) {
            int row = wn + nj * 16 + b_r;
            uint32_t kb = (uint32_t)(b_kb) ^ ((row & 7) << 4);
            LDMATRIX_X4(br2[0][nj][0], br2[0][nj][1], br2[0][nj][2], br2[0][nj][3],
                        sb + row * 128 + kb);
        }
#pragma unroll
        for (int ks = 0; ks < 4; ks++) {
            const int cur = ks & 1;
            if (ks < 3) {
#pragma unroll
                for (int nj = 0; nj < 4; nj++) {
                    int row = wn + nj * 16 + b_r;
                    uint32_t kb = (uint32_t)((ks + 1) * 32 + b_kb) ^ ((row & 7) << 4);
                    LDMATRIX_X4(br2[cur ^ 1][nj][0], br2[cur ^ 1][nj][1],
                                br2[cur ^ 1][nj][2], br2[cur ^ 1][nj][3],
                                sb + row * 128 + kb);
                }
            }
            uint32_t ar[2][4];
#pragma unroll
            for (int mi = 0; mi < 2; mi++) {
                int row = wm + mi * 16 + a_r;
                uint32_t kb = (uint32_t)(ks * 32 + a_kb) ^ ((row & 7) << 4);
                LDMATRIX_X4(ar[mi][0], ar[mi][1], ar[mi][2], ar[mi][3],
                            sa + row * 128 + kb);
            }
#pragma unroll
            for (int mi = 0; mi < 2; mi++)
#pragma unroll
                for (int nj = 0; nj < 4; nj++) {
                    MMA16816(acc[mi][nj * 2],     ar[mi], br2[cur][nj][0], br2[cur][nj][1]);
                    MMA16816(acc[mi][nj * 2 + 1], ar[mi], br2[cur][nj][2], br2[cur][nj][3]);
                }
        }
        stage++; if (stage == 3) stage = 0;
    }

    // ---- epilogue ----
    const int er = lane >> 2;
    const int ec = (lane & 3) * 2;
#pragma unroll
    for (int mi = 0; mi < 2; mi++) {
#pragma unroll
        for (int half = 0; half < 2; half++) {
            const int R = mb + wm + mi * 16 + er + half * 8;
            if (EPI == 0) {
                float* Crow = (float*)Cv + (long)bz * cStride + (long)R * ldc;
#pragma unroll
                for (int nj = 0; nj < 8; nj++) {
                    const int col = nb + wn + nj * 8 + ec;
                    *(float2*)&Crow[col] =
                        make_float2(acc[mi][nj][half * 2], acc[mi][nj][half * 2 + 1]);
                }
            } else if (EPI == 3) {
                const int mq = R >> 6, nq = R & 63;
                float* Crow = (float*)Cv + (long)(((nq << 4) + mq) * 8 + bz) * CC;
#pragma unroll
                for (int nj = 0; nj < 8; nj++) {
                    const int col = nb + wn + nj * 8 + ec;
                    *(float2*)&Crow[col] = make_float2(
                        acc[mi][nj][half * 2] + bias[col],
                        acc[mi][nj][half * 2 + 1] + bias[col + 1]);
                }
            } else {
                // EPI==2: split-bf16 A-mode emit [hi|lo|hi]
                __nv_bfloat16* Yr = (__nv_bfloat16*)Cv + (long)bz * cStride + (long)R * K3;
#pragma unroll
                for (int nj = 0; nj < 8; nj++) {
                    const int col = nb + wn + nj * 8 + ec;
                    __nv_bfloat16 h0, l0, h1, l1;
                    split_bf16(acc[mi][nj][half * 2],     h0, l0);
                    split_bf16(acc[mi][nj][half * 2 + 1], h1, l1);
                    uint32_t hp = pack2(h0, h1), lp = pack2(l0, l1);
                    *(uint32_t*)&Yr[col]        = hp;
                    *(uint32_t*)&Yr[col + CC]   = lp;
                    *(uint32_t*)&Yr[col + 2*CC] = hp;
                }
            }
        }
    }
}

// generic GEMM (vp, attn·v, projV)
template<int EPI>
__global__ __launch_bounds__(256, 2)
void hgemm(const __nv_bfloat16* __restrict__ A, const __nv_bfloat16* __restrict__ B,
           void* __restrict__ C, const float* __restrict__ bias,
           int Kp, int ldc, long aStride, long bStride, long cStride)
{
    extern __shared__ char smem[];
    const int bz = blockIdx.z;
    gemm_core<EPI>(A + bz * aStride, B + bz * bStride, C, bias,
                   Kp, Kp, Kp, ldc, blockIdx.y * 128, blockIdx.x * 128, bz,
                   cStride, smem);
}

// q+k projections fused: grid.y in [0,80): 0-63 q, 64-79 k
__global__ __launch_bounds__(256, 2)
void hgemm_projqk(const __nv_bfloat16* __restrict__ Aq, const __nv_bfloat16* __restrict__ Bq,
                  float* __restrict__ Cq,
                  const __nv_bfloat16* __restrict__ Ak, const __nv_bfloat16* __restrict__ Bk,
                  float* __restrict__ Ck)
{
    extern __shared__ char smem[];
    const int by = blockIdx.y;
    if (by < 64)
        gemm_core<0>(Aq, Bq, Cq, nullptr, K3, K3, K3, CC,
                     by * 128, blockIdx.x * 128, 0, 0, smem);
    else
        gemm_core<0>(Ak, Bk, Ck, nullptr, K3, K3, K3, CC,
                     (by - 64) * 128, blockIdx.x * 128, 0, 0, smem);
}

// sim split-K=2, single launch: z = b*2 + kh -> partial kh of batch b
__global__ __launch_bounds__(256, 2)
void hgemm_sim(const __nv_bfloat16* __restrict__ A, const __nv_bfloat16* __restrict__ B,
               float* __restrict__ S0, float* __restrict__ S1)
{
    extern __shared__ char smem[];
    const int z = blockIdx.z;
    const int b = z >> 1;
    const int kh = z & 1;
    gemm_core<0>(A + (long)b * 256 * K3 + kh * 768,
                 B + (long)b * 1024 * K3 + kh * 768,
                 kh ? S1 : S0, nullptr,
                 768, K3, K3, 1024,
                 blockIdx.y * 128, blockIdx.x * 128, b, (long)256 * 1024, smem);
}

// ---------------------------------------------------------------------------
// conv3 helpers
// ---------------------------------------------------------------------------
__device__ __forceinline__ void conv3_row(const float* __restrict__ in,
                                          __nv_bfloat16* __restrict__ out,
                                          int t, int mode)
{
    float4 v = ((const float4*)in)[t];
    __nv_bfloat16 h0,h1,h2,h3,l0,l1,l2,l3;
    split_bf16(v.x,h0,l0); split_bf16(v.y,h1,l1);
    split_bf16(v.z,h2,l2); split_bf16(v.w,h3,l3);
    ushort4 hp = make_ushort4(bfr(h0),bfr(h1),bfr(h2),bfr(h3));
    ushort4 lp = make_ushort4(bfr(l0),bfr(l1),bfr(l2),bfr(l3));
    ((ushort4*)(out))[t]        = hp;
    ((ushort4*)(out + CC))[t]   = mode ? hp : lp;
    ((ushort4*)(out + 2*CC))[t] = mode ? lp : hp;
}

__global__ void conv3_weights(const float* __restrict__ w0, __nv_bfloat16* __restrict__ o0,
                              const float* __restrict__ w1, __nv_bfloat16* __restrict__ o1,
                              const float* __restrict__ w2, __nv_bfloat16* __restrict__ o2,
                              const float* __restrict__ w3, __nv_bfloat16* __restrict__ o3)
{
    const int r = blockIdx.x;
    const int sel = r >> 9, rw = r & 511;
    const float* in; __nv_bfloat16* out;
    if (sel == 0)      { in = w0; out = o0; }
    else if (sel == 1) { in = w1; out = o1; }
    else if (sel == 2) { in = w2; out = o2; }
    else               { in = w3; out = o3; }
    conv3_row(in + (long)rw * CC, out + (long)rw * K3, threadIdx.x, 1);
}

__global__ void conv3_acts(const float* __restrict__ xq, __nv_bfloat16* __restrict__ oq,
                           const float* __restrict__ xk, __nv_bfloat16* __restrict__ ok,
                           const float* __restrict__ xv, __nv_bfloat16* __restrict__ ov)
{
    const int r = blockIdx.x;       // 0..12287
    const float* in; __nv_bfloat16* out; int rr;
    if (r < 8192)       { in = xq; out = oq; rr = r; }
    else if (r < 10240) { in = xk; out = ok; rr = r - 8192; }
    else                { in = xv; out = ov; rr = r - 10240; }
    conv3_row(in + (long)rr * CC, out + (long)rr * K3, threadIdx.x, 0);
}

// ---------------------------------------------------------------------------
// Fused norm: rows <8192 = q (reorder + MODE1), else k (MODE0).
// ---------------------------------------------------------------------------
__global__ void norm_fused(const float* __restrict__ qin, __nv_bfloat16* __restrict__ qout,
                           const float* __restrict__ kin, __nv_bfloat16* __restrict__ kout)
{
    const int r = blockIdx.x;
    const int t = threadIdx.x;
    const float* in;
    __nv_bfloat16* out;
    long orow;
    int mode;
    if (r < NROWS_Q) {
        in = qin + (long)r * CC;
        int n = r >> 7, m = (r >> 3) & 15, b = r & 7;
        orow = (long)(b * 1024 + m * 64 + n);
        out = qout; mode = 1;
    } else {
        int rk = r - NROWS_Q;
        in = kin + (long)rk * CC;
        orow = rk;
        out = kout; mode = 0;
    }
    float4 v = ((const float4*)in)[t];
    float ss = v.x*v.x + v.y*v.y + v.z*v.z + v.w*v.w;
#pragma unroll
    for (int o = 16; o; o >>= 1) ss += __shfl_xor_sync(0xffffffffu, ss, o);
    __shared__ float sw[4];
    if ((t & 31) == 0) sw[t >> 5] = ss;
    __syncthreads();
    float tot = sw[0] + sw[1] + sw[2] + sw[3];
    float scale = 1.0f / fmaxf(sqrtf(tot), 1e-12f);

    __nv_bfloat16 h0,h1,h2,h3,l0,l1,l2,l3;
    split_bf16(v.x*scale,h0,l0); split_bf16(v.y*scale,h1,l1);
    split_bf16(v.z*scale,h2,l2); split_bf16(v.w*scale,h3,l3);
    ushort4 hp = make_ushort4(bfr(h0),bfr(h1),bfr(h2),bfr(h3));
    ushort4 lp = make_ushort4(bfr(l0),bfr(l1),bfr(l2),bfr(l3));
    __nv_bfloat16* base = out + orow * K3;
    ((ushort4*)(base))[t]        = hp;
    ((ushort4*)(base + CC))[t]   = mode ? hp : lp;
    ((ushort4*)(base + 2*CC))[t] = mode ? lp : hp;
}

// ---------------------------------------------------------------------------
// Transpose + split-convert: in fp32 [b][256][W] -> out bf16 [b][W][768]
// ---------------------------------------------------------------------------
template<int MODE>
__global__ void trconv_kernel(const float* __restrict__ in, __nv_bfloat16* __restrict__ out, int W)
{
    __shared__ float s[32][33];
    const int b = blockIdx.z;
    const float* ib = in + (long)b * 256 * W;
    __nv_bfloat16* ob = out + (long)b * W * 768;
    const int k0 = blockIdx.y * 32, w0 = blockIdx.x * 32;
    const int tx = threadIdx.x, ty = threadIdx.y;
#pragma unroll
    for (int i = 0; i < 4; i++)
        s[ty + 8*i][tx] = ib[(long)(k0 + ty + 8*i) * W + w0 + tx];
    __syncthreads();
#pragma unroll
    for (int i = 0; i < 4; i++) {
        const int wrow = w0 + ty + 8*i;
        float x = s[tx][ty + 8*i];
        __nv_bfloat16 h, l; split_bf16(x, h, l);
        __nv_bfloat16* p = ob + (long)wrow * 768 + k0 + tx;
        p[0]   = h;
        p[256] = MODE ? h : l;
        p[512] = MODE ? l : h;
    }
}

// ---------------------------------------------------------------------------
// Sinkhorn: one warp per (b,k) problem, scaling-domain, halving shfl tree.
// Reads split-K partials S0+S1; writes T (fp32) + score.
// ---------------------------------------------------------------------------
__global__ __launch_bounds__(256)
void sinkhorn_kernel(const float* __restrict__ S0, const float* __restrict__ S1,
                     float* __restrict__ T, float* __restrict__ score)
{
    const int p    = blockIdx.x * 8 + (threadIdx.x >> 5);
    const int lane = threadIdx.x & 31;
    const float* s0 = S0 + (long)p * (MMQ * NQ);
    const float* s1 = S1 + (long)p * (MMQ * NQ);

    float Km[32];
#pragma unroll
    for (int i = 0; i < 16; i++) {
        Km[i]      = __expf((s0[i*64+lane]    + s1[i*64+lane]    - 1.0f) * INV_EPS);
        Km[i + 16] = __expf((s0[i*64+lane+32] + s1[i*64+lane+32] - 1.0f) * INV_EPS);
    }

    const float MU = 1.0f / 16.0f + 1e-8f;
    const float NU = 1.0f / 64.0f + 1e-8f;
    float b0 = 1.0f, b1 = 1.0f;
    float a[16];

#pragma unroll 1
    for (int iter = 0; iter < 100; iter++) {
        float v[16];
#pragma unroll
        for (int i = 0; i < 16; i++) v[i] = Km[i] * b0 + Km[i + 16] * b1;
#pragma unroll
        for (int i = 0; i < 8; i++) {
            float t0 = v[i], t1 = v[i + 8];
            float r0 = __shfl_xor_sync(0xffffffffu, t0, 16);
            float r1 = __shfl_xor_sync(0xffffffffu, t1, 16);
            v[i] = (lane & 16) ? (t1 + r1) : (t0 + r0);
        }
#pragma unroll
        for (int i = 0; i < 4; i++) {
            float t0 = v[i], t1 = v[i + 4];
            float r0 = __shfl_xor_sync(0xffffffffu, t0, 8);
            float r1 = __shfl_xor_sync(0xffffffffu, t1, 8);
            v[i] = (lane & 8) ? (t1 + r1) : (t0 + r0);
        }
#pragma unroll
        for (int i = 0; i < 2; i++) {
            float t0 = v[i], t1 = v[i + 2];
            float r0 = __shfl_xor_sync(0xffffffffu, t0, 4);
            float r1 = __shfl_xor_sync(0xffffffffu, t1, 4);
            v[i] = (lane & 4) ? (t1 + r1) : (t0 + r0);
        }
        {
            float t0 = v[0], t1 = v[1];
            float r0 = __shfl_xor_sync(0xffffffffu, t0, 2);
            float r1 = __shfl_xor_sync(0xffffffffu, t1, 2);
            v[0] = (lane & 2) ? (t1 + r1) : (t0 + r0);
        }
        v[0] += __shfl_xor_sync(0xffffffffu, v[0], 1);

        float av = __fdividef(MU, v[0]);
#pragma unroll
        for (int i = 0; i < 16; i++) a[i] = __shfl_sync(0xffffffffu, av, 2 * i);

        float c0a = 0.f, c0b = 0.f, c1a = 0.f, c1b = 0.f;
#pragma unroll
        for (int i = 0; i < 16; i += 2) {
            c0a += Km[i] * a[i];       c0b += Km[i + 1] * a[i + 1];
            c1a += Km[i + 16] * a[i];  c1b += Km[i + 17] * a[i + 1];
        }
        b0 = __fdividef(NU, c0a + c0b);
        b1 = __fdividef(NU, c1a + c1b);
    }

    float* Trow = T + (long)p * (MMQ * NQ);
    float* Srow = score + (long)p * (MMQ * NQ);
#pragma unroll
    for (int i = 0; i < 16; i++) {
        float T0 = a[i] * Km[i] * b0;
        float T1 = a[i] * Km[i + 16] * b1;
        float sv0 = s0[i*64+lane]    + s1[i*64+lane];
        float sv1 = s0[i*64+lane+32] + s1[i*64+lane+32];
        Trow[i * 64 + lane]      = T0;
        Trow[i * 64 + lane + 32] = T1;
        Srow[i * 64 + lane]      = 1024.0f * sv0 * T0;
        Srow[i * 64 + lane + 32] = 1024.0f * sv1 * T1;
    }
}

// ---------------------------------------------------------------------------
extern "C" void kernel_launch(void* const* d_in, const int* in_sizes, int n_in,
                              void* d_out, int out_size)
{
    const float* xq = (const float*)d_in[0];
    const float* xk = (const float*)d_in[1];
    const float* xv = (const float*)d_in[2];
    const float* Wq = (const float*)d_in[3];
    const float* Wk = (const float*)d_in[4];
    const float* Wv = (const float*)d_in[5];
    const float* Wp = (const float*)d_in[6];
    const float* bp = (const float*)d_in[7];
    float* out_x     = (float*)d_out;
    float* out_score = out_x + X_ELEMS;

    __nv_bfloat16 *xq3,*xk3,*xv3,*wq3,*wk3,*wv3,*wp3,*qr3,*kn3,*Tt3,*vT3,*v3;
    float *qlin,*klin,*vp,*S0,*S1,*T;
    cudaGetSymbolAddress((void**)&xq3, g_xq3);
    cudaGetSymbolAddress((void**)&xk3, g_xk3);
    cudaGetSymbolAddress((void**)&xv3, g_xv3);
    cudaGetSymbolAddress((void**)&wq3, g_wq3);
    cudaGetSymbolAddress((void**)&wk3, g_wk3);
    cudaGetSymbolAddress((void**)&wv3, g_wv3);
    cudaGetSymbolAddress((void**)&wp3, g_wp3);
    cudaGetSymbolAddress((void**)&qr3, g_qr3);
    cudaGetSymbolAddress((void**)&kn3, g_kn3);
    cudaGetSymbolAddress((void**)&Tt3, g_Tt3);
    cudaGetSymbolAddress((void**)&vT3, g_vT3);
    cudaGetSymbolAddress((void**)&v3,  g_v3);
    cudaGetSymbolAddress((void**)&qlin, g_qlin);
    cudaGetSymbolAddress((void**)&klin, g_klin);
    cudaGetSymbolAddress((void**)&vp,   g_v);
    cudaGetSymbolAddress((void**)&S0,   g_S0);
    cudaGetSymbolAddress((void**)&S1,   g_S1);
    cudaGetSymbolAddress((void**)&T,    g_T);

    cudaFuncSetAttribute(hgemm<0>,     cudaFuncAttributeMaxDynamicSharedMemorySize, GSMEM);
    cudaFuncSetAttribute(hgemm<2>,     cudaFuncAttributeMaxDynamicSharedMemorySize, GSMEM);
    cudaFuncSetAttribute(hgemm<3>,     cudaFuncAttributeMaxDynamicSharedMemorySize, GSMEM);
    cudaFuncSetAttribute(hgemm_projqk, cudaFuncAttributeMaxDynamicSharedMemorySize, GSMEM);
    cudaFuncSetAttribute(hgemm_sim,    cudaFuncAttributeMaxDynamicSharedMemorySize, GSMEM);

    // Side stream + events for fork/join (host objects; graph replays skip host code)
    cudaStream_t sA;
    cudaStreamCreateWithFlags(&sA, cudaStreamNonBlocking);
    cudaEvent_t eRoot, eW, eActs, eV;
    cudaEventCreateWithFlags(&eRoot, cudaEventDisableTiming);
    cudaEventCreateWithFlags(&eW,    cudaEventDisableTiming);
    cudaEventCreateWithFlags(&eActs, cudaEventDisableTiming);
    cudaEventCreateWithFlags(&eV,    cudaEventDisableTiming);

    // --- fork: weights conv (main) || acts conv (sA) ---
    cudaEventRecord(eRoot, 0);
    conv3_weights<<<4 * CC, 128>>>(Wq, wq3, Wk, wk3, Wv, wv3, Wp, wp3);
    cudaEventRecord(eW, 0);
    cudaStreamWaitEvent(sA, eRoot, 0);
    conv3_acts<<<12288, 128, 0, sA>>>(xq, xq3, xk, xk3, xv, xv3);
    cudaEventRecord(eActs, sA);

    // --- sA: v projection -> vp -> transpose (concurrent with projQK) ---
    cudaStreamWaitEvent(sA, eW, 0);
    hgemm<2><<<dim3(4, 16), 256, GSMEM, sA>>>(
        xv3, wv3, v3, nullptr, K3, 0, 0, 0, 0);
    hgemm<0><<<dim3(4, 16), 256, GSMEM, sA>>>(
        v3, wp3, vp, nullptr, K3, CC, 0, 0, 0);
    trconv_kernel<1><<<dim3(16, 8, 8), dim3(32, 8), 0, sA>>>(vp, vT3, 512);
    cudaEventRecord(eV, sA);

    // --- main: q+k projections (320 CTAs; sA's 128+64 CTAs pack the 2nd wave) ---
    cudaStreamWaitEvent(0, eActs, 0);
    hgemm_projqk<<<dim3(4, 80), 256, GSMEM>>>(xq3, wq3, qlin, xk3, wk3, klin);

    // --- l2 normalize (fused q+k), split-bf16 emit ---
    norm_fused<<<NROWS_Q + NROWS_K, 128>>>(qlin, qr3, klin, kn3);

    // --- sim split-K=2, single launch, 256 CTAs (full chip) ---
    hgemm_sim<<<dim3(8, 2, 16), 256, GSMEM>>>(kn3, qr3, S0, S1);

    // --- Sinkhorn (reads S0+S1) -> T + score_map ---
    sinkhorn_kernel<<<BKP / 8, 256>>>(S0, S1, T, out_score);

    // --- T transpose ---
    trconv_kernel<0><<<dim3(32, 8, 8), dim3(32, 8)>>>(T, Tt3, 1024);

    // --- join vp path; x = T^T·vp + bp with direct scatter to (n,m,b,c) ---
    cudaStreamWaitEvent(0, eV, 0);
    hgemm<3><<<dim3(4, 8, 8), 256, GSMEM>>>(
        Tt3, vT3, out_x, bp, 768, CC,
        (long)1024 * 768, (long)512 * 768, 0);
}

// round 13
// speedup vs baseline: 1.2834x; 1.0443x over previous
#include <cuda_runtime.h>
#include <cuda_bf16.h>
#include <cstdint>
#include <math.h>

// ---------------------------------------------------------------------------
// Problem constants
// ---------------------------------------------------------------------------
#define NQ   64
#define MMQ  16
#define BB   8
#define KK   256
#define CC   512
#define K2   1024           // folded [hi|lo] physical width for C=512 trios
#define K3   1536           // logical K for split-bf16 GEMMs
#define NROWS_Q 8192
#define NROWS_K 2048
#define BKP     2048
#define INV_EPS 20.0f
#define X_ELEMS (NROWS_Q*CC)

// ---------------------------------------------------------------------------
// Scratch (device globals; no allocation allowed). All trio buffers are
// FOLDED: physical [hi|lo]; GEMM loader remaps logical chunk -> physical.
// ---------------------------------------------------------------------------
__device__ __nv_bfloat16 g_xq3[NROWS_Q*K2];
__device__ __nv_bfloat16 g_xk3[NROWS_K*K2];
__device__ __nv_bfloat16 g_xv3[NROWS_K*K2];
__device__ __nv_bfloat16 g_wq3[CC*K2];
__device__ __nv_bfloat16 g_wk3[CC*K2];
__device__ __nv_bfloat16 g_wv3[CC*K2];
__device__ __nv_bfloat16 g_wp3[CC*K2];
__device__ float g_qlin[NROWS_Q*CC];
__device__ float g_klin[NROWS_K*CC];
__device__ float g_v   [NROWS_K*CC];          // vp = v @ Wp^T (fp32)
__device__ __nv_bfloat16 g_qr3[NROWS_Q*K2];
__device__ __nv_bfloat16 g_kn3[NROWS_K*K2];
__device__ float g_S0[BKP*MMQ*NQ];            // sim split-K partial 0
__device__ float g_S1[BKP*MMQ*NQ];            // sim split-K partial 1
__device__ __nv_bfloat16 g_Tt3[BB*1024*512];  // folded [hi|lo], width 512
__device__ __nv_bfloat16 g_vT3[BB*512*512];   // folded [hi|lo], width 512
__device__ __nv_bfloat16 g_v3[NROWS_K*K2];    // folded split-bf16 v

// ---------------------------------------------------------------------------
// PTX helpers
// ---------------------------------------------------------------------------
__device__ __forceinline__ uint32_t s2u(const void* p){
    uint32_t a;
    asm("{ .reg .u64 t; cvta.to.shared.u64 t, %1; cvt.u32.u64 %0, t; }"
        : "=r"(a) : "l"(p));
    return a;
}

#define CP_ASYNC16(dst, src) \
    asm volatile("cp.async.cg.shared.global [%0], [%1], 16;" :: "r"(dst), "l"(src) : "memory")
#define CP_COMMIT() asm volatile("cp.async.commit_group;" ::: "memory")
#define CP_WAIT1()  asm volatile("cp.async.wait_group 1;" ::: "memory")
#define CP_WAIT0()  asm volatile("cp.async.wait_group 0;" ::: "memory")

#define LDMATRIX_X4(r0, r1, r2, r3, addr) \
    asm volatile("ldmatrix.sync.aligned.m8n8.x4.shared.b16 {%0,%1,%2,%3}, [%4];" \
                 : "=r"(r0), "=r"(r1), "=r"(r2), "=r"(r3) : "r"(addr))

#define MMA16816(d, a, b0, b1) \
    asm volatile("mma.sync.aligned.m16n8k16.row.col.f32.bf16.bf16.f32 " \
                 "{%0,%1,%2,%3}, {%4,%5,%6,%7}, {%8,%9}, {%0,%1,%2,%3};" \
                 : "+f"((d)[0]), "+f"((d)[1]), "+f"((d)[2]), "+f"((d)[3]) \
                 : "r"((a)[0]), "r"((a)[1]), "r"((a)[2]), "r"((a)[3]), \
                   "r"(b0), "r"(b1))

__device__ __forceinline__ unsigned short bfr(__nv_bfloat16 h){
    return *reinterpret_cast<unsigned short*>(&h);
}
__device__ __forceinline__ void split_bf16(float x, __nv_bfloat16& h, __nv_bfloat16& l){
    h = __float2bfloat16(x);
    l = __float2bfloat16(x - __bfloat162float(h));
}
__device__ __forceinline__ uint32_t pack2(__nv_bfloat16 a, __nv_bfloat16 b){
    return (uint32_t)bfr(a) | ((uint32_t)bfr(b) << 16);
}

// ---------------------------------------------------------------------------
// HMMA GEMM core (R6-proven mainloop): C = A·Bᵀ over logical K = Kp,
// operands folded: A logical [hi|lo|hi] -> phys chunk ca = cg>=2S ? cg-2S : cg
//                  B logical [hi|hi|lo] -> phys chunk cb = cg>=S  ? cg-S  : cg
// c0 = global chunk offset (split-K). lda/ldb = physical row widths.
// CTA tile 128x128, BK=64, 3-stage cp.async ring, 8 warps, 2 CTAs/SM.
// EPI=0 fp32 store; EPI=2 folded split-bf16 emit; EPI=3 out scatter+bias.
// ---------------------------------------------------------------------------
#define STG   32768
#define GSMEM (3*STG)

template<int EPI>
__device__ __forceinline__
void gemm_core(const __nv_bfloat16* __restrict__ A, const __nv_bfloat16* __restrict__ B,
               void* __restrict__ Cv, const float* __restrict__ bias,
               int Kp, int c0, int S, int lda, int ldb, int ldc,
               int mb, int nb, int bz, long cStride, char* smem)
{
    const int tid  = threadIdx.x;
    const int w    = tid >> 5;
    const int lane = tid & 31;
    const int wm   = (w & 3) * 32;
    const int wn   = (w >> 2) * 64;

    const uint32_t sbase = s2u(smem);
    const int NC = Kp >> 6;

    const int lrow = tid >> 1;
    const int lcg0 = (tid & 1) * 4;

    auto load_chunk = [&](int c, int s){
        const uint32_t st = sbase + s * STG;
        const int cg = c0 + c;
        const int ca = (cg >= 2 * S) ? cg - 2 * S : cg;   // A-fold [hi|lo|hi]
        const int cb = (cg >= S)     ? cg - S     : cg;   // B-fold [hi|hi|lo]
        const __nv_bfloat16* Ag = A + (long)(mb + lrow) * lda + ca * 64 + lcg0 * 8;
        const __nv_bfloat16* Bg = B + (long)(nb + lrow) * ldb + cb * 64 + lcg0 * 8;
        const uint32_t rbase = lrow * 128;
        const uint32_t sw    = (lrow & 7) << 4;
#pragma unroll
        for (int j = 0; j < 4; j++) {
            uint32_t off = rbase + (((lcg0 + j) << 4) ^ sw);
            CP_ASYNC16(st + off, Ag + j * 8);
            CP_ASYNC16(st + 16384 + off, Bg + j * 8);
        }
        CP_COMMIT();
    };

    float acc[2][8][4];
#pragma unroll
    for (int i = 0; i < 2; i++)
#pragma unroll
        for (int j = 0; j < 8; j++)
#pragma unroll
            for (int q = 0; q < 4; q++) acc[i][j][q] = 0.f;

    load_chunk(0, 0);
    load_chunk(1, 1);

    const int a_r  = lane & 15;
    const int a_kb = (lane & 16);
    const int b_r  = ((lane >> 4) << 3) + (lane & 7);
    const int b_kb = ((lane >> 3) & 1) << 4;

    int stage = 0;
    for (int c = 0; c < NC; c++) {
        if (c + 1 < NC) CP_WAIT1(); else CP_WAIT0();
        __syncthreads();

        if (c + 2 < NC) {
            int ns = stage + 2; if (ns >= 3) ns -= 3;
            load_chunk(c + 2, ns);
        }

        const uint32_t sa = sbase + stage * STG;
        const uint32_t sb = sa + 16384;

        uint32_t br2[2][4][4];
#pragma unroll
        for (int nj = 0; nj < 4; nj++) {
            int row = wn + nj * 16 + b_r;
            uint32_t kb = (uint32_t)(b_kb) ^ ((row & 7) << 4);
            LDMATRIX_X4(br2[0][nj][0], br2[0][nj][1], br2[0][nj][2], br2[0][nj][3],
                        sb + row * 128 + kb);
        }
#pragma unroll
        for (int ks = 0; ks < 4; ks++) {
            const int cur = ks & 1;
            if (ks < 3) {
#pragma unroll
                for (int nj = 0; nj < 4; nj++) {
                    int row = wn + nj * 16 + b_r;
                    uint32_t kb = (uint32_t)((ks + 1) * 32 + b_kb) ^ ((row & 7) << 4);
                    LDMATRIX_X4(br2[cur ^ 1][nj][0], br2[cur ^ 1][nj][1],
                                br2[cur ^ 1][nj][2], br2[cur ^ 1][nj][3],
                                sb + row * 128 + kb);
                }
            }
            uint32_t ar[2][4];
#pragma unroll
            for (int mi = 0; mi < 2; mi++) {
                int row = wm + mi * 16 + a_r;
                uint32_t kb = (uint32_t)(ks * 32 + a_kb) ^ ((row & 7) << 4);
                LDMATRIX_X4(ar[mi][0], ar[mi][1], ar[mi][2], ar[mi][3],
                            sa + row * 128 + kb);
            }
#pragma unroll
            for (int mi = 0; mi < 2; mi++)
#pragma unroll
                for (int nj = 0; nj < 4; nj++) {
                    MMA16816(acc[mi][nj * 2],     ar[mi], br2[cur][nj][0], br2[cur][nj][1]);
                    MMA16816(acc[mi][nj * 2 + 1], ar[mi], br2[cur][nj][2], br2[cur][nj][3]);
                }
        }
        stage++; if (stage == 3) stage = 0;
    }

    // ---- epilogue ----
    const int er = lane >> 2;
    const int ec = (lane & 3) * 2;
#pragma unroll
    for (int mi = 0; mi < 2; mi++) {
#pragma unroll
        for (int half = 0; half < 2; half++) {
            const int R = mb + wm + mi * 16 + er + half * 8;
            if (EPI == 0) {
                float* Crow = (float*)Cv + (long)bz * cStride + (long)R * ldc;
#pragma unroll
                for (int nj = 0; nj < 8; nj++) {
                    const int col = nb + wn + nj * 8 + ec;
                    *(float2*)&Crow[col] =
                        make_float2(acc[mi][nj][half * 2], acc[mi][nj][half * 2 + 1]);
                }
            } else if (EPI == 3) {
                const int mq = R >> 6, nq = R & 63;
                float* Crow = (float*)Cv + (long)(((nq << 4) + mq) * 8 + bz) * CC;
#pragma unroll
                for (int nj = 0; nj < 8; nj++) {
                    const int col = nb + wn + nj * 8 + ec;
                    *(float2*)&Crow[col] = make_float2(
                        acc[mi][nj][half * 2] + bias[col],
                        acc[mi][nj][half * 2 + 1] + bias[col + 1]);
                }
            } else {
                // EPI==2: folded split-bf16 emit [hi|lo], row width K2
                __nv_bfloat16* Yr = (__nv_bfloat16*)Cv + (long)bz * cStride + (long)R * K2;
#pragma unroll
                for (int nj = 0; nj < 8; nj++) {
                    const int col = nb + wn + nj * 8 + ec;
                    __nv_bfloat16 h0, l0, h1, l1;
                    split_bf16(acc[mi][nj][half * 2],     h0, l0);
                    split_bf16(acc[mi][nj][half * 2 + 1], h1, l1);
                    *(uint32_t*)&Yr[col]       = pack2(h0, h1);
                    *(uint32_t*)&Yr[col + CC]  = pack2(l0, l1);
                }
            }
        }
    }
}

// generic GEMM (vp, attn·v, projV)
template<int EPI>
__global__ __launch_bounds__(256, 2)
void hgemm(const __nv_bfloat16* __restrict__ A, const __nv_bfloat16* __restrict__ B,
           void* __restrict__ C, const float* __restrict__ bias,
           int Kp, int S, int lda, int ldb, int ldc,
           long aStride, long bStride, long cStride)
{
    extern __shared__ char smem[];
    const int bz = blockIdx.z;
    gemm_core<EPI>(A + bz * aStride, B + bz * bStride, C, bias,
                   Kp, 0, S, lda, ldb, ldc,
                   blockIdx.y * 128, blockIdx.x * 128, bz, cStride, smem);
}

// q+k projections fused: grid.y in [0,80): 0-63 q, 64-79 k
__global__ __launch_bounds__(256, 2)
void hgemm_projqk(const __nv_bfloat16* __restrict__ Aq, const __nv_bfloat16* __restrict__ Bq,
                  float* __restrict__ Cq,
                  const __nv_bfloat16* __restrict__ Ak, const __nv_bfloat16* __restrict__ Bk,
                  float* __restrict__ Ck)
{
    extern __shared__ char smem[];
    const int by = blockIdx.y;
    if (by < 64)
        gemm_core<0>(Aq, Bq, Cq, nullptr, K3, 0, 8, K2, K2, CC,
                     by * 128, blockIdx.x * 128, 0, 0, smem);
    else
        gemm_core<0>(Ak, Bk, Ck, nullptr, K3, 0, 8, K2, K2, CC,
                     (by - 64) * 128, blockIdx.x * 128, 0, 0, smem);
}

// sim split-K=2, single launch: z = b*2 + kh -> partial kh of batch b.
// Split realized via chunk offset c0 = kh*12 (fold handled in loader).
__global__ __launch_bounds__(256, 2)
void hgemm_sim(const __nv_bfloat16* __restrict__ A, const __nv_bfloat16* __restrict__ B,
               float* __restrict__ S0, float* __restrict__ S1)
{
    extern __shared__ char smem[];
    const int z = blockIdx.z;
    const int b = z >> 1;
    const int kh = z & 1;
    gemm_core<0>(A + (long)b * 256 * K2,
                 B + (long)b * 1024 * K2,
                 kh ? S1 : S0, nullptr,
                 768, kh * 12, 8, K2, K2, 1024,
                 blockIdx.y * 128, blockIdx.x * 128, b, (long)256 * 1024, smem);
}

// ---------------------------------------------------------------------------
// conv3 helpers: fp32 [512] row -> folded bf16 [hi(512)|lo(512)]
// ---------------------------------------------------------------------------
__device__ __forceinline__ void conv3_row(const float* __restrict__ in,
                                          __nv_bfloat16* __restrict__ out, int t)
{
    float4 v = ((const float4*)in)[t];
    __nv_bfloat16 h0,h1,h2,h3,l0,l1,l2,l3;
    split_bf16(v.x,h0,l0); split_bf16(v.y,h1,l1);
    split_bf16(v.z,h2,l2); split_bf16(v.w,h3,l3);
    ((ushort4*)(out))[t]      = make_ushort4(bfr(h0),bfr(h1),bfr(h2),bfr(h3));
    ((ushort4*)(out + CC))[t] = make_ushort4(bfr(l0),bfr(l1),bfr(l2),bfr(l3));
}

__global__ void conv3_weights(const float* __restrict__ w0, __nv_bfloat16* __restrict__ o0,
                              const float* __restrict__ w1, __nv_bfloat16* __restrict__ o1,
                              const float* __restrict__ w2, __nv_bfloat16* __restrict__ o2,
                              const float* __restrict__ w3, __nv_bfloat16* __restrict__ o3)
{
    const int r = blockIdx.x;
    const int sel = r >> 9, rw = r & 511;
    const float* in; __nv_bfloat16* out;
    if (sel == 0)      { in = w0; out = o0; }
    else if (sel == 1) { in = w1; out = o1; }
    else if (sel == 2) { in = w2; out = o2; }
    else               { in = w3; out = o3; }
    conv3_row(in + (long)rw * CC, out + (long)rw * K2, threadIdx.x);
}

__global__ void conv3_acts(const float* __restrict__ xq, __nv_bfloat16* __restrict__ oq,
                           const float* __restrict__ xk, __nv_bfloat16* __restrict__ ok,
                           const float* __restrict__ xv, __nv_bfloat16* __restrict__ ov)
{
    const int r = blockIdx.x;       // 0..12287
    const float* in; __nv_bfloat16* out; int rr;
    if (r < 8192)       { in = xq; out = oq; rr = r; }
    else if (r < 10240) { in = xk; out = ok; rr = r - 8192; }
    else                { in = xv; out = ov; rr = r - 10240; }
    conv3_row(in + (long)rr * CC, out + (long)rr * K2, threadIdx.x);
}

// ---------------------------------------------------------------------------
// Fused norm: rows <8192 = q (reorder), else k. Folded [hi|lo] emit.
// ---------------------------------------------------------------------------
__global__ void norm_fused(const float* __restrict__ qin, __nv_bfloat16* __restrict__ qout,
                           const float* __restrict__ kin, __nv_bfloat16* __restrict__ kout)
{
    const int r = blockIdx.x;
    const int t = threadIdx.x;
    const float* in;
    __nv_bfloat16* out;
    long orow;
    if (r < NROWS_Q) {
        in = qin + (long)r * CC;
        int n = r >> 7, m = (r >> 3) & 15, b = r & 7;
        orow = (long)(b * 1024 + m * 64 + n);
        out = qout;
    } else {
        int rk = r - NROWS_Q;
        in = kin + (long)rk * CC;
        orow = rk;
        out = kout;
    }
    float4 v = ((const float4*)in)[t];
    float ss = v.x*v.x + v.y*v.y + v.z*v.z + v.w*v.w;
#pragma unroll
    for (int o = 16; o; o >>= 1) ss += __shfl_xor_sync(0xffffffffu, ss, o);
    __shared__ float sw[4];
    if ((t & 31) == 0) sw[t >> 5] = ss;
    __syncthreads();
    float tot = sw[0] + sw[1] + sw[2] + sw[3];
    float scale = 1.0f / fmaxf(sqrtf(tot), 1e-12f);

    __nv_bfloat16 h0,h1,h2,h3,l0,l1,l2,l3;
    split_bf16(v.x*scale,h0,l0); split_bf16(v.y*scale,h1,l1);
    split_bf16(v.z*scale,h2,l2); split_bf16(v.w*scale,h3,l3);
    __nv_bfloat16* base = out + orow * K2;
    ((ushort4*)(base))[t]      = make_ushort4(bfr(h0),bfr(h1),bfr(h2),bfr(h3));
    ((ushort4*)(base + CC))[t] = make_ushort4(bfr(l0),bfr(l1),bfr(l2),bfr(l3));
}

// ---------------------------------------------------------------------------
// Transpose + folded split-convert: vp fp32 [b][256][512] -> vT3 [b][512][512]
// ---------------------------------------------------------------------------
__global__ void trconv_v(const float* __restrict__ in, __nv_bfloat16* __restrict__ out)
{
    __shared__ float s[32][33];
    const int b = blockIdx.z;
    const float* ib = in + (long)b * 256 * 512;
    __nv_bfloat16* ob = out + (long)b * 512 * 512;
    const int k0 = blockIdx.y * 32, w0 = blockIdx.x * 32;
    const int tx = threadIdx.x, ty = threadIdx.y;
#pragma unroll
    for (int i = 0; i < 4; i++)
        s[ty + 8*i][tx] = ib[(long)(k0 + ty + 8*i) * 512 + w0 + tx];
    __syncthreads();
#pragma unroll
    for (int i = 0; i < 4; i++) {
        const int wrow = w0 + ty + 8*i;
        float x = s[tx][ty + 8*i];
        __nv_bfloat16 h, l; split_bf16(x, h, l);
        __nv_bfloat16* p = ob + (long)wrow * 512 + k0 + tx;
        p[0]   = h;
        p[256] = l;
    }
}

// ---------------------------------------------------------------------------
// Sinkhorn: one warp per (b,k) problem. Reads S0+S1. Writes score AND the
// folded transposed Tt3 directly via a chunked smem transpose (8KB).
// CTA = 8 warps = problems pb..pb+7 (same b, k0..k0+7).
// ---------------------------------------------------------------------------
__global__ __launch_bounds__(256)
void sinkhorn_kernel(const float* __restrict__ S0, const float* __restrict__ S1,
                     __nv_bfloat16* __restrict__ Tt3, float* __restrict__ score)
{
    __shared__ __align__(16) __nv_bfloat16 th[256][8];
    __shared__ __align__(16) __nv_bfloat16 tl[256][8];

    const int w    = threadIdx.x >> 5;
    const int lane = threadIdx.x & 31;
    const int pb   = blockIdx.x * 8;
    const int p    = pb + w;
    const int b    = pb >> 8;
    const int k0   = pb & 255;
    const float* s0 = S0 + (long)p * (MMQ * NQ);
    const float* s1 = S1 + (long)p * (MMQ * NQ);

    float Km[32];
#pragma unroll
    for (int i = 0; i < 16; i++) {
        Km[i]      = __expf((s0[i*64+lane]    + s1[i*64+lane]    - 1.0f) * INV_EPS);
        Km[i + 16] = __expf((s0[i*64+lane+32] + s1[i*64+lane+32] - 1.0f) * INV_EPS);
    }

    const float MU = 1.0f / 16.0f + 1e-8f;
    const float NU = 1.0f / 64.0f + 1e-8f;
    float b0 = 1.0f, b1 = 1.0f;
    float a[16];

#pragma unroll 1
    for (int iter = 0; iter < 100; iter++) {
        float v[16];
#pragma unroll
        for (int i = 0; i < 16; i++) v[i] = Km[i] * b0 + Km[i + 16] * b1;
#pragma unroll
        for (int i = 0; i < 8; i++) {
            float t0 = v[i], t1 = v[i + 8];
            float r0 = __shfl_xor_sync(0xffffffffu, t0, 16);
            float r1 = __shfl_xor_sync(0xffffffffu, t1, 16);
            v[i] = (lane & 16) ? (t1 + r1) : (t0 + r0);
        }
#pragma unroll
        for (int i = 0; i < 4; i++) {
            float t0 = v[i], t1 = v[i + 4];
            float r0 = __shfl_xor_sync(0xffffffffu, t0, 8);
            float r1 = __shfl_xor_sync(0xffffffffu, t1, 8);
            v[i] = (lane & 8) ? (t1 + r1) : (t0 + r0);
        }
#pragma unroll
        for (int i = 0; i < 2; i++) {
            float t0 = v[i], t1 = v[i + 2];
            float r0 = __shfl_xor_sync(0xffffffffu, t0, 4);
            float r1 = __shfl_xor_sync(0xffffffffu, t1, 4);
            v[i] = (lane & 4) ? (t1 + r1) : (t0 + r0);
        }
        {
            float t0 = v[0], t1 = v[1];
            float r0 = __shfl_xor_sync(0xffffffffu, t0, 2);
            float r1 = __shfl_xor_sync(0xffffffffu, t1, 2);
            v[0] = (lane & 2) ? (t1 + r1) : (t0 + r0);
        }
        v[0] += __shfl_xor_sync(0xffffffffu, v[0], 1);

        float av = __fdividef(MU, v[0]);
#pragma unroll
        for (int i = 0; i < 16; i++) a[i] = __shfl_sync(0xffffffffu, av, 2 * i);

        float c0a = 0.f, c0b = 0.f, c1a = 0.f, c1b = 0.f;
#pragma unroll
        for (int i = 0; i < 16; i += 2) {
            c0a += Km[i] * a[i];       c0b += Km[i + 1] * a[i + 1];
            c1a += Km[i + 16] * a[i];  c1b += Km[i + 17] * a[i + 1];
        }
        b0 = __fdividef(NU, c0a + c0b);
        b1 = __fdividef(NU, c1a + c1b);
    }

    // ---- epilogue: score + chunked smem transpose into folded Tt3 ----
    float* Srow = score + (long)p * (MMQ * NQ);
#pragma unroll 1
    for (int q = 0; q < 4; q++) {
#pragma unroll
        for (int ii = 0; ii < 4; ii++) {
            const int i = q * 4 + ii;
            float T0 = a[i] * Km[i] * b0;
            float T1 = a[i] * Km[i + 16] * b1;
            float sv0 = s0[i*64+lane]    + s1[i*64+lane];
            float sv1 = s0[i*64+lane+32] + s1[i*64+lane+32];
            Srow[i * 64 + lane]      = 1024.0f * sv0 * T0;
            Srow[i * 64 + lane + 32] = 1024.0f * sv1 * T1;
            __nv_bfloat16 h, l;
            split_bf16(T0, h, l);
            th[i * 64 + lane - q * 256][w] = h;
            tl[i * 64 + lane - q * 256][w] = l;
            split_bf16(T1, h, l);
            th[i * 64 + lane + 32 - q * 256][w] = h;
            tl[i * 64 + lane + 32 - q * 256][w] = l;
        }
        __syncthreads();
        {
            const int r = threadIdx.x;      // 0..255
            __nv_bfloat16* d = Tt3 + ((long)b * 1024 + q * 256 + r) * 512 + k0;
            *(uint4*)(d)       = *(const uint4*)&th[r][0];
            *(uint4*)(d + 256) = *(const uint4*)&tl[r][0];
        }
        __syncthreads();
    }
}

// ---------------------------------------------------------------------------
extern "C" void kernel_launch(void* const* d_in, const int* in_sizes, int n_in,
                              void* d_out, int out_size)
{
    const float* xq = (const float*)d_in[0];
    const float* xk = (const float*)d_in[1];
    const float* xv = (const float*)d_in[2];
    const float* Wq = (const float*)d_in[3];
    const float* Wk = (const float*)d_in[4];
    const float* Wv = (const float*)d_in[5];
    const float* Wp = (const float*)d_in[6];
    const float* bp = (const float*)d_in[7];
    float* out_x     = (float*)d_out;
    float* out_score = out_x + X_ELEMS;

    __nv_bfloat16 *xq3,*xk3,*xv3,*wq3,*wk3,*wv3,*wp3,*qr3,*kn3,*Tt3,*vT3,*v3;
    float *qlin,*klin,*vp,*S0,*S1;
    cudaGetSymbolAddress((void**)&xq3, g_xq3);
    cudaGetSymbolAddress((void**)&xk3, g_xk3);
    cudaGetSymbolAddress((void**)&xv3, g_xv3);
    cudaGetSymbolAddress((void**)&wq3, g_wq3);
    cudaGetSymbolAddress((void**)&wk3, g_wk3);
    cudaGetSymbolAddress((void**)&wv3, g_wv3);
    cudaGetSymbolAddress((void**)&wp3, g_wp3);
    cudaGetSymbolAddress((void**)&qr3, g_qr3);
    cudaGetSymbolAddress((void**)&kn3, g_kn3);
    cudaGetSymbolAddress((void**)&Tt3, g_Tt3);
    cudaGetSymbolAddress((void**)&vT3, g_vT3);
    cudaGetSymbolAddress((void**)&v3,  g_v3);
    cudaGetSymbolAddress((void**)&qlin, g_qlin);
    cudaGetSymbolAddress((void**)&klin, g_klin);
    cudaGetSymbolAddress((void**)&vp,   g_v);
    cudaGetSymbolAddress((void**)&S0,   g_S0);
    cudaGetSymbolAddress((void**)&S1,   g_S1);

    cudaFuncSetAttribute(hgemm<0>,     cudaFuncAttributeMaxDynamicSharedMemorySize, GSMEM);
    cudaFuncSetAttribute(hgemm<2>,     cudaFuncAttributeMaxDynamicSharedMemorySize, GSMEM);
    cudaFuncSetAttribute(hgemm<3>,     cudaFuncAttributeMaxDynamicSharedMemorySize, GSMEM);
    cudaFuncSetAttribute(hgemm_projqk, cudaFuncAttributeMaxDynamicSharedMemorySize, GSMEM);
    cudaFuncSetAttribute(hgemm_sim,    cudaFuncAttributeMaxDynamicSharedMemorySize, GSMEM);

    // Side stream + events for fork/join (host objects; graph replays skip host code)
    cudaStream_t sA;
    cudaStreamCreateWithFlags(&sA, cudaStreamNonBlocking);
    cudaEvent_t eRoot, eW, eActs, eV;
    cudaEventCreateWithFlags(&eRoot, cudaEventDisableTiming);
    cudaEventCreateWithFlags(&eW,    cudaEventDisableTiming);
    cudaEventCreateWithFlags(&eActs, cudaEventDisableTiming);
    cudaEventCreateWithFlags(&eV,    cudaEventDisableTiming);

    // --- fork: weights conv (main) || acts conv (sA) ---
    cudaEventRecord(eRoot, 0);
    conv3_weights<<<4 * CC, 128>>>(Wq, wq3, Wk, wk3, Wv, wv3, Wp, wp3);
    cudaEventRecord(eW, 0);
    cudaStreamWaitEvent(sA, eRoot, 0);
    conv3_acts<<<12288, 128, 0, sA>>>(xq, xq3, xk, xk3, xv, xv3);
    cudaEventRecord(eActs, sA);

    // --- sA: v projection -> vp -> transpose (concurrent with projQK) ---
    cudaStreamWaitEvent(sA, eW, 0);
    hgemm<2><<<dim3(4, 16), 256, GSMEM, sA>>>(
        xv3, wv3, v3, nullptr, K3, 8, K2, K2, 0, 0, 0, 0);
    hgemm<0><<<dim3(4, 16), 256, GSMEM, sA>>>(
        v3, wp3, vp, nullptr, K3, 8, K2, K2, CC, 0, 0, 0);
    trconv_v<<<dim3(16, 8, 8), dim3(32, 8), 0, sA>>>(vp, vT3);
    cudaEventRecord(eV, sA);

    // --- main: q+k projections (320 CTAs; sA packs the 2nd wave) ---
    cudaStreamWaitEvent(0, eActs, 0);
    hgemm_projqk<<<dim3(4, 80), 256, GSMEM>>>(xq3, wq3, qlin, xk3, wk3, klin);

    // --- l2 normalize (fused q+k), folded split-bf16 emit ---
    norm_fused<<<NROWS_Q + NROWS_K, 128>>>(qlin, qr3, klin, kn3);

    // --- sim split-K=2, single launch, 256 CTAs (full chip) ---
    hgemm_sim<<<dim3(8, 2, 16), 256, GSMEM>>>(kn3, qr3, S0, S1);

    // --- Sinkhorn (reads S0+S1) -> folded Tt3 + score_map ---
    sinkhorn_kernel<<<BKP / 8, 256>>>(S0, S1, Tt3, out_score);

    // --- join vp path; x = T^T·vp + bp with direct scatter to (n,m,b,c) ---
    cudaStreamWaitEvent(0, eV, 0);
    hgemm<3><<<dim3(4, 8, 8), 256, GSMEM>>>(
        Tt3, vT3, out_x, bp, 768, 4, 512, 512, CC,
        (long)1024 * 512, (long)512 * 512, 0);
}

// round 14
// speedup vs baseline: 1.2928x; 1.0073x over previous
#include <cuda_runtime.h>
#include <cuda_bf16.h>
#include <cstdint>
#include <math.h>

// ---------------------------------------------------------------------------
// Problem constants
// ---------------------------------------------------------------------------
#define NQ   64
#define MMQ  16
#define BB   8
#define KK   256
#define CC   512
#define K2   1024           // folded [hi|lo] physical width for C=512 trios
#define K3   1536           // logical K for split-bf16 GEMMs
#define NROWS_Q 8192
#define NROWS_K 2048
#define BKP     2048
#define INV_EPS 20.0f
#define SINK_ITERS 72
#define X_ELEMS (NROWS_Q*CC)

// ---------------------------------------------------------------------------
// Scratch (device globals; no allocation allowed). Folded [hi|lo] storage.
// ---------------------------------------------------------------------------
__device__ __nv_bfloat16 g_xq3[NROWS_Q*K2];
__device__ __nv_bfloat16 g_xk3[NROWS_K*K2];
__device__ __nv_bfloat16 g_xv3[NROWS_K*K2];
__device__ __nv_bfloat16 g_wq3[CC*K2];
__device__ __nv_bfloat16 g_wk3[CC*K2];
__device__ __nv_bfloat16 g_wvT3[CC*K2];       // folded Wv^T (rows = input dim)
__device__ __nv_bfloat16 g_wp3[CC*K2];
__device__ __nv_bfloat16 g_wc3[CC*K2];        // folded Wc = Wp·Wv
__device__ float g_qlin[NROWS_Q*CC];
__device__ float g_klin[NROWS_K*CC];
__device__ float g_v   [NROWS_K*CC];          // Wc fp32 (rows 0-511), then vp
__device__ __nv_bfloat16 g_qr3[NROWS_Q*K2];
__device__ __nv_bfloat16 g_kn3[NROWS_K*K2];
__device__ float g_S0[BKP*MMQ*NQ];            // sim split-K partial 0
__device__ float g_S1[BKP*MMQ*NQ];            // sim split-K partial 1
__device__ __nv_bfloat16 g_Tt3[BB*1024*512];  // folded [hi|lo]
__device__ __nv_bfloat16 g_vT3[BB*512*512];   // folded [hi|lo]

// ---------------------------------------------------------------------------
// PTX helpers
// ---------------------------------------------------------------------------
__device__ __forceinline__ uint32_t s2u(const void* p){
    uint32_t a;
    asm("{ .reg .u64 t; cvta.to.shared.u64 t, %1; cvt.u32.u64 %0, t; }"
        : "=r"(a) : "l"(p));
    return a;
}

#define CP_ASYNC16(dst, src) \
    asm volatile("cp.async.cg.shared.global [%0], [%1], 16;" :: "r"(dst), "l"(src) : "memory")
#define CP_COMMIT() asm volatile("cp.async.commit_group;" ::: "memory")
#define CP_WAIT1()  asm volatile("cp.async.wait_group 1;" ::: "memory")
#define CP_WAIT0()  asm volatile("cp.async.wait_group 0;" ::: "memory")

#define LDMATRIX_X4(r0, r1, r2, r3, addr) \
    asm volatile("ldmatrix.sync.aligned.m8n8.x4.shared.b16 {%0,%1,%2,%3}, [%4];" \
                 : "=r"(r0), "=r"(r1), "=r"(r2), "=r"(r3) : "r"(addr))

#define MMA16816(d, a, b0, b1) \
    asm volatile("mma.sync.aligned.m16n8k16.row.col.f32.bf16.bf16.f32 " \
                 "{%0,%1,%2,%3}, {%4,%5,%6,%7}, {%8,%9}, {%0,%1,%2,%3};" \
                 : "+f"((d)[0]), "+f"((d)[1]), "+f"((d)[2]), "+f"((d)[3]) \
                 : "r"((a)[0]), "r"((a)[1]), "r"((a)[2]), "r"((a)[3]), \
                   "r"(b0), "r"(b1))

__device__ __forceinline__ unsigned short bfr(__nv_bfloat16 h){
    return *reinterpret_cast<unsigned short*>(&h);
}
__device__ __forceinline__ void split_bf16(float x, __nv_bfloat16& h, __nv_bfloat16& l){
    h = __float2bfloat16(x);
    l = __float2bfloat16(x - __bfloat162float(h));
}
__device__ __forceinline__ uint32_t pack2(__nv_bfloat16 a, __nv_bfloat16 b){
    return (uint32_t)bfr(a) | ((uint32_t)bfr(b) << 16);
}

// ---------------------------------------------------------------------------
// HMMA GEMM core (R6-proven mainloop; folded-operand loader):
//  A logical [hi|lo|hi]: phys chunk ca = cg>=2S ? cg-2S : cg
//  B logical [hi|hi|lo]: phys chunk cb = cg>=S  ? cg-S  : cg
// c0 = split-K chunk offset. CTA 128x128, BK=64, 3-stage ring, 2 CTAs/SM.
// EPI=0 fp32 store; EPI=3 out scatter+bias.
// ---------------------------------------------------------------------------
#define STG   32768
#define GSMEM (3*STG)

template<int EPI>
__device__ __forceinline__
void gemm_core(const __nv_bfloat16* __restrict__ A, const __nv_bfloat16* __restrict__ B,
               void* __restrict__ Cv, const float* __restrict__ bias,
               int Kp, int c0, int S, int lda, int ldb, int ldc,
               int mb, int nb, int bz, long cStride, char* smem)
{
    const int tid  = threadIdx.x;
    const int w    = tid >> 5;
    const int lane = tid & 31;
    const int wm   = (w & 3) * 32;
    const int wn   = (w >> 2) * 64;

    const uint32_t sbase = s2u(smem);
    const int NC = Kp >> 6;

    const int lrow = tid >> 1;
    const int lcg0 = (tid & 1) * 4;

    auto load_chunk = [&](int c, int s){
        const uint32_t st = sbase + s * STG;
        const int cg = c0 + c;
        const int ca = (cg >= 2 * S) ? cg - 2 * S : cg;
        const int cb = (cg >= S)     ? cg - S     : cg;
        const __nv_bfloat16* Ag = A + (long)(mb + lrow) * lda + ca * 64 + lcg0 * 8;
        const __nv_bfloat16* Bg = B + (long)(nb + lrow) * ldb + cb * 64 + lcg0 * 8;
        const uint32_t rbase = lrow * 128;
        const uint32_t sw    = (lrow & 7) << 4;
#pragma unroll
        for (int j = 0; j < 4; j++) {
            uint32_t off = rbase + (((lcg0 + j) << 4) ^ sw);
            CP_ASYNC16(st + off, Ag + j * 8);
            CP_ASYNC16(st + 16384 + off, Bg + j * 8);
        }
        CP_COMMIT();
    };

    float acc[2][8][4];
#pragma unroll
    for (int i = 0; i < 2; i++)
#pragma unroll
        for (int j = 0; j < 8; j++)
#pragma unroll
            for (int q = 0; q < 4; q++) acc[i][j][q] = 0.f;

    load_chunk(0, 0);
    load_chunk(1, 1);

    const int a_r  = lane & 15;
    const int a_kb = (lane & 16);
    const int b_r  = ((lane >> 4) << 3) + (lane & 7);
    const int b_kb = ((lane >> 3) & 1) << 4;

    int stage = 0;
    for (int c = 0; c < NC; c++) {
        if (c + 1 < NC) CP_WAIT1(); else CP_WAIT0();
        __syncthreads();

        if (c + 2 < NC) {
            int ns = stage + 2; if (ns >= 3) ns -= 3;
            load_chunk(c + 2, ns);
        }

        const uint32_t sa = sbase + stage * STG;
        const uint32_t sb = sa + 16384;

        uint32_t br2[2][4][4];
#pragma unroll
        for (int nj = 0; nj < 4; nj++) {
            int row = wn + nj * 16 + b_r;
            uint32_t kb = (uint32_t)(b_kb) ^ ((row & 7) << 4);
            LDMATRIX_X4(br2[0][nj][0], br2[0][nj][1], br2[0][nj][2], br2[0][nj][3],
                        sb + row * 128 + kb);
        }
#pragma unroll
        for (int ks = 0; ks < 4; ks++) {
            const int cur = ks & 1;
            if (ks < 3) {
#pragma unroll
                for (int nj = 0; nj < 4; nj++) {
                    int row = wn + nj * 16 + b_r;
                    uint32_t kb = (uint32_t)((ks + 1) * 32 + b_kb) ^ ((row & 7) << 4);
                    LDMATRIX_X4(br2[cur ^ 1][nj][0], br2[cur ^ 1][nj][1],
                                br2[cur ^ 1][nj][2], br2[cur ^ 1][nj][3],
                                sb + row * 128 + kb);
                }
            }
            uint32_t ar[2][4];
#pragma unroll
            for (int mi = 0; mi < 2; mi++) {
                int row = wm + mi * 16 + a_r;
                uint32_t kb = (uint32_t)(ks * 32 + a_kb) ^ ((row & 7) << 4);
                LDMATRIX_X4(ar[mi][0], ar[mi][1], ar[mi][2], ar[mi][3],
                            sa + row * 128 + kb);
            }
#pragma unroll
            for (int mi = 0; mi < 2; mi++)
#pragma unroll
                for (int nj = 0; nj < 4; nj++) {
                    MMA16816(acc[mi][nj * 2],     ar[mi], br2[cur][nj][0], br2[cur][nj][1]);
                    MMA16816(acc[mi][nj * 2 + 1], ar[mi], br2[cur][nj][2], br2[cur][nj][3]);
                }
        }
        stage++; if (stage == 3) stage = 0;
    }

    // ---- epilogue ----
    const int er = lane >> 2;
    const int ec = (lane & 3) * 2;
#pragma unroll
    for (int mi = 0; mi < 2; mi++) {
#pragma unroll
        for (int half = 0; half < 2; half++) {
            const int R = mb + wm + mi * 16 + er + half * 8;
            if (EPI == 0) {
                float* Crow = (float*)Cv + (long)bz * cStride + (long)R * ldc;
#pragma unroll
                for (int nj = 0; nj < 8; nj++) {
                    const int col = nb + wn + nj * 8 + ec;
                    *(float2*)&Crow[col] =
                        make_float2(acc[mi][nj][half * 2], acc[mi][nj][half * 2 + 1]);
                }
            } else {
                const int mq = R >> 6, nq = R & 63;
                float* Crow = (float*)Cv + (long)(((nq << 4) + mq) * 8 + bz) * CC;
#pragma unroll
                for (int nj = 0; nj < 8; nj++) {
                    const int col = nb + wn + nj * 8 + ec;
                    *(float2*)&Crow[col] = make_float2(
                        acc[mi][nj][half * 2] + bias[col],
                        acc[mi][nj][half * 2 + 1] + bias[col + 1]);
                }
            }
        }
    }
}

// generic GEMM
template<int EPI>
__global__ __launch_bounds__(256, 2)
void hgemm(const __nv_bfloat16* __restrict__ A, const __nv_bfloat16* __restrict__ B,
           void* __restrict__ C, const float* __restrict__ bias,
           int Kp, int S, int lda, int ldb, int ldc,
           long aStride, long bStride, long cStride)
{
    extern __shared__ char smem[];
    const int bz = blockIdx.z;
    gemm_core<EPI>(A + bz * aStride, B + bz * bStride, C, bias,
                   Kp, 0, S, lda, ldb, ldc,
                   blockIdx.y * 128, blockIdx.x * 128, bz, cStride, smem);
}

// q+k projections fused: grid.y in [0,80): 0-63 q, 64-79 k
__global__ __launch_bounds__(256, 2)
void hgemm_projqk(const __nv_bfloat16* __restrict__ Aq, const __nv_bfloat16* __restrict__ Bq,
                  float* __restrict__ Cq,
                  const __nv_bfloat16* __restrict__ Ak, const __nv_bfloat16* __restrict__ Bk,
                  float* __restrict__ Ck)
{
    extern __shared__ char smem[];
    const int by = blockIdx.y;
    if (by < 64)
        gemm_core<0>(Aq, Bq, Cq, nullptr, K3, 0, 8, K2, K2, CC,
                     by * 128, blockIdx.x * 128, 0, 0, smem);
    else
        gemm_core<0>(Ak, Bk, Ck, nullptr, K3, 0, 8, K2, K2, CC,
                     (by - 64) * 128, blockIdx.x * 128, 0, 0, smem);
}

// sim split-K=2: z = b*2 + kh; chunk offset c0 = kh*12
__global__ __launch_bounds__(256, 2)
void hgemm_sim(const __nv_bfloat16* __restrict__ A, const __nv_bfloat16* __restrict__ B,
               float* __restrict__ S0, float* __restrict__ S1)
{
    extern __shared__ char smem[];
    const int z = blockIdx.z;
    const int b = z >> 1;
    const int kh = z & 1;
    gemm_core<0>(A + (long)b * 256 * K2,
                 B + (long)b * 1024 * K2,
                 kh ? S1 : S0, nullptr,
                 768, kh * 12, 8, K2, K2, 1024,
                 blockIdx.y * 128, blockIdx.x * 128, b, (long)256 * 1024, smem);
}

// ---------------------------------------------------------------------------
// conv3 helpers: fp32 [512] row -> folded bf16 [hi(512)|lo(512)]
// ---------------------------------------------------------------------------
__device__ __forceinline__ void conv3_row(const float* __restrict__ in,
                                          __nv_bfloat16* __restrict__ out, int t)
{
    float4 v = ((const float4*)in)[t];
    __nv_bfloat16 h0,h1,h2,h3,l0,l1,l2,l3;
    split_bf16(v.x,h0,l0); split_bf16(v.y,h1,l1);
    split_bf16(v.z,h2,l2); split_bf16(v.w,h3,l3);
    ((ushort4*)(out))[t]      = make_ushort4(bfr(h0),bfr(h1),bfr(h2),bfr(h3));
    ((ushort4*)(out + CC))[t] = make_ushort4(bfr(l0),bfr(l1),bfr(l2),bfr(l3));
}

__global__ void conv3_weights3(const float* __restrict__ w0, __nv_bfloat16* __restrict__ o0,
                               const float* __restrict__ w1, __nv_bfloat16* __restrict__ o1,
                               const float* __restrict__ w2, __nv_bfloat16* __restrict__ o2)
{
    const int r = blockIdx.x;
    const int sel = r >> 9, rw = r & 511;
    const float* in; __nv_bfloat16* out;
    if (sel == 0)      { in = w0; out = o0; }
    else if (sel == 1) { in = w1; out = o1; }
    else               { in = w2; out = o2; }
    conv3_row(in + (long)rw * CC, out + (long)rw * K2, threadIdx.x);
}

__global__ void conv3_qk(const float* __restrict__ xq, __nv_bfloat16* __restrict__ oq,
                         const float* __restrict__ xk, __nv_bfloat16* __restrict__ ok)
{
    const int r = blockIdx.x;       // 0..10239
    const float* in; __nv_bfloat16* out; int rr;
    if (r < 8192) { in = xq; out = oq; rr = r; }
    else          { in = xk; out = ok; rr = r - 8192; }
    conv3_row(in + (long)rr * CC, out + (long)rr * K2, threadIdx.x);
}

__global__ void conv3_one(const float* __restrict__ in, __nv_bfloat16* __restrict__ out)
{
    const long r = blockIdx.x;
    conv3_row(in + r * CC, out + r * K2, threadIdx.x);
}

// ---------------------------------------------------------------------------
// Fused norm: rows <8192 = q (reorder), else k. Folded [hi|lo] emit.
// ---------------------------------------------------------------------------
__global__ void norm_fused(const float* __restrict__ qin, __nv_bfloat16* __restrict__ qout,
                           const float* __restrict__ kin, __nv_bfloat16* __restrict__ kout)
{
    const int r = blockIdx.x;
    const int t = threadIdx.x;
    const float* in;
    __nv_bfloat16* out;
    long orow;
    if (r < NROWS_Q) {
        in = qin + (long)r * CC;
        int n = r >> 7, m = (r >> 3) & 15, b = r & 7;
        orow = (long)(b * 1024 + m * 64 + n);
        out = qout;
    } else {
        int rk = r - NROWS_Q;
        in = kin + (long)rk * CC;
        orow = rk;
        out = kout;
    }
    float4 v = ((const float4*)in)[t];
    float ss = v.x*v.x + v.y*v.y + v.z*v.z + v.w*v.w;
#pragma unroll
    for (int o = 16; o; o >>= 1) ss += __shfl_xor_sync(0xffffffffu, ss, o);
    __shared__ float sw[4];
    if ((t & 31) == 0) sw[t >> 5] = ss;
    __syncthreads();
    float tot = sw[0] + sw[1] + sw[2] + sw[3];
    float scale = 1.0f / fmaxf(sqrtf(tot), 1e-12f);

    __nv_bfloat16 h0,h1,h2,h3,l0,l1,l2,l3;
    split_bf16(v.x*scale,h0,l0); split_bf16(v.y*scale,h1,l1);
    split_bf16(v.z*scale,h2,l2); split_bf16(v.w*scale,h3,l3);
    __nv_bfloat16* base = out + orow * K2;
    ((ushort4*)(base))[t]      = make_ushort4(bfr(h0),bfr(h1),bfr(h2),bfr(h3));
    ((ushort4*)(base + CC))[t] = make_ushort4(bfr(l0),bfr(l1),bfr(l2),bfr(l3));
}

// ---------------------------------------------------------------------------
// Transpose + folded split: Wv fp32 [512][512] -> wvT3 [512][1024]
// (row c of output = column c of Wv)
// ---------------------------------------------------------------------------
__global__ void trconv_w(const float* __restrict__ in, __nv_bfloat16* __restrict__ out)
{
    __shared__ float s[32][33];
    const int d0 = blockIdx.y * 32, c0 = blockIdx.x * 32;
    const int tx = threadIdx.x, ty = threadIdx.y;
#pragma unroll
    for (int i = 0; i < 4; i++)
        s[ty + 8*i][tx] = in[(long)(d0 + ty + 8*i) * 512 + c0 + tx];
    __syncthreads();
#pragma unroll
    for (int i = 0; i < 4; i++) {
        const int c = c0 + ty + 8*i;
        float x = s[tx][ty + 8*i];
        __nv_bfloat16 h, l; split_bf16(x, h, l);
        __nv_bfloat16* p = out + (long)c * K2 + d0 + tx;
        p[0]  = h;
        p[CC] = l;
    }
}

// ---------------------------------------------------------------------------
// Transpose + folded split: vp fp32 [b][256][512] -> vT3 [b][512][512]
// ---------------------------------------------------------------------------
__global__ void trconv_v(const float* __restrict__ in, __nv_bfloat16* __restrict__ out)
{
    __shared__ float s[32][33];
    const int b = blockIdx.z;
    const float* ib = in + (long)b * 256 * 512;
    __nv_bfloat16* ob = out + (long)b * 512 * 512;
    const int k0 = blockIdx.y * 32, w0 = blockIdx.x * 32;
    const int tx = threadIdx.x, ty = threadIdx.y;
#pragma unroll
    for (int i = 0; i < 4; i++)
        s[ty + 8*i][tx] = ib[(long)(k0 + ty + 8*i) * 512 + w0 + tx];
    __syncthreads();
#pragma unroll
    for (int i = 0; i < 4; i++) {
        const int wrow = w0 + ty + 8*i;
        float x = s[tx][ty + 8*i];
        __nv_bfloat16 h, l; split_bf16(x, h, l);
        __nv_bfloat16* p = ob + (long)wrow * 512 + k0 + tx;
        p[0]   = h;
        p[256] = l;
    }
}

// ---------------------------------------------------------------------------
// Sinkhorn: one warp per (b,k) problem, SINK_ITERS iterations.
// Reads S0+S1. Writes score + folded transposed Tt3 via chunked smem transpose.
// ---------------------------------------------------------------------------
__global__ __launch_bounds__(256)
void sinkhorn_kernel(const float* __restrict__ S0, const float* __restrict__ S1,
                     __nv_bfloat16* __restrict__ Tt3, float* __restrict__ score)
{
    __shared__ __align__(16) __nv_bfloat16 th[256][8];
    __shared__ __align__(16) __nv_bfloat16 tl[256][8];

    const int w    = threadIdx.x >> 5;
    const int lane = threadIdx.x & 31;
    const int pb   = blockIdx.x * 8;
    const int p    = pb + w;
    const int b    = pb >> 8;
    const int k0   = pb & 255;
    const float* s0 = S0 + (long)p * (MMQ * NQ);
    const float* s1 = S1 + (long)p * (MMQ * NQ);

    float Km[32];
#pragma unroll
    for (int i = 0; i < 16; i++) {
        Km[i]      = __expf((s0[i*64+lane]    + s1[i*64+lane]    - 1.0f) * INV_EPS);
        Km[i + 16] = __expf((s0[i*64+lane+32] + s1[i*64+lane+32] - 1.0f) * INV_EPS);
    }

    const float MU = 1.0f / 16.0f + 1e-8f;
    const float NU = 1.0f / 64.0f + 1e-8f;
    float b0 = 1.0f, b1 = 1.0f;
    float a[16];

#pragma unroll 1
    for (int iter = 0; iter < SINK_ITERS; iter++) {
        float v[16];
#pragma unroll
        for (int i = 0; i < 16; i++) v[i] = Km[i] * b0 + Km[i + 16] * b1;
#pragma unroll
        for (int i = 0; i < 8; i++) {
            float t0 = v[i], t1 = v[i + 8];
            float r0 = __shfl_xor_sync(0xffffffffu, t0, 16);
            float r1 = __shfl_xor_sync(0xffffffffu, t1, 16);
            v[i] = (lane & 16) ? (t1 + r1) : (t0 + r0);
        }
#pragma unroll
        for (int i = 0; i < 4; i++) {
            float t0 = v[i], t1 = v[i + 4];
            float r0 = __shfl_xor_sync(0xffffffffu, t0, 8);
            float r1 = __shfl_xor_sync(0xffffffffu, t1, 8);
            v[i] = (lane & 8) ? (t1 + r1) : (t0 + r0);
        }
#pragma unroll
        for (int i = 0; i < 2; i++) {
            float t0 = v[i], t1 = v[i + 2];
            float r0 = __shfl_xor_sync(0xffffffffu, t0, 4);
            float r1 = __shfl_xor_sync(0xffffffffu, t1, 4);
            v[i] = (lane & 4) ? (t1 + r1) : (t0 + r0);
        }
        {
            float t0 = v[0], t1 = v[1];
            float r0 = __shfl_xor_sync(0xffffffffu, t0, 2);
            float r1 = __shfl_xor_sync(0xffffffffu, t1, 2);
            v[0] = (lane & 2) ? (t1 + r1) : (t0 + r0);
        }
        v[0] += __shfl_xor_sync(0xffffffffu, v[0], 1);

        float av = __fdividef(MU, v[0]);
#pragma unroll
        for (int i = 0; i < 16; i++) a[i] = __shfl_sync(0xffffffffu, av, 2 * i);

        float c0a = 0.f, c0b = 0.f, c1a = 0.f, c1b = 0.f;
#pragma unroll
        for (int i = 0; i < 16; i += 2) {
            c0a += Km[i] * a[i];       c0b += Km[i + 1] * a[i + 1];
            c1a += Km[i + 16] * a[i];  c1b += Km[i + 17] * a[i + 1];
        }
        b0 = __fdividef(NU, c0a + c0b);
        b1 = __fdividef(NU, c1a + c1b);
    }

    // ---- epilogue: score + chunked smem transpose into folded Tt3 ----
    float* Srow = score + (long)p * (MMQ * NQ);
#pragma unroll 1
    for (int q = 0; q < 4; q++) {
#pragma unroll
        for (int ii = 0; ii < 4; ii++) {
            const int i = q * 4 + ii;
            float T0 = a[i] * Km[i] * b0;
            float T1 = a[i] * Km[i + 16] * b1;
            float sv0 = s0[i*64+lane]    + s1[i*64+lane];
            float sv1 = s0[i*64+lane+32] + s1[i*64+lane+32];
            Srow[i * 64 + lane]      = 1024.0f * sv0 * T0;
            Srow[i * 64 + lane + 32] = 1024.0f * sv1 * T1;
            __nv_bfloat16 h, l;
            split_bf16(T0, h, l);
            th[i * 64 + lane - q * 256][w] = h;
            tl[i * 64 + lane - q * 256][w] = l;
            split_bf16(T1, h, l);
            th[i * 64 + lane + 32 - q * 256][w] = h;
            tl[i * 64 + lane + 32 - q * 256][w] = l;
        }
        __syncthreads();
        {
            const int r = threadIdx.x;      // 0..255
            __nv_bfloat16* d = Tt3 + ((long)b * 1024 + q * 256 + r) * 512 + k0;
            *(uint4*)(d)       = *(const uint4*)&th[r][0];
            *(uint4*)(d + 256) = *(const uint4*)&tl[r][0];
        }
        __syncthreads();
    }
}

// ---------------------------------------------------------------------------
extern "C" void kernel_launch(void* const* d_in, const int* in_sizes, int n_in,
                              void* d_out, int out_size)
{
    const float* xq = (const float*)d_in[0];
    const float* xk = (const float*)d_in[1];
    const float* xv = (const float*)d_in[2];
    const float* Wq = (const float*)d_in[3];
    const float* Wk = (const float*)d_in[4];
    const float* Wv = (const float*)d_in[5];
    const float* Wp = (const float*)d_in[6];
    const float* bp = (const float*)d_in[7];
    float* out_x     = (float*)d_out;
    float* out_score = out_x + X_ELEMS;

    __nv_bfloat16 *xq3,*xk3,*xv3,*wq3,*wk3,*wvT3,*wp3,*wc3,*qr3,*kn3,*Tt3,*vT3;
    float *qlin,*klin,*vp,*S0,*S1;
    cudaGetSymbolAddress((void**)&xq3,  g_xq3);
    cudaGetSymbolAddress((void**)&xk3,  g_xk3);
    cudaGetSymbolAddress((void**)&xv3,  g_xv3);
    cudaGetSymbolAddress((void**)&wq3,  g_wq3);
    cudaGetSymbolAddress((void**)&wk3,  g_wk3);
    cudaGetSymbolAddress((void**)&wvT3, g_wvT3);
    cudaGetSymbolAddress((void**)&wp3,  g_wp3);
    cudaGetSymbolAddress((void**)&wc3,  g_wc3);
    cudaGetSymbolAddress((void**)&qr3,  g_qr3);
    cudaGetSymbolAddress((void**)&kn3,  g_kn3);
    cudaGetSymbolAddress((void**)&Tt3,  g_Tt3);
    cudaGetSymbolAddress((void**)&vT3,  g_vT3);
    cudaGetSymbolAddress((void**)&qlin, g_qlin);
    cudaGetSymbolAddress((void**)&klin, g_klin);
    cudaGetSymbolAddress((void**)&vp,   g_v);
    cudaGetSymbolAddress((void**)&S0,   g_S0);
    cudaGetSymbolAddress((void**)&S1,   g_S1);

    cudaFuncSetAttribute(hgemm<0>,     cudaFuncAttributeMaxDynamicSharedMemorySize, GSMEM);
    cudaFuncSetAttribute(hgemm<3>,     cudaFuncAttributeMaxDynamicSharedMemorySize, GSMEM);
    cudaFuncSetAttribute(hgemm_projqk, cudaFuncAttributeMaxDynamicSharedMemorySize, GSMEM);
    cudaFuncSetAttribute(hgemm_sim,    cudaFuncAttributeMaxDynamicSharedMemorySize, GSMEM);

    // Side stream + events (host objects; graph replays skip host code)
    cudaStream_t sA;
    cudaStreamCreateWithFlags(&sA, cudaStreamNonBlocking);
    cudaEvent_t eRoot, eW, eV;
    cudaEventCreateWithFlags(&eRoot, cudaEventDisableTiming);
    cudaEventCreateWithFlags(&eW,    cudaEventDisableTiming);
    cudaEventCreateWithFlags(&eV,    cudaEventDisableTiming);

    // --- main: weight conv (Wq, Wk, Wp) ---
    cudaEventRecord(eRoot, 0);
    conv3_weights3<<<3 * CC, 128>>>(Wq, wq3, Wk, wk3, Wp, wp3);
    cudaEventRecord(eW, 0);

    // --- sA: Wv transpose+split, xv conv, then Wc = Wp·Wv, conv, vp, trconv ---
    cudaStreamWaitEvent(sA, eRoot, 0);
    trconv_w<<<dim3(16, 16), dim3(32, 8), 0, sA>>>(Wv, wvT3);
    conv3_one<<<NROWS_K, 128, 0, sA>>>(xv, xv3);
    cudaStreamWaitEvent(sA, eW, 0);
    hgemm<0><<<dim3(4, 4), 256, GSMEM, sA>>>(
        wp3, wvT3, vp /*Wc fp32 scratch*/, nullptr, K3, 8, K2, K2, 512, 0, 0, 0);
    conv3_one<<<CC, 128, 0, sA>>>(vp, wc3);
    hgemm<0><<<dim3(4, 16), 256, GSMEM, sA>>>(
        xv3, wc3, vp, nullptr, K3, 8, K2, K2, CC, 0, 0, 0);
    trconv_v<<<dim3(16, 8, 8), dim3(32, 8), 0, sA>>>(vp, vT3);
    cudaEventRecord(eV, sA);

    // --- main: xq+xk conv, q+k projections ---
    conv3_qk<<<NROWS_Q + NROWS_K, 128>>>(xq, xq3, xk, xk3);
    hgemm_projqk<<<dim3(4, 80), 256, GSMEM>>>(xq3, wq3, qlin, xk3, wk3, klin);

    // --- l2 normalize (fused q+k), folded split-bf16 emit ---
    norm_fused<<<NROWS_Q + NROWS_K, 128>>>(qlin, qr3, klin, kn3);

    // --- sim split-K=2, single launch, 256 CTAs (full chip) ---
    hgemm_sim<<<dim3(8, 2, 16), 256, GSMEM>>>(kn3, qr3, S0, S1);

    // --- Sinkhorn (reads S0+S1) -> folded Tt3 + score_map ---
    sinkhorn_kernel<<<BKP / 8, 256>>>(S0, S1, Tt3, out_score);

    // --- join vp path; x = T^T·vp + bp with direct scatter to (n,m,b,c) ---
    cudaStreamWaitEvent(0, eV, 0);
    hgemm<3><<<dim3(4, 8, 8), 256, GSMEM>>>(
        Tt3, vT3, out_x, bp, 768, 4, 512, 512, CC,
        (long)1024 * 512, (long)512 * 512, 0);
}

// round 15
// speedup vs baseline: 1.3987x; 1.0819x over previous
#include <cuda_runtime.h>
#include <cuda_bf16.h>
#include <cstdint>
#include <math.h>

// ---------------------------------------------------------------------------
// Problem constants
// ---------------------------------------------------------------------------
#define NQ   64
#define MMQ  16
#define BB   8
#define KK   256
#define CC   512
#define K2   1024           // folded [hi|lo] physical width for C=512 trios
#define K3   1536           // logical K for split-bf16 GEMMs
#define NROWS_Q 8192
#define NROWS_K 2048
#define BKP     2048
#define INV_EPS 20.0f
#define SINK_ITERS 48
#define X_ELEMS (NROWS_Q*CC)

// ---------------------------------------------------------------------------
// Scratch (device globals; no allocation allowed). Folded [hi|lo] storage.
// ---------------------------------------------------------------------------
__device__ __nv_bfloat16 g_xq3[NROWS_Q*K2];
__device__ __nv_bfloat16 g_xk3[NROWS_K*K2];
__device__ __nv_bfloat16 g_xv3[NROWS_K*K2];
__device__ __nv_bfloat16 g_wq3[CC*K2];
__device__ __nv_bfloat16 g_wk3[CC*K2];
__device__ __nv_bfloat16 g_wvT3[CC*K2];       // folded Wv^T (rows = input dim)
__device__ __nv_bfloat16 g_wp3[CC*K2];
__device__ __nv_bfloat16 g_wc3[CC*K2];        // folded Wc = Wp·Wv
__device__ float g_qlin[NROWS_Q*CC];
__device__ float g_klin[NROWS_K*CC];
__device__ float g_v   [NROWS_K*CC];          // Wc fp32 scratch, then vp
__device__ __nv_bfloat16 g_qr3[NROWS_Q*K2];
__device__ __nv_bfloat16 g_kn3[NROWS_K*K2];
__device__ float g_S0[BKP*MMQ*NQ];            // sim split-K partial 0
__device__ float g_S1[BKP*MMQ*NQ];            // sim split-K partial 1
__device__ __nv_bfloat16 g_Tt3[BB*1024*512];  // folded [hi|lo]
__device__ __nv_bfloat16 g_vT3[BB*512*512];   // folded [hi|lo]

// ---------------------------------------------------------------------------
// PTX helpers
// ---------------------------------------------------------------------------
__device__ __forceinline__ uint32_t s2u(const void* p){
    uint32_t a;
    asm("{ .reg .u64 t; cvta.to.shared.u64 t, %1; cvt.u32.u64 %0, t; }"
        : "=r"(a) : "l"(p));
    return a;
}

#define CP_ASYNC16(dst, src) \
    asm volatile("cp.async.cg.shared.global [%0], [%1], 16;" :: "r"(dst), "l"(src) : "memory")
#define CP_COMMIT() asm volatile("cp.async.commit_group;" ::: "memory")
#define CP_WAIT1()  asm volatile("cp.async.wait_group 1;" ::: "memory")
#define CP_WAIT0()  asm volatile("cp.async.wait_group 0;" ::: "memory")

#define LDMATRIX_X4(r0, r1, r2, r3, addr) \
    asm volatile("ldmatrix.sync.aligned.m8n8.x4.shared.b16 {%0,%1,%2,%3}, [%4];" \
                 : "=r"(r0), "=r"(r1), "=r"(r2), "=r"(r3) : "r"(addr))

#define MMA16816(d, a, b0, b1) \
    asm volatile("mma.sync.aligned.m16n8k16.row.col.f32.bf16.bf16.f32 " \
                 "{%0,%1,%2,%3}, {%4,%5,%6,%7}, {%8,%9}, {%0,%1,%2,%3};" \
                 : "+f"((d)[0]), "+f"((d)[1]), "+f"((d)[2]), "+f"((d)[3]) \
                 : "r"((a)[0]), "r"((a)[1]), "r"((a)[2]), "r"((a)[3]), \
                   "r"(b0), "r"(b1))

__device__ __forceinline__ unsigned short bfr(__nv_bfloat16 h){
    return *reinterpret_cast<unsigned short*>(&h);
}
__device__ __forceinline__ void split_bf16(float x, __nv_bfloat16& h, __nv_bfloat16& l){
    h = __float2bfloat16(x);
    l = __float2bfloat16(x - __bfloat162float(h));
}
__device__ __forceinline__ uint32_t pack2(__nv_bfloat16 a, __nv_bfloat16 b){
    return (uint32_t)bfr(a) | ((uint32_t)bfr(b) << 16);
}

// ---------------------------------------------------------------------------
// HMMA GEMM core (R6-proven mainloop; folded-operand loader):
//  A logical [hi|lo|hi]: phys chunk ca = cg>=2S ? cg-2S : cg
//  B logical [hi|hi|lo]: phys chunk cb = cg>=S  ? cg-S  : cg
// c0 = split-K chunk offset. CTA 128x128, BK=64, 3-stage ring, 2 CTAs/SM.
// EPI=0 fp32 store; EPI=3 out scatter+bias.
// ---------------------------------------------------------------------------
#define STG   32768
#define GSMEM (3*STG)

template<int EPI>
__device__ __forceinline__
void gemm_core(const __nv_bfloat16* __restrict__ A, const __nv_bfloat16* __restrict__ B,
               void* __restrict__ Cv, const float* __restrict__ bias,
               int Kp, int c0, int S, int lda, int ldb, int ldc,
               int mb, int nb, int bz, long cStride, char* smem)
{
    const int tid  = threadIdx.x;
    const int w    = tid >> 5;
    const int lane = tid & 31;
    const int wm   = (w & 3) * 32;
    const int wn   = (w >> 2) * 64;

    const uint32_t sbase = s2u(smem);
    const int NC = Kp >> 6;

    const int lrow = tid >> 1;
    const int lcg0 = (tid & 1) * 4;

    auto load_chunk = [&](int c, int s){
        const uint32_t st = sbase + s * STG;
        const int cg = c0 + c;
        const int ca = (cg >= 2 * S) ? cg - 2 * S : cg;
        const int cb = (cg >= S)     ? cg - S     : cg;
        const __nv_bfloat16* Ag = A + (long)(mb + lrow) * lda + ca * 64 + lcg0 * 8;
        const __nv_bfloat16* Bg = B + (long)(nb + lrow) * ldb + cb * 64 + lcg0 * 8;
        const uint32_t rbase = lrow * 128;
        const uint32_t sw    = (lrow & 7) << 4;
#pragma unroll
        for (int j = 0; j < 4; j++) {
            uint32_t off = rbase + (((lcg0 + j) << 4) ^ sw);
            CP_ASYNC16(st + off, Ag + j * 8);
            CP_ASYNC16(st + 16384 + off, Bg + j * 8);
        }
        CP_COMMIT();
    };

    float acc[2][8][4];
#pragma unroll
    for (int i = 0; i < 2; i++)
#pragma unroll
        for (int j = 0; j < 8; j++)
#pragma unroll
            for (int q = 0; q < 4; q++) acc[i][j][q] = 0.f;

    load_chunk(0, 0);
    load_chunk(1, 1);

    const int a_r  = lane & 15;
    const int a_kb = (lane & 16);
    const int b_r  = ((lane >> 4) << 3) + (lane & 7);
    const int b_kb = ((lane >> 3) & 1) << 4;

    int stage = 0;
    for (int c = 0; c < NC; c++) {
        if (c + 1 < NC) CP_WAIT1(); else CP_WAIT0();
        __syncthreads();

        if (c + 2 < NC) {
            int ns = stage + 2; if (ns >= 3) ns -= 3;
            load_chunk(c + 2, ns);
        }

        const uint32_t sa = sbase + stage * STG;
        const uint32_t sb = sa + 16384;

        uint32_t br2[2][4][4];
#pragma unroll
        for (int nj = 0; nj < 4; nj++) {
            int row = wn + nj * 16 + b_r;
            uint32_t kb = (uint32_t)(b_kb) ^ ((row & 7) << 4);
            LDMATRIX_X4(br2[0][nj][0], br2[0][nj][1], br2[0][nj][2], br2[0][nj][3],
                        sb + row * 128 + kb);
        }
#pragma unroll
        for (int ks = 0; ks < 4; ks++) {
            const int cur = ks & 1;
            if (ks < 3) {
#pragma unroll
                for (int nj = 0; nj < 4; nj++) {
                    int row = wn + nj * 16 + b_r;
                    uint32_t kb = (uint32_t)((ks + 1) * 32 + b_kb) ^ ((row & 7) << 4);
                    LDMATRIX_X4(br2[cur ^ 1][nj][0], br2[cur ^ 1][nj][1],
                                br2[cur ^ 1][nj][2], br2[cur ^ 1][nj][3],
                                sb + row * 128 + kb);
                }
            }
            uint32_t ar[2][4];
#pragma unroll
            for (int mi = 0; mi < 2; mi++) {
                int row = wm + mi * 16 + a_r;
                uint32_t kb = (uint32_t)(ks * 32 + a_kb) ^ ((row & 7) << 4);
                LDMATRIX_X4(ar[mi][0], ar[mi][1], ar[mi][2], ar[mi][3],
                            sa + row * 128 + kb);
            }
#pragma unroll
            for (int mi = 0; mi < 2; mi++)
#pragma unroll
                for (int nj = 0; nj < 4; nj++) {
                    MMA16816(acc[mi][nj * 2],     ar[mi], br2[cur][nj][0], br2[cur][nj][1]);
                    MMA16816(acc[mi][nj * 2 + 1], ar[mi], br2[cur][nj][2], br2[cur][nj][3]);
                }
        }
        stage++; if (stage == 3) stage = 0;
    }

    // ---- epilogue ----
    const int er = lane >> 2;
    const int ec = (lane & 3) * 2;
#pragma unroll
    for (int mi = 0; mi < 2; mi++) {
#pragma unroll
        for (int half = 0; half < 2; half++) {
            const int R = mb + wm + mi * 16 + er + half * 8;
            if (EPI == 0) {
                float* Crow = (float*)Cv + (long)bz * cStride + (long)R * ldc;
#pragma unroll
                for (int nj = 0; nj < 8; nj++) {
                    const int col = nb + wn + nj * 8 + ec;
                    *(float2*)&Crow[col] =
                        make_float2(acc[mi][nj][half * 2], acc[mi][nj][half * 2 + 1]);
                }
            } else {
                const int mq = R >> 6, nq = R & 63;
                float* Crow = (float*)Cv + (long)(((nq << 4) + mq) * 8 + bz) * CC;
#pragma unroll
                for (int nj = 0; nj < 8; nj++) {
                    const int col = nb + wn + nj * 8 + ec;
                    *(float2*)&Crow[col] = make_float2(
                        acc[mi][nj][half * 2] + bias[col],
                        acc[mi][nj][half * 2 + 1] + bias[col + 1]);
                }
            }
        }
    }
}

// generic GEMM
template<int EPI>
__global__ __launch_bounds__(256, 2)
void hgemm(const __nv_bfloat16* __restrict__ A, const __nv_bfloat16* __restrict__ B,
           void* __restrict__ C, const float* __restrict__ bias,
           int Kp, int S, int lda, int ldb, int ldc,
           long aStride, long bStride, long cStride)
{
    extern __shared__ char smem[];
    const int bz = blockIdx.z;
    gemm_core<EPI>(A + bz * aStride, B + bz * bStride, C, bias,
                   Kp, 0, S, lda, ldb, ldc,
                   blockIdx.y * 128, blockIdx.x * 128, bz, cStride, smem);
}

// q+k projections fused: grid.y in [0,80): 0-63 q, 64-79 k
__global__ __launch_bounds__(256, 2)
void hgemm_projqk(const __nv_bfloat16* __restrict__ Aq, const __nv_bfloat16* __restrict__ Bq,
                  float* __restrict__ Cq,
                  const __nv_bfloat16* __restrict__ Ak, const __nv_bfloat16* __restrict__ Bk,
                  float* __restrict__ Ck)
{
    extern __shared__ char smem[];
    const int by = blockIdx.y;
    if (by < 64)
        gemm_core<0>(Aq, Bq, Cq, nullptr, K3, 0, 8, K2, K2, CC,
                     by * 128, blockIdx.x * 128, 0, 0, smem);
    else
        gemm_core<0>(Ak, Bk, Ck, nullptr, K3, 0, 8, K2, K2, CC,
                     (by - 64) * 128, blockIdx.x * 128, 0, 0, smem);
}

// sim split-K=2: z = b*2 + kh; chunk offset c0 = kh*12
__global__ __launch_bounds__(256, 2)
void hgemm_sim(const __nv_bfloat16* __restrict__ A, const __nv_bfloat16* __restrict__ B,
               float* __restrict__ S0, float* __restrict__ S1)
{
    extern __shared__ char smem[];
    const int z = blockIdx.z;
    const int b = z >> 1;
    const int kh = z & 1;
    gemm_core<0>(A + (long)b * 256 * K2,
                 B + (long)b * 1024 * K2,
                 kh ? S1 : S0, nullptr,
                 768, kh * 12, 8, K2, K2, 1024,
                 blockIdx.y * 128, blockIdx.x * 128, b, (long)256 * 1024, smem);
}

// ---------------------------------------------------------------------------
// conv3 helpers: fp32 [512] row -> folded bf16 [hi(512)|lo(512)]
// ---------------------------------------------------------------------------
__device__ __forceinline__ void conv3_row(const float* __restrict__ in,
                                          __nv_bfloat16* __restrict__ out, int t)
{
    float4 v = ((const float4*)in)[t];
    __nv_bfloat16 h0,h1,h2,h3,l0,l1,l2,l3;
    split_bf16(v.x,h0,l0); split_bf16(v.y,h1,l1);
    split_bf16(v.z,h2,l2); split_bf16(v.w,h3,l3);
    ((ushort4*)(out))[t]      = make_ushort4(bfr(h0),bfr(h1),bfr(h2),bfr(h3));
    ((ushort4*)(out + CC))[t] = make_ushort4(bfr(l0),bfr(l1),bfr(l2),bfr(l3));
}

// Merged conversion: r<512 Wq; <1024 Wk; <1536 Wp; then xq (8192) then xk (2048)
__global__ void conv_all(const float* __restrict__ Wq, __nv_bfloat16* __restrict__ oWq,
                         const float* __restrict__ Wk, __nv_bfloat16* __restrict__ oWk,
                         const float* __restrict__ Wp, __nv_bfloat16* __restrict__ oWp,
                         const float* __restrict__ xq, __nv_bfloat16* __restrict__ oxq,
                         const float* __restrict__ xk, __nv_bfloat16* __restrict__ oxk)
{
    const int r = blockIdx.x;
    const float* in; __nv_bfloat16* out; int rr;
    if (r < 512)        { in = Wq; out = oWq; rr = r; }
    else if (r < 1024)  { in = Wk; out = oWk; rr = r - 512; }
    else if (r < 1536)  { in = Wp; out = oWp; rr = r - 1024; }
    else if (r < 9728)  { in = xq; out = oxq; rr = r - 1536; }
    else                { in = xk; out = oxk; rr = r - 9728; }
    conv3_row(in + (long)rr * CC, out + (long)rr * K2, threadIdx.x);
}

__global__ void conv3_one(const float* __restrict__ in, __nv_bfloat16* __restrict__ out)
{
    const long r = blockIdx.x;
    conv3_row(in + r * CC, out + r * K2, threadIdx.x);
}

// ---------------------------------------------------------------------------
// Fused norm: rows <8192 = q (reorder), else k. Folded [hi|lo] emit.
// ---------------------------------------------------------------------------
__global__ void norm_fused(const float* __restrict__ qin, __nv_bfloat16* __restrict__ qout,
                           const float* __restrict__ kin, __nv_bfloat16* __restrict__ kout)
{
    const int r = blockIdx.x;
    const int t = threadIdx.x;
    const float* in;
    __nv_bfloat16* out;
    long orow;
    if (r < NROWS_Q) {
        in = qin + (long)r * CC;
        int n = r >> 7, m = (r >> 3) & 15, b = r & 7;
        orow = (long)(b * 1024 + m * 64 + n);
        out = qout;
    } else {
        int rk = r - NROWS_Q;
        in = kin + (long)rk * CC;
        orow = rk;
        out = kout;
    }
    float4 v = ((const float4*)in)[t];
    float ss = v.x*v.x + v.y*v.y + v.z*v.z + v.w*v.w;
#pragma unroll
    for (int o = 16; o; o >>= 1) ss += __shfl_xor_sync(0xffffffffu, ss, o);
    __shared__ float sw[4];
    if ((t & 31) == 0) sw[t >> 5] = ss;
    __syncthreads();
    float tot = sw[0] + sw[1] + sw[2] + sw[3];
    float scale = 1.0f / fmaxf(sqrtf(tot), 1e-12f);

    __nv_bfloat16 h0,h1,h2,h3,l0,l1,l2,l3;
    split_bf16(v.x*scale,h0,l0); split_bf16(v.y*scale,h1,l1);
    split_bf16(v.z*scale,h2,l2); split_bf16(v.w*scale,h3,l3);
    __nv_bfloat16* base = out + orow * K2;
    ((ushort4*)(base))[t]      = make_ushort4(bfr(h0),bfr(h1),bfr(h2),bfr(h3));
    ((ushort4*)(base + CC))[t] = make_ushort4(bfr(l0),bfr(l1),bfr(l2),bfr(l3));
}

// ---------------------------------------------------------------------------
// Transpose + folded split: Wv fp32 [512][512] -> wvT3 [512][1024]
// ---------------------------------------------------------------------------
__global__ void trconv_w(const float* __restrict__ in, __nv_bfloat16* __restrict__ out)
{
    __shared__ float s[32][33];
    const int d0 = blockIdx.y * 32, c0 = blockIdx.x * 32;
    const int tx = threadIdx.x, ty = threadIdx.y;
#pragma unroll
    for (int i = 0; i < 4; i++)
        s[ty + 8*i][tx] = in[(long)(d0 + ty + 8*i) * 512 + c0 + tx];
    __syncthreads();
#pragma unroll
    for (int i = 0; i < 4; i++) {
        const int c = c0 + ty + 8*i;
        float x = s[tx][ty + 8*i];
        __nv_bfloat16 h, l; split_bf16(x, h, l);
        __nv_bfloat16* p = out + (long)c * K2 + d0 + tx;
        p[0]  = h;
        p[CC] = l;
    }
}

// ---------------------------------------------------------------------------
// Transpose + folded split: vp fp32 [b][256][512] -> vT3 [b][512][512]
// ---------------------------------------------------------------------------
__global__ void trconv_v(const float* __restrict__ in, __nv_bfloat16* __restrict__ out)
{
    __shared__ float s[32][33];
    const int b = blockIdx.z;
    const float* ib = in + (long)b * 256 * 512;
    __nv_bfloat16* ob = out + (long)b * 512 * 512;
    const int k0 = blockIdx.y * 32, w0 = blockIdx.x * 32;
    const int tx = threadIdx.x, ty = threadIdx.y;
#pragma unroll
    for (int i = 0; i < 4; i++)
        s[ty + 8*i][tx] = ib[(long)(k0 + ty + 8*i) * 512 + w0 + tx];
    __syncthreads();
#pragma unroll
    for (int i = 0; i < 4; i++) {
        const int wrow = w0 + ty + 8*i;
        float x = s[tx][ty + 8*i];
        __nv_bfloat16 h, l; split_bf16(x, h, l);
        __nv_bfloat16* p = ob + (long)wrow * 512 + k0 + tx;
        p[0]   = h;
        p[256] = l;
    }
}

// ---------------------------------------------------------------------------
// Sinkhorn: one warp per (b,k) problem, SINK_ITERS iterations.
// Reads S0+S1. Writes score + folded transposed Tt3 via chunked smem transpose.
// ---------------------------------------------------------------------------
__global__ __launch_bounds__(256)
void sinkhorn_kernel(const float* __restrict__ S0, const float* __restrict__ S1,
                     __nv_bfloat16* __restrict__ Tt3, float* __restrict__ score)
{
    __shared__ __align__(16) __nv_bfloat16 th[256][8];
    __shared__ __align__(16) __nv_bfloat16 tl[256][8];

    const int w    = threadIdx.x >> 5;
    const int lane = threadIdx.x & 31;
    const int pb   = blockIdx.x * 8;
    const int p    = pb + w;
    const int b    = pb >> 8;
    const int k0   = pb & 255;
    const float* s0 = S0 + (long)p * (MMQ * NQ);
    const float* s1 = S1 + (long)p * (MMQ * NQ);

    float Km[32];
#pragma unroll
    for (int i = 0; i < 16; i++) {
        Km[i]      = __expf((s0[i*64+lane]    + s1[i*64+lane]    - 1.0f) * INV_EPS);
        Km[i + 16] = __expf((s0[i*64+lane+32] + s1[i*64+lane+32] - 1.0f) * INV_EPS);
    }

    const float MU = 1.0f / 16.0f + 1e-8f;
    const float NU = 1.0f / 64.0f + 1e-8f;
    float b0 = 1.0f, b1 = 1.0f;
    float a[16];

#pragma unroll 1
    for (int iter = 0; iter < SINK_ITERS; iter++) {
        float v[16];
#pragma unroll
        for (int i = 0; i < 16; i++) v[i] = Km[i] * b0 + Km[i + 16] * b1;
#pragma unroll
        for (int i = 0; i < 8; i++) {
            float t0 = v[i], t1 = v[i + 8];
            float r0 = __shfl_xor_sync(0xffffffffu, t0, 16);
            float r1 = __shfl_xor_sync(0xffffffffu, t1, 16);
            v[i] = (lane & 16) ? (t1 + r1) : (t0 + r0);
        }
#pragma unroll
        for (int i = 0; i < 4; i++) {
            float t0 = v[i], t1 = v[i + 4];
            float r0 = __shfl_xor_sync(0xffffffffu, t0, 8);
            float r1 = __shfl_xor_sync(0xffffffffu, t1, 8);
            v[i] = (lane & 8) ? (t1 + r1) : (t0 + r0);
        }
#pragma unroll
        for (int i = 0; i < 2; i++) {
            float t0 = v[i], t1 = v[i + 2];
            float r0 = __shfl_xor_sync(0xffffffffu, t0, 4);
            float r1 = __shfl_xor_sync(0xffffffffu, t1, 4);
            v[i] = (lane & 4) ? (t1 + r1) : (t0 + r0);
        }
        {
            float t0 = v[0], t1 = v[1];
            float r0 = __shfl_xor_sync(0xffffffffu, t0, 2);
            float r1 = __shfl_xor_sync(0xffffffffu, t1, 2);
            v[0] = (lane & 2) ? (t1 + r1) : (t0 + r0);
        }
        v[0] += __shfl_xor_sync(0xffffffffu, v[0], 1);

        float av = __fdividef(MU, v[0]);
#pragma unroll
        for (int i = 0; i < 16; i++) a[i] = __shfl_sync(0xffffffffu, av, 2 * i);

        float c0a = 0.f, c0b = 0.f, c1a = 0.f, c1b = 0.f;
#pragma unroll
        for (int i = 0; i < 16; i += 2) {
            c0a += Km[i] * a[i];       c0b += Km[i + 1] * a[i + 1];
            c1a += Km[i + 16] * a[i];  c1b += Km[i + 17] * a[i + 1];
        }
        b0 = __fdividef(NU, c0a + c0b);
        b1 = __fdividef(NU, c1a + c1b);
    }

    // ---- epilogue: score + chunked smem transpose into folded Tt3 ----
    float* Srow = score + (long)p * (MMQ * NQ);
#pragma unroll 1
    for (int q = 0; q < 4; q++) {
#pragma unroll
        for (int ii = 0; ii < 4; ii++) {
            const int i = q * 4 + ii;
            float T0 = a[i] * Km[i] * b0;
            float T1 = a[i] * Km[i + 16] * b1;
            float sv0 = s0[i*64+lane]    + s1[i*64+lane];
            float sv1 = s0[i*64+lane+32] + s1[i*64+lane+32];
            Srow[i * 64 + lane]      = 1024.0f * sv0 * T0;
            Srow[i * 64 + lane + 32] = 1024.0f * sv1 * T1;
            __nv_bfloat16 h, l;
            split_bf16(T0, h, l);
            th[i * 64 + lane - q * 256][w] = h;
            tl[i * 64 + lane - q * 256][w] = l;
            split_bf16(T1, h, l);
            th[i * 64 + lane + 32 - q * 256][w] = h;
            tl[i * 64 + lane + 32 - q * 256][w] = l;
        }
        __syncthreads();
        {
            const int r = threadIdx.x;      // 0..255
            __nv_bfloat16* d = Tt3 + ((long)b * 1024 + q * 256 + r) * 512 + k0;
            *(uint4*)(d)       = *(const uint4*)&th[r][0];
            *(uint4*)(d + 256) = *(const uint4*)&tl[r][0];
        }
        __syncthreads();
    }
}

// ---------------------------------------------------------------------------
extern "C" void kernel_launch(void* const* d_in, const int* in_sizes, int n_in,
                              void* d_out, int out_size)
{
    const float* xq = (const float*)d_in[0];
    const float* xk = (const float*)d_in[1];
    const float* xv = (const float*)d_in[2];
    const float* Wq = (const float*)d_in[3];
    const float* Wk = (const float*)d_in[4];
    const float* Wv = (const float*)d_in[5];
    const float* Wp = (const float*)d_in[6];
    const float* bp = (const float*)d_in[7];
    float* out_x     = (float*)d_out;
    float* out_score = out_x + X_ELEMS;

    __nv_bfloat16 *xq3,*xk3,*xv3,*wq3,*wk3,*wvT3,*wp3,*wc3,*qr3,*kn3,*Tt3,*vT3;
    float *qlin,*klin,*vp,*S0,*S1;
    cudaGetSymbolAddress((void**)&xq3,  g_xq3);
    cudaGetSymbolAddress((void**)&xk3,  g_xk3);
    cudaGetSymbolAddress((void**)&xv3,  g_xv3);
    cudaGetSymbolAddress((void**)&wq3,  g_wq3);
    cudaGetSymbolAddress((void**)&wk3,  g_wk3);
    cudaGetSymbolAddress((void**)&wvT3, g_wvT3);
    cudaGetSymbolAddress((void**)&wp3,  g_wp3);
    cudaGetSymbolAddress((void**)&wc3,  g_wc3);
    cudaGetSymbolAddress((void**)&qr3,  g_qr3);
    cudaGetSymbolAddress((void**)&kn3,  g_kn3);
    cudaGetSymbolAddress((void**)&Tt3,  g_Tt3);
    cudaGetSymbolAddress((void**)&vT3,  g_vT3);
    cudaGetSymbolAddress((void**)&qlin, g_qlin);
    cudaGetSymbolAddress((void**)&klin, g_klin);
    cudaGetSymbolAddress((void**)&vp,   g_v);
    cudaGetSymbolAddress((void**)&S0,   g_S0);
    cudaGetSymbolAddress((void**)&S1,   g_S1);

    cudaFuncSetAttribute(hgemm<0>,     cudaFuncAttributeMaxDynamicSharedMemorySize, GSMEM);
    cudaFuncSetAttribute(hgemm<3>,     cudaFuncAttributeMaxDynamicSharedMemorySize, GSMEM);
    cudaFuncSetAttribute(hgemm_projqk, cudaFuncAttributeMaxDynamicSharedMemorySize, GSMEM);
    cudaFuncSetAttribute(hgemm_sim,    cudaFuncAttributeMaxDynamicSharedMemorySize, GSMEM);

    // Side stream + events (host objects; graph replays skip host code)
    cudaStream_t sA;
    cudaStreamCreateWithFlags(&sA, cudaStreamNonBlocking);
    cudaEvent_t eRoot, eW, eV;
    cudaEventCreateWithFlags(&eRoot, cudaEventDisableTiming);
    cudaEventCreateWithFlags(&eW,    cudaEventDisableTiming);
    cudaEventCreateWithFlags(&eV,    cudaEventDisableTiming);

    // --- main: all conversions (weights + xq + xk) in one launch ---
    cudaEventRecord(eRoot, 0);
    conv_all<<<11776, 128>>>(Wq, wq3, Wk, wk3, Wp, wp3, xq, xq3, xk, xk3);
    cudaEventRecord(eW, 0);

    // --- sA: Wv transpose+split, xv conv, then Wc = Wp·Wv, conv, vp, trconv ---
    cudaStreamWaitEvent(sA, eRoot, 0);
    trconv_w<<<dim3(16, 16), dim3(32, 8), 0, sA>>>(Wv, wvT3);
    conv3_one<<<NROWS_K, 128, 0, sA>>>(xv, xv3);
    cudaStreamWaitEvent(sA, eW, 0);
    hgemm<0><<<dim3(4, 4), 256, GSMEM, sA>>>(
        wp3, wvT3, vp /*Wc fp32 scratch*/, nullptr, K3, 8, K2, K2, 512, 0, 0, 0);
    conv3_one<<<CC, 128, 0, sA>>>(vp, wc3);
    hgemm<0><<<dim3(4, 16), 256, GSMEM, sA>>>(
        xv3, wc3, vp, nullptr, K3, 8, K2, K2, CC, 0, 0, 0);
    trconv_v<<<dim3(16, 8, 8), dim3(32, 8), 0, sA>>>(vp, vT3);
    cudaEventRecord(eV, sA);

    // --- main: q+k projections ---
    hgemm_projqk<<<dim3(4, 80), 256, GSMEM>>>(xq3, wq3, qlin, xk3, wk3, klin);

    // --- l2 normalize (fused q+k), folded split-bf16 emit ---
    norm_fused<<<NROWS_Q + NROWS_K, 128>>>(qlin, qr3, klin, kn3);

    // --- sim split-K=2, single launch, 256 CTAs (full chip) ---
    hgemm_sim<<<dim3(8, 2, 16), 256, GSMEM>>>(kn3, qr3, S0, S1);

    // --- Sinkhorn (reads S0+S1) -> folded Tt3 + score_map ---
    sinkhorn_kernel<<<BKP / 8, 256>>>(S0, S1, Tt3, out_score);

    // --- join vp path; x = T^T·vp + bp with direct scatter to (n,m,b,c) ---
    cudaStreamWaitEvent(0, eV, 0);
    hgemm<3><<<dim3(4, 8, 8), 256, GSMEM>>>(
        Tt3, vT3, out_x, bp, 768, 4, 512, 512, CC,
        (long)1024 * 512, (long)512 * 512, 0);
}

// round 17
// speedup vs baseline: 1.5304x; 1.0941x over previous
#include <cuda_runtime.h>
#include <cuda_bf16.h>
#include <cstdint>
#include <math.h>

// ---------------------------------------------------------------------------
// Problem constants
// ---------------------------------------------------------------------------
#define NQ   64
#define MMQ  16
#define BB   8
#define KK   256
#define CC   512
#define K2   1024           // folded [hi|lo] physical width for C=512 trios
#define K3   1536           // logical K for split-bf16 GEMMs
#define NROWS_Q 8192
#define NROWS_K 2048
#define BKP     2048
#define INV_EPS 20.0f
#define SINK_ITERS 36
#define X_ELEMS (NROWS_Q*CC)

// ---------------------------------------------------------------------------
// Scratch (device globals; no allocation allowed). Folded [hi|lo] storage.
// ---------------------------------------------------------------------------
__device__ __nv_bfloat16 g_xq3[NROWS_Q*K2];
__device__ __nv_bfloat16 g_xk3[NROWS_K*K2];
__device__ __nv_bfloat16 g_xv3[NROWS_K*K2];
__device__ __nv_bfloat16 g_wq3[CC*K2];
__device__ __nv_bfloat16 g_wk3[CC*K2];
__device__ __nv_bfloat16 g_wvT3[CC*K2];       // folded Wv^T (rows = input dim)
__device__ __nv_bfloat16 g_wp3[CC*K2];
__device__ __nv_bfloat16 g_wc3[CC*K2];        // folded Wc = Wp·Wv
__device__ float g_qlin[NROWS_Q*CC];
__device__ float g_klin[NROWS_K*CC];
__device__ float g_WC0[CC*CC];                // Wc split-K partials
__device__ float g_WC1[CC*CC];
__device__ float g_VP0[NROWS_K*CC];           // vp split-K partials
__device__ float g_VP1[NROWS_K*CC];
__device__ __nv_bfloat16 g_qr3[NROWS_Q*K2];
__device__ __nv_bfloat16 g_kn3[NROWS_K*K2];
__device__ float g_S0[BKP*MMQ*NQ];            // sim split-K partial 0
__device__ float g_S1[BKP*MMQ*NQ];            // sim split-K partial 1
__device__ __nv_bfloat16 g_Tt3[BB*1024*512];  // folded [hi|lo]
__device__ __nv_bfloat16 g_vT3[BB*512*512];   // folded [hi|lo]

// ---------------------------------------------------------------------------
// PTX helpers
// ---------------------------------------------------------------------------
__device__ __forceinline__ uint32_t s2u(const void* p){
    uint32_t a;
    asm("{ .reg .u64 t; cvta.to.shared.u64 t, %1; cvt.u32.u64 %0, t; }"
        : "=r"(a) : "l"(p));
    return a;
}

#define CP_ASYNC16(dst, src) \
    asm volatile("cp.async.cg.shared.global [%0], [%1], 16;" :: "r"(dst), "l"(src) : "memory")
#define CP_COMMIT() asm volatile("cp.async.commit_group;" ::: "memory")
#define CP_WAIT1()  asm volatile("cp.async.wait_group 1;" ::: "memory")
#define CP_WAIT0()  asm volatile("cp.async.wait_group 0;" ::: "memory")

#define LDMATRIX_X4(r0, r1, r2, r3, addr) \
    asm volatile("ldmatrix.sync.aligned.m8n8.x4.shared.b16 {%0,%1,%2,%3}, [%4];" \
                 : "=r"(r0), "=r"(r1), "=r"(r2), "=r"(r3) : "r"(addr))

#define MMA16816(d, a, b0, b1) \
    asm volatile("mma.sync.aligned.m16n8k16.row.col.f32.bf16.bf16.f32 " \
                 "{%0,%1,%2,%3}, {%4,%5,%6,%7}, {%8,%9}, {%0,%1,%2,%3};" \
                 : "+f"((d)[0]), "+f"((d)[1]), "+f"((d)[2]), "+f"((d)[3]) \
                 : "r"((a)[0]), "r"((a)[1]), "r"((a)[2]), "r"((a)[3]), \
                   "r"(b0), "r"(b1))

__device__ __forceinline__ unsigned short bfr(__nv_bfloat16 h){
    return *reinterpret_cast<unsigned short*>(&h);
}
__device__ __forceinline__ void split_bf16(float x, __nv_bfloat16& h, __nv_bfloat16& l){
    h = __float2bfloat16(x);
    l = __float2bfloat16(x - __bfloat162float(h));
}

// ---------------------------------------------------------------------------
// HMMA GEMM core (R6-proven mainloop; folded-operand loader):
//  A logical [hi|lo|hi]: phys chunk ca = cg>=2S ? cg-2S : cg
//  B logical [hi|hi|lo]: phys chunk cb = cg>=S  ? cg-S  : cg
// c0 = split-K chunk offset. CTA 128x128, BK=64, 3-stage ring, 2 CTAs/SM.
// EPI=0 fp32 store; EPI=3 out scatter+bias.
// ---------------------------------------------------------------------------
#define STG   32768
#define GSMEM (3*STG)

template<int EPI>
__device__ __forceinline__
void gemm_core(const __nv_bfloat16* __restrict__ A, const __nv_bfloat16* __restrict__ B,
               void* __restrict__ Cv, const float* __restrict__ bias,
               int Kp, int c0, int S, int lda, int ldb, int ldc,
               int mb, int nb, int bz, long cStride, char* smem)
{
    const int tid  = threadIdx.x;
    const int w    = tid >> 5;
    const int lane = tid & 31;
    const int wm   = (w & 3) * 32;
    const int wn   = (w >> 2) * 64;

    const uint32_t sbase = s2u(smem);
    const int NC = Kp >> 6;

    const int lrow = tid >> 1;
    const int lcg0 = (tid & 1) * 4;

    auto load_chunk = [&](int c, int s){
        const uint32_t st = sbase + s * STG;
        const int cg = c0 + c;
        const int ca = (cg >= 2 * S) ? cg - 2 * S : cg;
        const int cb = (cg >= S)     ? cg - S     : cg;
        const __nv_bfloat16* Ag = A + (long)(mb + lrow) * lda + ca * 64 + lcg0 * 8;
        const __nv_bfloat16* Bg = B + (long)(nb + lrow) * ldb + cb * 64 + lcg0 * 8;
        const uint32_t rbase = lrow * 128;
        const uint32_t sw    = (lrow & 7) << 4;
#pragma unroll
        for (int j = 0; j < 4; j++) {
            uint32_t off = rbase + (((lcg0 + j) << 4) ^ sw);
            CP_ASYNC16(st + off, Ag + j * 8);
            CP_ASYNC16(st + 16384 + off, Bg + j * 8);
        }
        CP_COMMIT();
    };

    float acc[2][8][4];
#pragma unroll
    for (int i = 0; i < 2; i++)
#pragma unroll
        for (int j = 0; j < 8; j++)
#pragma unroll
            for (int q = 0; q < 4; q++) acc[i][j][q] = 0.f;

    load_chunk(0, 0);
    load_chunk(1, 1);

    const int a_r  = lane & 15;
    const int a_kb = (lane & 16);
    const int b_r  = ((lane >> 4) << 3) + (lane & 7);
    const int b_kb = ((lane >> 3) & 1) << 4;

    int stage = 0;
    for (int c = 0; c < NC; c++) {
        if (c + 1 < NC) CP_WAIT1(); else CP_WAIT0();
        __syncthreads();

        if (c + 2 < NC) {
            int ns = stage + 2; if (ns >= 3) ns -= 3;
            load_chunk(c + 2, ns);
        }

        const uint32_t sa = sbase + stage * STG;
        const uint32_t sb = sa + 16384;

        uint32_t br2[2][4][4];
#pragma unroll
        for (int nj = 0; nj < 4; nj++) {
            int row = wn + nj * 16 + b_r;
            uint32_t kb = (uint32_t)(b_kb) ^ ((row & 7) << 4);
            LDMATRIX_X4(br2[0][nj][0], br2[0][nj][1], br2[0][nj][2], br2[0][nj][3],
                        sb + row * 128 + kb);
        }
#pragma unroll
        for (int ks = 0; ks < 4; ks++) {
            const int cur = ks & 1;
            if (ks < 3) {
#pragma unroll
                for (int nj = 0; nj < 4; nj++) {
                    int row = wn + nj * 16 + b_r;
                    uint32_t kb = (uint32_t)((ks + 1) * 32 + b_kb) ^ ((row & 7) << 4);
                    LDMATRIX_X4(br2[cur ^ 1][nj][0], br2[cur ^ 1][nj][1],
                                br2[cur ^ 1][nj][2], br2[cur ^ 1][nj][3],
                                sb + row * 128 + kb);
                }
            }
            uint32_t ar[2][4];
#pragma unroll
            for (int mi = 0; mi < 2; mi++) {
                int row = wm + mi * 16 + a_r;
                uint32_t kb = (uint32_t)(ks * 32 + a_kb) ^ ((row & 7) << 4);
                LDMATRIX_X4(ar[mi][0], ar[mi][1], ar[mi][2], ar[mi][3],
                            sa + row * 128 + kb);
            }
#pragma unroll
            for (int mi = 0; mi < 2; mi++)
#pragma unroll
                for (int nj = 0; nj < 4; nj++) {
                    MMA16816(acc[mi][nj * 2],     ar[mi], br2[cur][nj][0], br2[cur][nj][1]);
                    MMA16816(acc[mi][nj * 2 + 1], ar[mi], br2[cur][nj][2], br2[cur][nj][3]);
                }
        }
        stage++; if (stage == 3) stage = 0;
    }

    // ---- epilogue ----
    const int er = lane >> 2;
    const int ec = (lane & 3) * 2;
#pragma unroll
    for (int mi = 0; mi < 2; mi++) {
#pragma unroll
        for (int half = 0; half < 2; half++) {
            const int R = mb + wm + mi * 16 + er + half * 8;
            if (EPI == 0) {
                float* Crow = (float*)Cv + (long)bz * cStride + (long)R * ldc;
#pragma unroll
                for (int nj = 0; nj < 8; nj++) {
                    const int col = nb + wn + nj * 8 + ec;
                    *(float2*)&Crow[col] =
                        make_float2(acc[mi][nj][half * 2], acc[mi][nj][half * 2 + 1]);
                }
            } else {
                const int mq = R >> 6, nq = R & 63;
                float* Crow = (float*)Cv + (long)(((nq << 4) + mq) * 8 + bz) * CC;
#pragma unroll
                for (int nj = 0; nj < 8; nj++) {
                    const int col = nb + wn + nj * 8 + ec;
                    *(float2*)&Crow[col] = make_float2(
                        acc[mi][nj][half * 2] + bias[col],
                        acc[mi][nj][half * 2 + 1] + bias[col + 1]);
                }
            }
        }
    }
}

// generic GEMM
template<int EPI>
__global__ __launch_bounds__(256, 2)
void hgemm(const __nv_bfloat16* __restrict__ A, const __nv_bfloat16* __restrict__ B,
           void* __restrict__ C, const float* __restrict__ bias,
           int Kp, int S, int lda, int ldb, int ldc,
           long aStride, long bStride, long cStride)
{
    extern __shared__ char smem[];
    const int bz = blockIdx.z;
    gemm_core<EPI>(A + bz * aStride, B + bz * bStride, C, bias,
                   Kp, 0, S, lda, ldb, ldc,
                   blockIdx.y * 128, blockIdx.x * 128, bz, cStride, smem);
}

// generic split-K=2 GEMM over logical K=1536: z = kh, partials C0/C1
__global__ __launch_bounds__(256, 2)
void hgemm_sk(const __nv_bfloat16* __restrict__ A, const __nv_bfloat16* __restrict__ B,
              float* __restrict__ C0, float* __restrict__ C1,
              int lda, int ldb, int ldc)
{
    extern __shared__ char smem[];
    const int kh = blockIdx.z;
    gemm_core<0>(A, B, kh ? C1 : C0, nullptr,
                 768, kh * 12, 8, lda, ldb, ldc,
                 blockIdx.y * 128, blockIdx.x * 128, 0, 0, smem);
}

// q+k projections fused: grid.y in [0,80): 0-63 q, 64-79 k
__global__ __launch_bounds__(256, 2)
void hgemm_projqk(const __nv_bfloat16* __restrict__ Aq, const __nv_bfloat16* __restrict__ Bq,
                  float* __restrict__ Cq,
                  const __nv_bfloat16* __restrict__ Ak, const __nv_bfloat16* __restrict__ Bk,
                  float* __restrict__ Ck)
{
    extern __shared__ char smem[];
    const int by = blockIdx.y;
    if (by < 64)
        gemm_core<0>(Aq, Bq, Cq, nullptr, K3, 0, 8, K2, K2, CC,
                     by * 128, blockIdx.x * 128, 0, 0, smem);
    else
        gemm_core<0>(Ak, Bk, Ck, nullptr, K3, 0, 8, K2, K2, CC,
                     (by - 64) * 128, blockIdx.x * 128, 0, 0, smem);
}

// sim split-K=2: z = b*2 + kh; chunk offset c0 = kh*12
__global__ __launch_bounds__(256, 2)
void hgemm_sim(const __nv_bfloat16* __restrict__ A, const __nv_bfloat16* __restrict__ B,
               float* __restrict__ S0, float* __restrict__ S1)
{
    extern __shared__ char smem[];
    const int z = blockIdx.z;
    const int b = z >> 1;
    const int kh = z & 1;
    gemm_core<0>(A + (long)b * 256 * K2,
                 B + (long)b * 1024 * K2,
                 kh ? S1 : S0, nullptr,
                 768, kh * 12, 8, K2, K2, 1024,
                 blockIdx.y * 128, blockIdx.x * 128, b, (long)256 * 1024, smem);
}

// ---------------------------------------------------------------------------
// conv helpers: fp32 [512] row -> folded bf16 [hi(512)|lo(512)]
// ---------------------------------------------------------------------------
__device__ __forceinline__ void conv3_emit(float4 v, __nv_bfloat16* __restrict__ out, int t)
{
    __nv_bfloat16 h0,h1,h2,h3,l0,l1,l2,l3;
    split_bf16(v.x,h0,l0); split_bf16(v.y,h1,l1);
    split_bf16(v.z,h2,l2); split_bf16(v.w,h3,l3);
    ((ushort4*)(out))[t]      = make_ushort4(bfr(h0),bfr(h1),bfr(h2),bfr(h3));
    ((ushort4*)(out + CC))[t] = make_ushort4(bfr(l0),bfr(l1),bfr(l2),bfr(l3));
}

__device__ __forceinline__ void conv3_row(const float* __restrict__ in,
                                          __nv_bfloat16* __restrict__ out, int t)
{
    conv3_emit(((const float4*)in)[t], out, t);
}

// weights Wq/Wk/Wp: 1536 rows
__global__ void conv_weights(const float* __restrict__ Wq, __nv_bfloat16* __restrict__ oWq,
                             const float* __restrict__ Wk, __nv_bfloat16* __restrict__ oWk,
                             const float* __restrict__ Wp, __nv_bfloat16* __restrict__ oWp)
{
    const int r = blockIdx.x;
    const int sel = r >> 9, rw = r & 511;
    const float* in; __nv_bfloat16* out;
    if (sel == 0)      { in = Wq; out = oWq; }
    else if (sel == 1) { in = Wk; out = oWk; }
    else               { in = Wp; out = oWp; }
    conv3_row(in + (long)rw * CC, out + (long)rw * K2, threadIdx.x);
}

// activations xq (8192) + xk (2048)
__global__ void conv_acts(const float* __restrict__ xq, __nv_bfloat16* __restrict__ oxq,
                          const float* __restrict__ xk, __nv_bfloat16* __restrict__ oxk)
{
    const int r = blockIdx.x;
    const float* in; __nv_bfloat16* out; int rr;
    if (r < 8192) { in = xq; out = oxq; rr = r; }
    else          { in = xk; out = oxk; rr = r - 8192; }
    conv3_row(in + (long)rr * CC, out + (long)rr * K2, threadIdx.x);
}

__global__ void conv3_one(const float* __restrict__ in, __nv_bfloat16* __restrict__ out)
{
    const long r = blockIdx.x;
    conv3_row(in + r * CC, out + r * K2, threadIdx.x);
}

// sum two fp32 partials then folded split (for Wc)
__global__ void conv3_sum(const float* __restrict__ in0, const float* __restrict__ in1,
                          __nv_bfloat16* __restrict__ out)
{
    const long r = blockIdx.x;
    const int t = threadIdx.x;
    float4 a = ((const float4*)(in0 + r * CC))[t];
    float4 b = ((const float4*)(in1 + r * CC))[t];
    conv3_emit(make_float4(a.x+b.x, a.y+b.y, a.z+b.z, a.w+b.w),
               out + r * K2, t);
}

// ---------------------------------------------------------------------------
// Fused norm: rows <8192 = q (reorder), else k. Folded [hi|lo] emit.
// ---------------------------------------------------------------------------
__global__ void norm_fused(const float* __restrict__ qin, __nv_bfloat16* __restrict__ qout,
                           const float* __restrict__ kin, __nv_bfloat16* __restrict__ kout)
{
    const int r = blockIdx.x;
    const int t = threadIdx.x;
    const float* in;
    __nv_bfloat16* out;
    long orow;
    if (r < NROWS_Q) {
        in = qin + (long)r * CC;
        int n = r >> 7, m = (r >> 3) & 15, b = r & 7;
        orow = (long)(b * 1024 + m * 64 + n);
        out = qout;
    } else {
        int rk = r - NROWS_Q;
        in = kin + (long)rk * CC;
        orow = rk;
        out = kout;
    }
    float4 v = ((const float4*)in)[t];
    float ss = v.x*v.x + v.y*v.y + v.z*v.z + v.w*v.w;
#pragma unroll
    for (int o = 16; o; o >>= 1) ss += __shfl_xor_sync(0xffffffffu, ss, o);
    __shared__ float sw[4];
    if ((t & 31) == 0) sw[t >> 5] = ss;
    __syncthreads();
    float tot = sw[0] + sw[1] + sw[2] + sw[3];
    float scale = 1.0f / fmaxf(sqrtf(tot), 1e-12f);
    conv3_emit(make_float4(v.x*scale, v.y*scale, v.z*scale, v.w*scale),
               out + orow * K2, t);
}

// ---------------------------------------------------------------------------
// Transpose + folded split: Wv fp32 [512][512] -> wvT3 [512][1024]
// ---------------------------------------------------------------------------
__global__ void trconv_w(const float* __restrict__ in, __nv_bfloat16* __restrict__ out)
{
    __shared__ float s[32][33];
    const int d0 = blockIdx.y * 32, c0 = blockIdx.x * 32;
    const int tx = threadIdx.x, ty = threadIdx.y;
#pragma unroll
    for (int i = 0; i < 4; i++)
        s[ty + 8*i][tx] = in[(long)(d0 + ty + 8*i) * 512 + c0 + tx];
    __syncthreads();
#pragma unroll
    for (int i = 0; i < 4; i++) {
        const int c = c0 + ty + 8*i;
        float x = s[tx][ty + 8*i];
        __nv_bfloat16 h, l; split_bf16(x, h, l);
        __nv_bfloat16* p = out + (long)c * K2 + d0 + tx;
        p[0]  = h;
        p[CC] = l;
    }
}

// ---------------------------------------------------------------------------
// Sum + transpose + folded split: VP0+VP1 fp32 [b][256][512] -> vT3 [b][512][512]
// ---------------------------------------------------------------------------
__global__ void trconv_v_sum(const float* __restrict__ in0, const float* __restrict__ in1,
                             __nv_bfloat16* __restrict__ out)
{
    __shared__ float s[32][33];
    const int b = blockIdx.z;
    const long base = (long)b * 256 * 512;
    __nv_bfloat16* ob = out + (long)b * 512 * 512;
    const int k0 = blockIdx.y * 32, w0 = blockIdx.x * 32;
    const int tx = threadIdx.x, ty = threadIdx.y;
#pragma unroll
    for (int i = 0; i < 4; i++) {
        long idx = base + (long)(k0 + ty + 8*i) * 512 + w0 + tx;
        s[ty + 8*i][tx] = in0[idx] + in1[idx];
    }
    __syncthreads();
#pragma unroll
    for (int i = 0; i < 4; i++) {
        const int wrow = w0 + ty + 8*i;
        float x = s[tx][ty + 8*i];
        __nv_bfloat16 h, l; split_bf16(x, h, l);
        __nv_bfloat16* p = ob + (long)wrow * 512 + k0 + tx;
        p[0]   = h;
        p[256] = l;
    }
}

// ---------------------------------------------------------------------------
// Sinkhorn: one warp per (b,k) problem, SINK_ITERS iterations.
// Reads S0+S1. Writes score + folded transposed Tt3 via chunked smem transpose.
// ---------------------------------------------------------------------------
__global__ __launch_bounds__(256)
void sinkhorn_kernel(const float* __restrict__ S0, const float* __restrict__ S1,
                     __nv_bfloat16* __restrict__ Tt3, float* __restrict__ score)
{
    __shared__ __align__(16) __nv_bfloat16 th[256][8];
    __shared__ __align__(16) __nv_bfloat16 tl[256][8];

    const int w    = threadIdx.x >> 5;
    const int lane = threadIdx.x & 31;
    const int pb   = blockIdx.x * 8;
    const int p    = pb + w;
    const int b    = pb >> 8;
    const int k0   = pb & 255;
    const float* s0 = S0 + (long)p * (MMQ * NQ);
    const float* s1 = S1 + (long)p * (MMQ * NQ);

    float Km[32];
#pragma unroll
    for (int i = 0; i < 16; i++) {
        Km[i]      = __expf((s0[i*64+lane]    + s1[i*64+lane]    - 1.0f) * INV_EPS);
        Km[i + 16] = __expf((s0[i*64+lane+32] + s1[i*64+lane+32] - 1.0f) * INV_EPS);
    }

    const float MU = 1.0f / 16.0f + 1e-8f;
    const float NU = 1.0f / 64.0f + 1e-8f;
    float b0 = 1.0f, b1 = 1.0f;
    float a[16];

#pragma unroll 1
    for (int iter = 0; iter < SINK_ITERS; iter++) {
        float v[16];
#pragma unroll
        for (int i = 0; i < 16; i++) v[i] = Km[i] * b0 + Km[i + 16] * b1;
#pragma unroll
        for (int i = 0; i < 8; i++) {
            float t0 = v[i], t1 = v[i + 8];
            float r0 = __shfl_xor_sync(0xffffffffu, t0, 16);
            float r1 = __shfl_xor_sync(0xffffffffu, t1, 16);
            v[i] = (lane & 16) ? (t1 + r1) : (t0 + r0);
        }
#pragma unroll
        for (int i = 0; i < 4; i++) {
            float t0 = v[i], t1 = v[i + 4];
            float r0 = __shfl_xor_sync(0xffffffffu, t0, 8);
            float r1 = __shfl_xor_sync(0xffffffffu, t1, 8);
            v[i] = (lane & 8) ? (t1 + r1) : (t0 + r0);
        }
#pragma unroll
        for (int i = 0; i < 2; i++) {
            float t0 = v[i], t1 = v[i + 2];
            float r0 = __shfl_xor_sync(0xffffffffu, t0, 4);
            float r1 = __shfl_xor_sync(0xffffffffu, t1, 4);
            v[i] = (lane & 4) ? (t1 + r1) : (t0 + r0);
        }
        {
            float t0 = v[0], t1 = v[1];
            float r0 = __shfl_xor_sync(0xffffffffu, t0, 2);
            float r1 = __shfl_xor_sync(0xffffffffu, t1, 2);
            v[0] = (lane & 2) ? (t1 + r1) : (t0 + r0);
        }
        v[0] += __shfl_xor_sync(0xffffffffu, v[0], 1);

        float av = __fdividef(MU, v[0]);
#pragma unroll
        for (int i = 0; i < 16; i++) a[i] = __shfl_sync(0xffffffffu, av, 2 * i);

        float c0a = 0.f, c0b = 0.f, c1a = 0.f, c1b = 0.f;
#pragma unroll
        for (int i = 0; i < 16; i += 2) {
            c0a += Km[i] * a[i];       c0b += Km[i + 1] * a[i + 1];
            c1a += Km[i + 16] * a[i];  c1b += Km[i + 17] * a[i + 1];
        }
        b0 = __fdividef(NU, c0a + c0b);
        b1 = __fdividef(NU, c1a + c1b);
    }

    // ---- epilogue: score + chunked smem transpose into folded Tt3 ----
    float* Srow = score + (long)p * (MMQ * NQ);
#pragma unroll 1
    for (int q = 0; q < 4; q++) {
#pragma unroll
        for (int ii = 0; ii < 4; ii++) {
            const int i = q * 4 + ii;
            float T0 = a[i] * Km[i] * b0;
            float T1 = a[i] * Km[i + 16] * b1;
            float sv0 = s0[i*64+lane]    + s1[i*64+lane];
            float sv1 = s0[i*64+lane+32] + s1[i*64+lane+32];
            Srow[i * 64 + lane]      = 1024.0f * sv0 * T0;
            Srow[i * 64 + lane + 32] = 1024.0f * sv1 * T1;
            __nv_bfloat16 h, l;
            split_bf16(T0, h, l);
            th[i * 64 + lane - q * 256][w] = h;
            tl[i * 64 + lane - q * 256][w] = l;
            split_bf16(T1, h, l);
            th[i * 64 + lane + 32 - q * 256][w] = h;
            tl[i * 64 + lane + 32 - q * 256][w] = l;
        }
        __syncthreads();
        {
            const int r = threadIdx.x;      // 0..255
            __nv_bfloat16* d = Tt3 + ((long)b * 1024 + q * 256 + r) * 512 + k0;
            *(uint4*)(d)       = *(const uint4*)&th[r][0];
            *(uint4*)(d + 256) = *(const uint4*)&tl[r][0];
        }
        __syncthreads();
    }
}

// ---------------------------------------------------------------------------
extern "C" void kernel_launch(void* const* d_in, const int* in_sizes, int n_in,
                              void* d_out, int out_size)
{
    const float* xq = (const float*)d_in[0];
    const float* xk = (const float*)d_in[1];
    const float* xv = (const float*)d_in[2];
    const float* Wq = (const float*)d_in[3];
    const float* Wk = (const float*)d_in[4];
    const float* Wv = (const float*)d_in[5];
    const float* Wp = (const float*)d_in[6];
    const float* bp = (const float*)d_in[7];
    float* out_x     = (float*)d_out;
    float* out_score = out_x + X_ELEMS;

    __nv_bfloat16 *xq3,*xk3,*xv3,*wq3,*wk3,*wvT3,*wp3,*wc3,*qr3,*kn3,*Tt3,*vT3;
    float *qlin,*klin,*WC0,*WC1,*VP0,*VP1,*S0,*S1;
    cudaGetSymbolAddress((void**)&xq3,  g_xq3);
    cudaGetSymbolAddress((void**)&xk3,  g_xk3);
    cudaGetSymbolAddress((void**)&xv3,  g_xv3);
    cudaGetSymbolAddress((void**)&wq3,  g_wq3);
    cudaGetSymbolAddress((void**)&wk3,  g_wk3);
    cudaGetSymbolAddress((void**)&wvT3, g_wvT3);
    cudaGetSymbolAddress((void**)&wp3,  g_wp3);
    cudaGetSymbolAddress((void**)&wc3,  g_wc3);
    cudaGetSymbolAddress((void**)&qr3,  g_qr3);
    cudaGetSymbolAddress((void**)&kn3,  g_kn3);
    cudaGetSymbolAddress((void**)&Tt3,  g_Tt3);
    cudaGetSymbolAddress((void**)&vT3,  g_vT3);
    cudaGetSymbolAddress((void**)&qlin, g_qlin);
    cudaGetSymbolAddress((void**)&klin, g_klin);
    cudaGetSymbolAddress((void**)&WC0,  g_WC0);
    cudaGetSymbolAddress((void**)&WC1,  g_WC1);
    cudaGetSymbolAddress((void**)&VP0,  g_VP0);
    cudaGetSymbolAddress((void**)&VP1,  g_VP1);
    cudaGetSymbolAddress((void**)&S0,   g_S0);
    cudaGetSymbolAddress((void**)&S1,   g_S1);

    cudaFuncSetAttribute(hgemm<3>,     cudaFuncAttributeMaxDynamicSharedMemorySize, GSMEM);
    cudaFuncSetAttribute(hgemm_sk,     cudaFuncAttributeMaxDynamicSharedMemorySize, GSMEM);
    cudaFuncSetAttribute(hgemm_projqk, cudaFuncAttributeMaxDynamicSharedMemorySize, GSMEM);
    cudaFuncSetAttribute(hgemm_sim,    cudaFuncAttributeMaxDynamicSharedMemorySize, GSMEM);

    // ONE side stream + 3 events (proven leak-free in R13-R15)
    cudaStream_t sA;
    cudaStreamCreateWithFlags(&sA, cudaStreamNonBlocking);
    cudaEvent_t eRoot, eW, eV;
    cudaEventCreateWithFlags(&eRoot, cudaEventDisableTiming);
    cudaEventCreateWithFlags(&eW,    cudaEventDisableTiming);
    cudaEventCreateWithFlags(&eV,    cudaEventDisableTiming);

    // --- main: weight conv first (fires eW early for sA's Wc GEMM) ---
    cudaEventRecord(eRoot, 0);
    conv_weights<<<3 * CC, 128>>>(Wq, wq3, Wk, wk3, Wp, wp3);
    cudaEventRecord(eW, 0);

    // --- sA: Wv^T, xv conv; Wc (split-K) -> wc3; vp (split-K) -> vT3 ---
    cudaStreamWaitEvent(sA, eRoot, 0);
    trconv_w<<<dim3(16, 16), dim3(32, 8), 0, sA>>>(Wv, wvT3);
    conv3_one<<<NROWS_K, 128, 0, sA>>>(xv, xv3);
    cudaStreamWaitEvent(sA, eW, 0);
    hgemm_sk<<<dim3(4, 4, 2), 256, GSMEM, sA>>>(wp3, wvT3, WC0, WC1, K2, K2, 512);
    conv3_sum<<<CC, 128, 0, sA>>>(WC0, WC1, wc3);
    hgemm_sk<<<dim3(4, 16, 2), 256, GSMEM, sA>>>(xv3, wc3, VP0, VP1, K2, K2, 512);
    trconv_v_sum<<<dim3(16, 8, 8), dim3(32, 8), 0, sA>>>(VP0, VP1, vT3);
    cudaEventRecord(eV, sA);

    // --- main: activation conv, then q+k projections ---
    conv_acts<<<NROWS_Q + NROWS_K, 128>>>(xq, xq3, xk, xk3);
    hgemm_projqk<<<dim3(4, 80), 256, GSMEM>>>(xq3, wq3, qlin, xk3, wk3, klin);

    // --- l2 normalize (fused q+k), folded split-bf16 emit ---
    norm_fused<<<NROWS_Q + NROWS_K, 128>>>(qlin, qr3, klin, kn3);

    // --- sim split-K=2, single launch, 256 CTAs (full chip) ---
    hgemm_sim<<<dim3(8, 2, 16), 256, GSMEM>>>(kn3, qr3, S0, S1);

    // --- Sinkhorn (reads S0+S1) -> folded Tt3 + score_map ---
    sinkhorn_kernel<<<BKP / 8, 256>>>(S0, S1, Tt3, out_score);

    // --- join vp path; x = T^T·vp + bp with direct scatter to (n,m,b,c) ---
    cudaStreamWaitEvent(0, eV, 0);
    hgemm<3><<<dim3(4, 8, 8), 256, GSMEM>>>(
        Tt3, vT3, out_x, bp, 768, 4, 512, 512, CC,
        (long)1024 * 512, (long)512 * 512, 0);
}